// round 7
// baseline (speedup 1.0000x reference)
#include <cuda_runtime.h>
#include <cuda_fp16.h>
#include <math.h>
#include <stdint.h>

// ---------------------------------------------------------------------------
// Decoder — Round 7: pre-split fp16 operands + ldmatrix mma.sync GEMM
// (Round 6 + fix: dedicated encoder half buffers — no more ff aliasing)
// ---------------------------------------------------------------------------

#define Bb_ 4
#define Ss_ 512
#define Dm_ 512
#define Hh_ 8
#define Dk_ 64
#define Ff_ 2048
#define Vv_ 37000
#define VvP_ 37120
#define Nx_ 6
#define BS_ 2048

// ------------------------- scratch (static device globals) -----------------
__device__ __align__(16) float g_x    [BS_*Dm_];
__device__ __align__(16) float g_tmp  [BS_*Dm_];
__device__ __align__(16) float g_qkv  [BS_*3*Dm_];     // fp32 (V read by AV gemm)
__device__ __align__(16) float g_sc   [Bb_*Hh_*Ss_*Ss_];
__device__ __align__(16) float g_wt   [Dm_*3*Dm_];
__device__ float g_mu   [Dm_];
__device__ float g_rstd [Dm_];

// hi/lo half activations
__device__ __align__(16) __half g_xh   [BS_*Dm_];
__device__ __align__(16) __half g_xl   [BS_*Dm_];
__device__ __align__(16) __half g_qkvh [BS_*3*Dm_];
__device__ __align__(16) __half g_qkvl [BS_*3*Dm_];
__device__ __align__(16) __half g_attnh[BS_*Dm_];
__device__ __align__(16) __half g_attnl[BS_*Dm_];
__device__ __align__(16) __half g_ffh  [BS_*Ff_];
__device__ __align__(16) __half g_ffl  [BS_*Ff_];
__device__ __align__(16) __half g_ench [BS_*Dm_];      // FIX: dedicated buffers
__device__ __align__(16) __half g_encl [BS_*Dm_];

// hi/lo half weights, [N, K] K-major
__device__ __align__(16) __half g_wtT_h [12L*1536*512];
__device__ __align__(16) __half g_wtT_l [12L*1536*512];
__device__ __align__(16) __half g_w1T_h [6L*2048*512];
__device__ __align__(16) __half g_w1T_l [6L*2048*512];
__device__ __align__(16) __half g_w2T_h [6L*512*2048];
__device__ __align__(16) __half g_w2T_l [6L*512*2048];
__device__ __align__(16) __half g_wo1T_h[6L*512*512];
__device__ __align__(16) __half g_wo1T_l[6L*512*512];
__device__ __align__(16) __half g_wo2T_h[6L*512*512];
__device__ __align__(16) __half g_wo2T_l[6L*512*512];
__device__ __align__(16) __half g_woutT_h[(long long)VvP_*512];
__device__ __align__(16) __half g_woutT_l[(long long)VvP_*512];

// ------------------------------- helpers -----------------------------------
__device__ __forceinline__ void split2(float2 x, uint32_t& hi, uint32_t& lo) {
    __half2 h = __float22half2_rn(x);
    float2 hf = __half22float2(h);
    __half2 l = __float22half2_rn(make_float2(x.x - hf.x, x.y - hf.y));
    hi = *reinterpret_cast<uint32_t*>(&h);
    lo = *reinterpret_cast<uint32_t*>(&l);
}
__device__ __forceinline__ void cpasync16(uint32_t dst, const void* src) {
    asm volatile("cp.async.cg.shared.global [%0], [%1], 16;"
                 :: "r"(dst), "l"(src));
}
__device__ __forceinline__ void cpcommit() { asm volatile("cp.async.commit_group;"); }
template <int NN> __device__ __forceinline__ void cpwait() {
    asm volatile("cp.async.wait_group %0;" :: "n"(NN));
}
__device__ __forceinline__ void mma16(float* d, const uint32_t* a, const uint32_t* b) {
    asm volatile(
        "mma.sync.aligned.m16n8k16.row.col.f32.f16.f16.f32 "
        "{%0,%1,%2,%3}, {%4,%5,%6,%7}, {%8,%9}, {%0,%1,%2,%3};"
        : "+f"(d[0]), "+f"(d[1]), "+f"(d[2]), "+f"(d[3])
        : "r"(a[0]), "r"(a[1]), "r"(a[2]), "r"(a[3]), "r"(b[0]), "r"(b[1]));
}
__device__ __forceinline__ void ldsm4(uint32_t* r, uint32_t addr) {
    asm volatile("ldmatrix.sync.aligned.m8n8.x4.shared.b16 {%0,%1,%2,%3}, [%4];"
                 : "=r"(r[0]), "=r"(r[1]), "=r"(r[2]), "=r"(r[3]) : "r"(addr));
}

// ------------------------ GEMM: pure-half operands ---------------------------
// C[z] = alpha * A @ B^T (+bias)(+res)(relu). A: hi/lo half [M,K]; B: hi/lo
// half [N,K]. Tile 128x128x32, 8 warps (4m x 2n), ldmatrix fragments, 3-pass
// hi/lo fp16 split => fp32 accuracy. Optional half-pair output (Ch/Cl).
// flags: bit0 relu, bit1 causal-skip.
#define HSTRB 80                       // smem row stride (bytes) = 40 halves
#define HARR  (128*HSTRB)              // one array: 10240 B
#define HSTAGE (4*HARR)                // Ah,Al,Bh,Bl: 40960 B
#define GH_SMEM (2*HSTAGE)             // 81920 B

__global__ __launch_bounds__(256) void gemm_h(
    const __half* __restrict__ Ah, const __half* __restrict__ Al,
    const __half* __restrict__ Bh, const __half* __restrict__ Bl,
    float* __restrict__ C, __half* __restrict__ Ch, __half* __restrict__ Cl,
    const float* __restrict__ bias, const float* __restrict__ res,
    int M, int N, int K, int lda, int ldb, int ldc,
    long long aS1, long long aS2, int aDiv,
    long long bS1, long long bS2, int bDiv,
    long long cS1, long long cS2, int cDiv,
    float alpha, int flags)
{
    extern __shared__ char smh[];
    const int m0 = blockIdx.y * 128, n0 = blockIdx.x * 128;
    if ((flags & 2) && n0 >= m0 + 128) return;      // causal: fully-masked tile

    const int z = blockIdx.z;
    const long long aOff = (long long)(z / aDiv) * aS1 + (long long)(z % aDiv) * aS2;
    const long long bOff = (long long)(z / bDiv) * bS1 + (long long)(z % bDiv) * bS2;
    const long long cOff = (long long)(z / cDiv) * cS1 + (long long)(z % cDiv) * cS2;
    const __half* Ahb = Ah + aOff;
    const __half* Alb = Al + aOff;
    const __half* Bhb = Bh + bOff;
    const __half* Blb = Bl + bOff;

    const uint32_t sb = (uint32_t)__cvta_generic_to_shared(smh);
    const int tid = threadIdx.x;
    const int wid = tid >> 5, lane = tid & 31;
    const int wm = wid & 3, wn = wid >> 2;
    const int g = lane >> 2, t = lane & 3;

    // ldmatrix per-lane address components
    const int aRow = lane & 15, aChk = lane >> 4;                  // A: 16 rows x 2 k-chunks
    const int bRow = (lane & 7) + ((lane >> 4) << 3);              // B: n within 16
    const int bChk = (lane >> 3) & 1;

    float acc[2][8][4];
#pragma unroll
    for (int i = 0; i < 2; i++)
#pragma unroll
        for (int j = 0; j < 8; j++)
#pragma unroll
            for (int r = 0; r < 4; r++) acc[i][j][r] = 0.f;

    const int T = K >> 5;                 // 32-half k-tiles

    auto stage = [&](int it, int buf) {
        const int k0 = it << 5;
        uint32_t dst = sb + buf * HSTAGE;
#pragma unroll
        for (int j = 0; j < 2; j++) {
            int idx = tid + (j << 8);            // 512 chunks (128 rows x 4)
            int row = idx >> 2, c = idx & 3;
            long long asrc = (long long)(m0 + row) * lda + k0 + c * 8;
            long long bsrc = (long long)(n0 + row) * ldb + k0 + c * 8;
            uint32_t so = (uint32_t)(row * HSTRB + c * 16);
            cpasync16(dst + 0 * HARR + so, Ahb + asrc);
            cpasync16(dst + 1 * HARR + so, Alb + asrc);
            cpasync16(dst + 2 * HARR + so, Bhb + bsrc);
            cpasync16(dst + 3 * HARR + so, Blb + bsrc);
        }
    };

    stage(0, 0); cpcommit();

    for (int it = 0; it < T; ++it) {
        const int cur = it & 1;
        if (it + 1 < T) { stage(it + 1, cur ^ 1); cpcommit(); cpwait<1>(); }
        else            { cpwait<0>(); }
        __syncthreads();

        uint32_t base = sb + cur * HSTAGE;
        uint32_t aH = base + 0 * HARR + (uint32_t)((wm * 32 + aRow) * HSTRB + aChk * 16);
        uint32_t aL = base + 1 * HARR + (uint32_t)((wm * 32 + aRow) * HSTRB + aChk * 16);
        uint32_t bH = base + 2 * HARR + (uint32_t)((wn * 64 + bRow) * HSTRB + bChk * 16);
        uint32_t bL = base + 3 * HARR + (uint32_t)((wn * 64 + bRow) * HSTRB + bChk * 16);

#pragma unroll
        for (int kk = 0; kk < 2; kk++) {          // two k16 steps
            const uint32_t ko = kk << 5;          // 16 halves = 32 bytes
            uint32_t ah[2][4], al[2][4];
#pragma unroll
            for (int mt = 0; mt < 2; mt++) {
                ldsm4(ah[mt], aH + mt * (16 * HSTRB) + ko);
                ldsm4(al[mt], aL + mt * (16 * HSTRB) + ko);
            }
            uint32_t bh[4][4], bl[4][4];          // each covers 2 n8-tiles
#pragma unroll
            for (int p = 0; p < 4; p++) {
                ldsm4(bh[p], bH + p * (16 * HSTRB) + ko);
                ldsm4(bl[p], bL + p * (16 * HSTRB) + ko);
            }
#pragma unroll
            for (int mt = 0; mt < 2; mt++)
#pragma unroll
                for (int p = 0; p < 4; p++) {
                    mma16(acc[mt][2*p],   ah[mt], &bh[p][0]);
                    mma16(acc[mt][2*p],   al[mt], &bh[p][0]);
                    mma16(acc[mt][2*p],   ah[mt], &bl[p][0]);
                    mma16(acc[mt][2*p+1], ah[mt], &bh[p][2]);
                    mma16(acc[mt][2*p+1], al[mt], &bh[p][2]);
                    mma16(acc[mt][2*p+1], ah[mt], &bl[p][2]);
                }
        }
        __syncthreads();
    }

    // ------------------------------ epilogue --------------------------------
    const bool relu = flags & 1;
#pragma unroll
    for (int mt = 0; mt < 2; mt++) {
#pragma unroll
        for (int hrow = 0; hrow < 2; hrow++) {
            int m = m0 + wm * 32 + mt * 16 + g + hrow * 8;
            long long rowo = cOff + (long long)m * ldc;
#pragma unroll
            for (int nt = 0; nt < 8; nt++) {
                int n = n0 + wn * 64 + nt * 8 + 2 * t;
                if (n < N) {
                    float v0 = acc[mt][nt][hrow * 2 + 0] * alpha;
                    float v1 = acc[mt][nt][hrow * 2 + 1] * alpha;
                    if (bias) { v0 += bias[n]; v1 += bias[n + 1]; }
                    if (res) {
                        const float* rp = res + rowo;
                        v0 += rp[n]; v1 += rp[n + 1];
                    }
                    if (relu) { v0 = fmaxf(v0, 0.f); v1 = fmaxf(v1, 0.f); }
                    if (C) {
                        float2 vv; vv.x = v0; vv.y = v1;
                        *(float2*)(C + rowo + n) = vv;
                    }
                    if (Ch) {
                        uint32_t hi, lo;
                        split2(make_float2(v0, v1), hi, lo);
                        *(uint32_t*)(Ch + rowo + n) = hi;
                        *(uint32_t*)(Cl + rowo + n) = lo;
                    }
                }
            }
        }
    }
}

// -------------------- AV GEMM (fp32 A=probs, fp32 B=[k][n]) -----------------
#define ASTR 40
#define BSTRN 132
#define ASZ (128*ASTR)
#define BSZn (32*BSTRN)
#define GEMM_SMEM_N ((2*ASZ + 2*BSZn)*4)

__global__ __launch_bounds__(256) void gemm_av(
    const float* __restrict__ A, const float* __restrict__ B,
    __half* __restrict__ Ch, __half* __restrict__ Cl,
    int M, int N, int K, int lda, int ldb, int ldc,
    long long aS1, long long aS2, int aDiv,
    long long bS1, long long bS2, int bDiv,
    long long cS1, long long cS2, int cDiv)
{
    extern __shared__ float sm[];
    const int z = blockIdx.z;
    const float* Ab  = A + (long long)(z / aDiv) * aS1 + (long long)(z % aDiv) * aS2;
    const float* Bbp = B + (long long)(z / bDiv) * bS1 + (long long)(z % bDiv) * bS2;
    const long long cOff = (long long)(z / cDiv) * cS1 + (long long)(z % cDiv) * cS2;

    float* As = sm;
    float* Bs = sm + 2 * ASZ;

    const int tid  = threadIdx.x;
    const int wid  = tid >> 5, lane = tid & 31;
    const int wm   = wid & 3,  wn   = wid >> 2;
    const int g    = lane >> 2, t   = lane & 3;
    const int m0   = blockIdx.y * 128, n0 = blockIdx.x * 128;

    const uint32_t asA = (uint32_t)__cvta_generic_to_shared(As);
    const uint32_t asB = (uint32_t)__cvta_generic_to_shared(Bs);

    float acc[2][8][4];
#pragma unroll
    for (int i = 0; i < 2; i++)
#pragma unroll
        for (int j = 0; j < 8; j++)
#pragma unroll
            for (int r = 0; r < 4; r++) acc[i][j][r] = 0.f;

    const int nIter = K >> 5;

    auto doCopy = [&](int it, int buf) {
        const int k0 = it << 5;
#pragma unroll
        for (int j = 0; j < 4; j++) {
            int i   = tid + (j << 8);
            int row = i >> 3, kq = (i & 7) << 2;
            const float* src = Ab + (long long)(m0 + row) * lda + (k0 + kq);
            cpasync16(asA + (uint32_t)((buf * ASZ + row * ASTR + kq) << 2), src);
        }
#pragma unroll
        for (int j = 0; j < 4; j++) {
            int i  = tid + (j << 8);
            int kr = i >> 5, nc = (i & 31) << 2;
            int gn = n0 + nc;
            if (gn < N) {
                const float* src = Bbp + (long long)(k0 + kr) * ldb + gn;
                cpasync16(asB + (uint32_t)((buf * BSZn + kr * BSTRN + nc) << 2), src);
            }
        }
    };

    doCopy(0, 0); cpcommit();

    for (int it = 0; it < nIter; ++it) {
        const int cur = it & 1;
        if (it + 1 < nIter) { doCopy(it + 1, cur ^ 1); cpcommit(); cpwait<1>(); }
        else                { cpwait<0>(); }
        __syncthreads();

        const float* pa = As + cur * ASZ;
        const float* pb = Bs + cur * BSZn;

#pragma unroll
        for (int kk = 0; kk < 32; kk += 16) {
            uint32_t ah[2][4], al[2][4];
#pragma unroll
            for (int mt = 0; mt < 2; mt++) {
                int r0 = (wm * 32 + mt * 16 + g) * ASTR + kk + 2 * t;
                int r1 = r0 + 8 * ASTR;
                split2(*(const float2*)&pa[r0],     ah[mt][0], al[mt][0]);
                split2(*(const float2*)&pa[r1],     ah[mt][1], al[mt][1]);
                split2(*(const float2*)&pa[r0 + 8], ah[mt][2], al[mt][2]);
                split2(*(const float2*)&pa[r1 + 8], ah[mt][3], al[mt][3]);
            }
            uint32_t bh[8][2], bl[8][2];
#pragma unroll
            for (int nt = 0; nt < 8; nt++) {
                int nc = wn * 64 + nt * 8 + g;
                const float* base = pb + (long long)(kk + 2 * t) * BSTRN + nc;
                float2 y0 = make_float2(base[0], base[BSTRN]);
                float2 y1 = make_float2(base[8 * BSTRN], base[9 * BSTRN]);
                split2(y0, bh[nt][0], bl[nt][0]);
                split2(y1, bh[nt][1], bl[nt][1]);
            }
#pragma unroll
            for (int mt = 0; mt < 2; mt++)
#pragma unroll
                for (int nt = 0; nt < 8; nt++) {
                    mma16(acc[mt][nt], ah[mt], bh[nt]);
                    mma16(acc[mt][nt], al[mt], bh[nt]);
                    mma16(acc[mt][nt], ah[mt], bl[nt]);
                }
        }
        __syncthreads();
    }

#pragma unroll
    for (int mt = 0; mt < 2; mt++) {
#pragma unroll
        for (int hrow = 0; hrow < 2; hrow++) {
            int m = m0 + wm * 32 + mt * 16 + g + hrow * 8;
            long long rowo = cOff + (long long)m * ldc;
#pragma unroll
            for (int nt = 0; nt < 8; nt++) {
                int n = n0 + wn * 64 + nt * 8 + 2 * t;
                if (n < N) {
                    float v0 = acc[mt][nt][hrow * 2 + 0];
                    float v1 = acc[mt][nt][hrow * 2 + 1];
                    uint32_t hi, lo;
                    split2(make_float2(v0, v1), hi, lo);
                    *(uint32_t*)(Ch + rowo + n) = hi;
                    *(uint32_t*)(Cl + rowo + n) = lo;
                }
            }
        }
    }
}

// --------------------------- elementwise kernels ---------------------------
// Transpose-convert: W [K,N] fp32 -> hi/lo [Npad,K] half (zero-padded rows).
__global__ void convw_kernel(const float* __restrict__ W,
                             __half* __restrict__ hi, __half* __restrict__ lo,
                             int K, int N, int Npad, long long inS, long long outS)
{
    __shared__ float tile[32][33];
    int z = blockIdx.z;
    const float* Wz = W + (long long)z * inS;
    int k0 = blockIdx.y * 32, n0 = blockIdx.x * 32;
    for (int r = threadIdx.y; r < 32; r += 8) {
        int k = k0 + r, n = n0 + threadIdx.x;
        tile[r][threadIdx.x] = (k < K && n < N) ? Wz[(long long)k * N + n] : 0.f;
    }
    __syncthreads();
    for (int r = threadIdx.y; r < 32; r += 8) {
        int n = n0 + r, k = k0 + threadIdx.x;
        if (n < Npad && k < K) {
            float v = tile[threadIdx.x][r];
            __half h = __float2half_rn(v);
            long long o = (long long)z * outS + (long long)n * K + k;
            hi[o] = h;
            lo[o] = __float2half_rn(v - __half2float(h));
        }
    }
}

__global__ void pack_qkv_kernel(const float* __restrict__ Wq, const float* __restrict__ Wk,
                                const float* __restrict__ Wv, float* __restrict__ wt) {
    int idx = blockIdx.x * 256 + threadIdx.x;
    int col = idx % 1536, d = idx / 1536;
    int sel = col >> 9, c = col & 511;
    int h = c >> 6, e = c & 63;
    const float* W = (sel == 0) ? Wq : (sel == 1) ? Wk : Wv;
    wt[idx] = W[(h * Dm_ + d) * Dk_ + e];
}

__global__ void conva_kernel(const float* __restrict__ src,
                             __half* __restrict__ hi, __half* __restrict__ lo, int n) {
    int i = blockIdx.x * 256 + threadIdx.x;
    if (i < n) {
        float v = src[i];
        __half h = __float2half_rn(v);
        hi[i] = h;
        lo[i] = __float2half_rn(v - __half2float(h));
    }
}

__global__ void embed_kernel(const int* __restrict__ tok, const float* __restrict__ emb,
                             float* __restrict__ x,
                             __half* __restrict__ xh, __half* __restrict__ xl) {
    int idx = blockIdx.x * 256 + threadIdx.x;
    int t = tok[idx >> 9];
    float v = emb[(long long)t * Dm_ + (idx & 511)] * 8.0f;
    x[idx] = v;
    __half h = __float2half_rn(v);
    xh[idx] = h;
    xl[idx] = __float2half_rn(v - __half2float(h));
}

__global__ void bn_stats_kernel(const float* __restrict__ x,
                                float* __restrict__ mu, float* __restrict__ rstd) {
    int d = blockIdx.x * 32 + threadIdx.x;
    float s = 0.f, s2 = 0.f;
    for (int i = threadIdx.y; i < BS_; i += 8) {
        float v = x[(long long)i * Dm_ + d];
        s += v; s2 += v * v;
    }
    __shared__ float sh[8][33], sh2[8][33];
    sh[threadIdx.y][threadIdx.x] = s;
    sh2[threadIdx.y][threadIdx.x] = s2;
    __syncthreads();
    if (threadIdx.y == 0) {
#pragma unroll
        for (int r = 1; r < 8; r++) { s += sh[r][threadIdx.x]; s2 += sh2[r][threadIdx.x]; }
        float m = s * (1.f / BS_);
        float var = s2 * (1.f / BS_) - m * m;
        mu[d] = m;
        rstd[d] = rsqrtf(var + 1e-5f);
    }
}

__global__ void bn_apply_kernel(const float* __restrict__ xin, float* __restrict__ xout,
                                __half* __restrict__ xh, __half* __restrict__ xl,
                                const float* __restrict__ mu, const float* __restrict__ rstd,
                                const float* __restrict__ gamma, const float* __restrict__ beta) {
    int idx = blockIdx.x * 256 + threadIdx.x;
    int d = idx & 511;
    float v = (xin[idx] - mu[d]) * rstd[d] * gamma[d] + beta[d];
    xout[idx] = v;
    __half h = __float2half_rn(v);
    xh[idx] = h;
    xl[idx] = __float2half_rn(v - __half2float(h));
}

// Online row softmax. Causal masks t > (row & 511).
__global__ void softmax_kernel(float* __restrict__ p, int T, int causal) {
    extern __shared__ float red[];
    float* mred = red;
    float* sred = red + blockDim.x;
    long long row = blockIdx.x;
    float* x = p + row * (long long)T;
    int s = (int)(row & 511);
    int nt = blockDim.x;
    int tmax = causal ? s : (T - 1);

    float m = -1e30f, sum = 0.f;
    for (int t = threadIdx.x; t <= tmax; t += nt) {
        float v = x[t];
        if (v > m) { sum = sum * __expf(m - v) + 1.f; m = v; }
        else       { sum += __expf(v - m); }
    }
    mred[threadIdx.x] = m; sred[threadIdx.x] = sum;
    __syncthreads();
    for (int o = nt >> 1; o > 0; o >>= 1) {
        if ((int)threadIdx.x < o) {
            float m2 = mred[threadIdx.x + o], s2 = sred[threadIdx.x + o];
            float m1 = mred[threadIdx.x],     s1 = sred[threadIdx.x];
            float M = fmaxf(m1, m2);
            sred[threadIdx.x] = s1 * __expf(m1 - M) + s2 * __expf(m2 - M);
            mred[threadIdx.x] = M;
        }
        __syncthreads();
    }
    float M = mred[0];
    float inv = 1.f / sred[0];
    for (int t = threadIdx.x; t < T; t += nt) {
        float v = (causal && t > s) ? 0.f : __expf(x[t] - M) * inv;
        x[t] = v;
    }
}

// ------------------------------- host side ---------------------------------
static inline int cdiv(int a, int b) { return (a + b - 1) / b; }

// plain (non-batched) half GEMM
static void gh(const __half* Ah, const __half* Al, const __half* Bh, const __half* Bl,
               float* C, __half* Ch, __half* Cl,
               const float* bias, const float* res,
               int M, int N, int K, int lda, int ldb, int ldc, int flags)
{
    dim3 g(cdiv(N, 128), M / 128, 1);
    gemm_h<<<g, 256, GH_SMEM>>>(Ah, Al, Bh, Bl, C, Ch, Cl, bias, res,
                                M, N, K, lda, ldb, ldc,
                                0, 0, 1, 0, 0, 1, 0, 0, 1, 1.f, flags);
}

extern "C" void kernel_launch(void* const* d_in, const int* in_sizes, int n_in,
                              void* d_out, int out_size)
{
    const int*   tok   = (const int*)  d_in[0];
    const float* enc   = (const float*)d_in[1];
    const float* emb   = (const float*)d_in[2];
    const float* Wq1   = (const float*)d_in[3];
    const float* Wk1   = (const float*)d_in[4];
    const float* Wv1   = (const float*)d_in[5];
    const float* Wo1   = (const float*)d_in[6];
    const float* Wq2   = (const float*)d_in[7];
    const float* Wk2   = (const float*)d_in[8];
    const float* Wv2   = (const float*)d_in[9];
    const float* Wo2   = (const float*)d_in[10];
    const float* gamma = (const float*)d_in[11];
    const float* beta  = (const float*)d_in[12];
    const float* W1    = (const float*)d_in[13];
    const float* b1    = (const float*)d_in[14];
    const float* W2    = (const float*)d_in[15];
    const float* b2    = (const float*)d_in[16];
    const float* Wout  = (const float*)d_in[17];
    const float* bout  = (const float*)d_in[18];
    float* out = (float*)d_out;

    cudaFuncSetAttribute(gemm_h,  cudaFuncAttributeMaxDynamicSharedMemorySize, GH_SMEM);
    cudaFuncSetAttribute(gemm_av, cudaFuncAttributeMaxDynamicSharedMemorySize, GEMM_SMEM_N);

    float *x, *tmp, *qkv, *sc, *wt, *mu, *rstd;
    cudaGetSymbolAddress((void**)&x,    g_x);
    cudaGetSymbolAddress((void**)&tmp,  g_tmp);
    cudaGetSymbolAddress((void**)&qkv,  g_qkv);
    cudaGetSymbolAddress((void**)&sc,   g_sc);
    cudaGetSymbolAddress((void**)&wt,   g_wt);
    cudaGetSymbolAddress((void**)&mu,   g_mu);
    cudaGetSymbolAddress((void**)&rstd, g_rstd);

    __half *xh, *xl, *qkvh, *qkvl, *attnh, *attnl, *ffh, *ffl, *ench, *encl;
    cudaGetSymbolAddress((void**)&xh,    g_xh);
    cudaGetSymbolAddress((void**)&xl,    g_xl);
    cudaGetSymbolAddress((void**)&qkvh,  g_qkvh);
    cudaGetSymbolAddress((void**)&qkvl,  g_qkvl);
    cudaGetSymbolAddress((void**)&attnh, g_attnh);
    cudaGetSymbolAddress((void**)&attnl, g_attnl);
    cudaGetSymbolAddress((void**)&ffh,   g_ffh);
    cudaGetSymbolAddress((void**)&ffl,   g_ffl);
    cudaGetSymbolAddress((void**)&ench,  g_ench);
    cudaGetSymbolAddress((void**)&encl,  g_encl);

    __half *wtT_h, *wtT_l, *w1T_h, *w1T_l, *w2T_h, *w2T_l;
    __half *wo1T_h, *wo1T_l, *wo2T_h, *wo2T_l, *woutT_h, *woutT_l;
    cudaGetSymbolAddress((void**)&wtT_h,  g_wtT_h);
    cudaGetSymbolAddress((void**)&wtT_l,  g_wtT_l);
    cudaGetSymbolAddress((void**)&w1T_h,  g_w1T_h);
    cudaGetSymbolAddress((void**)&w1T_l,  g_w1T_l);
    cudaGetSymbolAddress((void**)&w2T_h,  g_w2T_h);
    cudaGetSymbolAddress((void**)&w2T_l,  g_w2T_l);
    cudaGetSymbolAddress((void**)&wo1T_h, g_wo1T_h);
    cudaGetSymbolAddress((void**)&wo1T_l, g_wo1T_l);
    cudaGetSymbolAddress((void**)&wo2T_h, g_wo2T_h);
    cudaGetSymbolAddress((void**)&wo2T_l, g_wo2T_l);
    cudaGetSymbolAddress((void**)&woutT_h, g_woutT_h);
    cudaGetSymbolAddress((void**)&woutT_l, g_woutT_l);

    const long long HW  = (long long)Dm_ * Dk_;
    const long long QBh = (long long)Ss_ * 1536;          // per-batch stride
    const long long SCZ = (long long)Ss_ * Ss_;
    const float     isq = 0.125f;
    dim3 cb(32, 8);

    // ---- weight conversion (deterministic per launch) ----
    convw_kernel<<<dim3(Ff_/32, Dm_/32, Nx_), cb>>>(W1, w1T_h, w1T_l, Dm_, Ff_, Ff_,
                                                    (long long)Dm_*Ff_, (long long)Ff_*Dm_);
    convw_kernel<<<dim3(Dm_/32, Ff_/32, Nx_), cb>>>(W2, w2T_h, w2T_l, Ff_, Dm_, Dm_,
                                                    (long long)Ff_*Dm_, (long long)Dm_*Ff_);
    convw_kernel<<<dim3(Dm_/32, Dm_/32, Nx_), cb>>>(Wo1, wo1T_h, wo1T_l, Dm_, Dm_, Dm_,
                                                    (long long)Dm_*Dm_, (long long)Dm_*Dm_);
    convw_kernel<<<dim3(Dm_/32, Dm_/32, Nx_), cb>>>(Wo2, wo2T_h, wo2T_l, Dm_, Dm_, Dm_,
                                                    (long long)Dm_*Dm_, (long long)Dm_*Dm_);
    convw_kernel<<<dim3(VvP_/32, Dm_/32, 1), cb>>>(Wout, woutT_h, woutT_l, Dm_, Vv_, VvP_, 0, 0);
    for (int s = 0; s < 12; s++) {
        int i = s >> 1, pass = s & 1;
        if (pass == 0)
            pack_qkv_kernel<<<Dm_*1536/256, 256>>>(Wq1 + (long long)i*Hh_*HW,
                                                   Wk1 + (long long)i*Hh_*HW,
                                                   Wv1 + (long long)i*Hh_*HW, wt);
        else
            pack_qkv_kernel<<<Dm_*1536/256, 256>>>(Wq2 + (long long)i*Hh_*HW,
                                                   Wk2 + (long long)i*Hh_*HW,
                                                   Wv2 + (long long)i*Hh_*HW, wt);
        convw_kernel<<<dim3(1536/32, Dm_/32, 1), cb>>>(wt, wtT_h + (long long)s*1536*512,
                                                       wtT_l + (long long)s*1536*512,
                                                       Dm_, 1536, 1536, 0, 0);
    }
    // encoder halves — dedicated buffers (FIX for Round-6 aliasing bug)
    conva_kernel<<<cdiv(BS_*Dm_, 256), 256>>>(enc, ench, encl, BS_*Dm_);

    embed_kernel<<<BS_ * Dm_ / 256, 256>>>(tok, emb, x, xh, xl);

    for (int i = 0; i < Nx_; i++) {
        const float* bb1 = b1 + (long long)i * Ff_;
        const float* bb2 = b2 + (long long)i * Dm_;

        for (int attn_pass = 0; attn_pass < 2; attn_pass++) {
            const int self = (attn_pass == 0);
            const int s = i * 2 + attn_pass;
            const __half* wth = wtT_h + (long long)s * 1536 * 512;
            const __half* wtl = wtT_l + (long long)s * 1536 * 512;

            if (self) {
                gh(xh, xl, wth, wtl, qkv, qkvh, qkvl, nullptr, nullptr,
                   BS_, 1536, Dm_, Dm_, Dm_, 1536, 0);
            } else {
                gh(xh, xl, wth, wtl, qkv, qkvh, qkvl, nullptr, nullptr,
                   BS_, 512, Dm_, Dm_, Dm_, 1536, 0);
                // KV from encoder (wt rows 512..1535)
                dim3 g(8, 16, 1);
                gemm_h<<<g, 256, GH_SMEM>>>(ench, encl,
                                            wth + 512LL*512, wtl + 512LL*512,
                                            qkv + 512, qkvh + 512, qkvl + 512,
                                            nullptr, nullptr,
                                            BS_, 1024, Dm_, Dm_, Dm_, 1536,
                                            0, 0, 1, 0, 0, 1, 0, 0, 1, 1.f, 0);
            }
            // scores[z=b*8+h] = Q @ K^T * isq  (causal skip for self)
            {
                dim3 g(4, 4, Bb_ * Hh_);
                gemm_h<<<g, 256, GH_SMEM>>>(qkvh, qkvl, qkvh + 512, qkvl + 512,
                                            sc, nullptr, nullptr, nullptr, nullptr,
                                            Ss_, Ss_, Dk_, 1536, 1536, Ss_,
                                            QBh, 64, Hh_,  QBh, 64, Hh_,  SCZ, 0, 1,
                                            isq, self ? 2 : 0);
            }
            softmax_kernel<<<Bb_*Hh_*Ss_, 256, 2*256*4>>>(sc, Ss_, self ? 1 : 0);
            // attn[b,s,h*64+e] = probs @ V  (fp32 operands, emits halves)
            {
                dim3 g(1, 4, Bb_ * Hh_);
                gemm_av<<<g, 256, GEMM_SMEM_N>>>(sc, qkv + 1024, attnh, attnl,
                                                 Ss_, Dk_, Ss_, Ss_, 1536, Dm_,
                                                 SCZ, 0, 1,  QBh, 64, Hh_,
                                                 (long long)Ss_*Dm_, Dk_, Hh_);
            }
            // tmp = attn @ Wo + x
            const __half* woh = (self ? wo1T_h : wo2T_h) + (long long)i*512*512;
            const __half* wol = (self ? wo1T_l : wo2T_l) + (long long)i*512*512;
            gh(attnh, attnl, woh, wol, tmp, nullptr, nullptr, nullptr, x,
               BS_, Dm_, Dm_, Dm_, Dm_, Dm_, 0);
            bn_stats_kernel<<<Dm_/32, dim3(32, 8)>>>(tmp, mu, rstd);
            bn_apply_kernel<<<BS_*Dm_/256, 256>>>(tmp, x, xh, xl, mu, rstd,
                                                  gamma + (long long)(i*3 + attn_pass)*Dm_,
                                                  beta  + (long long)(i*3 + attn_pass)*Dm_);
        }

        // ---- feed-forward
        gh(xh, xl, w1T_h + (long long)i*Ff_*512, w1T_l + (long long)i*Ff_*512,
           nullptr, ffh, ffl, bb1, nullptr, BS_, Ff_, Dm_, Dm_, Dm_, Ff_, 1);
        gh(ffh, ffl, w2T_h + (long long)i*512LL*Ff_, w2T_l + (long long)i*512LL*Ff_,
           tmp, nullptr, nullptr, bb2, x, BS_, Dm_, Ff_, Ff_, Ff_, Dm_, 0);
        bn_stats_kernel<<<Dm_/32, dim3(32, 8)>>>(tmp, mu, rstd);
        bn_apply_kernel<<<BS_*Dm_/256, 256>>>(tmp, x, xh, xl, mu, rstd,
                                              gamma + (long long)(i*3 + 2)*Dm_,
                                              beta  + (long long)(i*3 + 2)*Dm_);
    }

    // ---- output projection + vocab softmax
    gh(xh, xl, woutT_h, woutT_l, out, nullptr, nullptr, bout, nullptr,
       BS_, Vv_, Dm_, Dm_, Dm_, Vv_, 0);
    softmax_kernel<<<BS_, 1024, 2*1024*4>>>(out, Vv_, 0);

    (void)in_sizes; (void)n_in; (void)out_size;
}

// round 8
// speedup vs baseline: 1.1455x; 1.1455x over previous
#include <cuda_runtime.h>
#include <cuda_fp16.h>
#include <math.h>
#include <stdint.h>

// ---------------------------------------------------------------------------
// Decoder — Round 8: fused/vectorized weight conversion + BN=64 GEMM variant
// ---------------------------------------------------------------------------

#define Bb_ 4
#define Ss_ 512
#define Dm_ 512
#define Hh_ 8
#define Dk_ 64
#define Ff_ 2048
#define Vv_ 37000
#define VvP_ 37120
#define Nx_ 6
#define BS_ 2048

// ------------------------- scratch (static device globals) -----------------
__device__ __align__(16) float g_x    [BS_*Dm_];
__device__ __align__(16) float g_tmp  [BS_*Dm_];
__device__ __align__(16) float g_qkv  [BS_*3*Dm_];     // fp32 (V read by AV gemm)
__device__ __align__(16) float g_sc   [Bb_*Hh_*Ss_*Ss_];
__device__ float g_mu   [Dm_];
__device__ float g_rstd [Dm_];

// hi/lo half activations
__device__ __align__(16) __half g_xh   [BS_*Dm_];
__device__ __align__(16) __half g_xl   [BS_*Dm_];
__device__ __align__(16) __half g_qkvh [BS_*3*Dm_];
__device__ __align__(16) __half g_qkvl [BS_*3*Dm_];
__device__ __align__(16) __half g_attnh[BS_*Dm_];
__device__ __align__(16) __half g_attnl[BS_*Dm_];
__device__ __align__(16) __half g_ffh  [BS_*Ff_];
__device__ __align__(16) __half g_ffl  [BS_*Ff_];
__device__ __align__(16) __half g_ench [BS_*Dm_];
__device__ __align__(16) __half g_encl [BS_*Dm_];

// hi/lo half weights, [N, K] K-major
__device__ __align__(16) __half g_wtT_h [12L*1536*512];
__device__ __align__(16) __half g_wtT_l [12L*1536*512];
__device__ __align__(16) __half g_w1T_h [6L*2048*512];
__device__ __align__(16) __half g_w1T_l [6L*2048*512];
__device__ __align__(16) __half g_w2T_h [6L*512*2048];
__device__ __align__(16) __half g_w2T_l [6L*512*2048];
__device__ __align__(16) __half g_wo1T_h[6L*512*512];
__device__ __align__(16) __half g_wo1T_l[6L*512*512];
__device__ __align__(16) __half g_wo2T_h[6L*512*512];
__device__ __align__(16) __half g_wo2T_l[6L*512*512];
__device__ __align__(16) __half g_woutT_h[(long long)VvP_*512];
__device__ __align__(16) __half g_woutT_l[(long long)VvP_*512];

// ------------------------------- helpers -----------------------------------
__device__ __forceinline__ void split2(float2 x, uint32_t& hi, uint32_t& lo) {
    __half2 h = __float22half2_rn(x);
    float2 hf = __half22float2(h);
    __half2 l = __float22half2_rn(make_float2(x.x - hf.x, x.y - hf.y));
    hi = *reinterpret_cast<uint32_t*>(&h);
    lo = *reinterpret_cast<uint32_t*>(&l);
}
__device__ __forceinline__ void cpasync16(uint32_t dst, const void* src) {
    asm volatile("cp.async.cg.shared.global [%0], [%1], 16;"
                 :: "r"(dst), "l"(src));
}
__device__ __forceinline__ void cpcommit() { asm volatile("cp.async.commit_group;"); }
template <int NN> __device__ __forceinline__ void cpwait() {
    asm volatile("cp.async.wait_group %0;" :: "n"(NN));
}
__device__ __forceinline__ void mma16(float* d, const uint32_t* a, const uint32_t* b) {
    asm volatile(
        "mma.sync.aligned.m16n8k16.row.col.f32.f16.f16.f32 "
        "{%0,%1,%2,%3}, {%4,%5,%6,%7}, {%8,%9}, {%0,%1,%2,%3};"
        : "+f"(d[0]), "+f"(d[1]), "+f"(d[2]), "+f"(d[3])
        : "r"(a[0]), "r"(a[1]), "r"(a[2]), "r"(a[3]), "r"(b[0]), "r"(b[1]));
}
__device__ __forceinline__ void ldsm4(uint32_t* r, uint32_t addr) {
    asm volatile("ldmatrix.sync.aligned.m8n8.x4.shared.b16 {%0,%1,%2,%3}, [%4];"
                 : "=r"(r[0]), "=r"(r[1]), "=r"(r[2]), "=r"(r[3]) : "r"(addr));
}

// ------------------------ GEMM: pure-half operands --------------------------
// C[z] = alpha * A @ B^T (+bias)(+res)(relu). A: hi/lo half [M,K]; B: hi/lo
// half [N,K]. Tile 128xBN x32 (BN = NT*16), 8 warps (4m x 2n), ldmatrix
// fragments, 3-pass hi/lo fp16 split => fp32 accuracy.
// flags: bit0 relu, bit1 causal-skip.
#define HSTRB 80
#define HARR  (128*HSTRB)

template <int NT>
__global__ __launch_bounds__(256) void gemm_h(
    const __half* __restrict__ Ah, const __half* __restrict__ Al,
    const __half* __restrict__ Bh, const __half* __restrict__ Bl,
    float* __restrict__ C, __half* __restrict__ Ch, __half* __restrict__ Cl,
    const float* __restrict__ bias, const float* __restrict__ res,
    int M, int N, int K, int lda, int ldb, int ldc,
    long long aS1, long long aS2, int aDiv,
    long long bS1, long long bS2, int bDiv,
    long long cS1, long long cS2, int cDiv,
    float alpha, int flags)
{
    constexpr int BN   = NT * 16;
    constexpr int BARR = BN * HSTRB;
    constexpr int STG  = 2 * HARR + 2 * BARR;

    extern __shared__ char smh[];
    const int m0 = blockIdx.y * 128, n0 = blockIdx.x * BN;
    if ((flags & 2) && n0 >= m0 + 128) return;      // causal: fully-masked tile

    const int z = blockIdx.z;
    const long long aOff = (long long)(z / aDiv) * aS1 + (long long)(z % aDiv) * aS2;
    const long long bOff = (long long)(z / bDiv) * bS1 + (long long)(z % bDiv) * bS2;
    const long long cOff = (long long)(z / cDiv) * cS1 + (long long)(z % cDiv) * cS2;
    const __half* Ahb = Ah + aOff;
    const __half* Alb = Al + aOff;
    const __half* Bhb = Bh + bOff;
    const __half* Blb = Bl + bOff;

    const uint32_t sb = (uint32_t)__cvta_generic_to_shared(smh);
    const int tid = threadIdx.x;
    const int wid = tid >> 5, lane = tid & 31;
    const int wm = wid & 3, wn = wid >> 2;
    const int g = lane >> 2, t = lane & 3;

    const int aRow = lane & 15, aChk = lane >> 4;
    const int bRow = (lane & 7) + ((lane >> 4) << 3);
    const int bChk = (lane >> 3) & 1;

    float acc[2][NT][4];
#pragma unroll
    for (int i = 0; i < 2; i++)
#pragma unroll
        for (int j = 0; j < NT; j++)
#pragma unroll
            for (int r = 0; r < 4; r++) acc[i][j][r] = 0.f;

    const int T = K >> 5;

    auto stage = [&](int it, int buf) {
        const int k0 = it << 5;
        uint32_t dst = sb + buf * STG;
#pragma unroll
        for (int j = 0; j < 2; j++) {               // A: 512 chunks
            int idx = tid + (j << 8);
            int row = idx >> 2, c = idx & 3;
            long long asrc = (long long)(m0 + row) * lda + k0 + c * 8;
            uint32_t so = (uint32_t)(row * HSTRB + c * 16);
            cpasync16(dst + 0 * HARR + so, Ahb + asrc);
            cpasync16(dst + 1 * HARR + so, Alb + asrc);
        }
#pragma unroll
        for (int j = 0; j < NT / 4; j++) {          // B: BN*4 chunks
            int idx = tid + (j << 8);
            int row = idx >> 2, c = idx & 3;
            long long bsrc = (long long)(n0 + row) * ldb + k0 + c * 8;
            uint32_t so = (uint32_t)(row * HSTRB + c * 16);
            cpasync16(dst + 2 * HARR + so, Bhb + bsrc);
            cpasync16(dst + 2 * HARR + BARR + so, Blb + bsrc);
        }
    };

    stage(0, 0); cpcommit();

    for (int it = 0; it < T; ++it) {
        const int cur = it & 1;
        if (it + 1 < T) { stage(it + 1, cur ^ 1); cpcommit(); cpwait<1>(); }
        else            { cpwait<0>(); }
        __syncthreads();

        uint32_t base = sb + cur * STG;
        uint32_t aH = base + 0 * HARR + (uint32_t)((wm * 32 + aRow) * HSTRB + aChk * 16);
        uint32_t aL = base + 1 * HARR + (uint32_t)((wm * 32 + aRow) * HSTRB + aChk * 16);
        uint32_t bH = base + 2 * HARR + (uint32_t)((wn * (NT * 8) + bRow) * HSTRB + bChk * 16);
        uint32_t bL = bH + BARR;

#pragma unroll
        for (int kk = 0; kk < 2; kk++) {            // two k16 steps
            const uint32_t ko = kk << 5;
            uint32_t ah[2][4], al[2][4];
#pragma unroll
            for (int mt = 0; mt < 2; mt++) {
                ldsm4(ah[mt], aH + mt * (16 * HSTRB) + ko);
                ldsm4(al[mt], aL + mt * (16 * HSTRB) + ko);
            }
            uint32_t bh[NT / 2][4], bl[NT / 2][4];
#pragma unroll
            for (int p = 0; p < NT / 2; p++) {
                ldsm4(bh[p], bH + p * (16 * HSTRB) + ko);
                ldsm4(bl[p], bL + p * (16 * HSTRB) + ko);
            }
#pragma unroll
            for (int mt = 0; mt < 2; mt++)
#pragma unroll
                for (int p = 0; p < NT / 2; p++) {
                    mma16(acc[mt][2*p],   ah[mt], &bh[p][0]);
                    mma16(acc[mt][2*p],   al[mt], &bh[p][0]);
                    mma16(acc[mt][2*p],   ah[mt], &bl[p][0]);
                    mma16(acc[mt][2*p+1], ah[mt], &bh[p][2]);
                    mma16(acc[mt][2*p+1], al[mt], &bh[p][2]);
                    mma16(acc[mt][2*p+1], ah[mt], &bl[p][2]);
                }
        }
        __syncthreads();
    }

    // ------------------------------ epilogue --------------------------------
    const bool relu = flags & 1;
#pragma unroll
    for (int mt = 0; mt < 2; mt++) {
#pragma unroll
        for (int hrow = 0; hrow < 2; hrow++) {
            int m = m0 + wm * 32 + mt * 16 + g + hrow * 8;
            long long rowo = cOff + (long long)m * ldc;
#pragma unroll
            for (int nt = 0; nt < NT; nt++) {
                int n = n0 + wn * (NT * 8) + nt * 8 + 2 * t;
                if (n < N) {
                    float v0 = acc[mt][nt][hrow * 2 + 0] * alpha;
                    float v1 = acc[mt][nt][hrow * 2 + 1] * alpha;
                    if (bias) { v0 += bias[n]; v1 += bias[n + 1]; }
                    if (res) {
                        const float* rp = res + rowo;
                        v0 += rp[n]; v1 += rp[n + 1];
                    }
                    if (relu) { v0 = fmaxf(v0, 0.f); v1 = fmaxf(v1, 0.f); }
                    if (C) {
                        float2 vv; vv.x = v0; vv.y = v1;
                        *(float2*)(C + rowo + n) = vv;
                    }
                    if (Ch) {
                        uint32_t hi, lo;
                        split2(make_float2(v0, v1), hi, lo);
                        *(uint32_t*)(Ch + rowo + n) = hi;
                        *(uint32_t*)(Cl + rowo + n) = lo;
                    }
                }
            }
        }
    }
}

#define GH_SMEM8 (2 * (2 * HARR + 2 * 128 * HSTRB))   // 81920
#define GH_SMEM4 (2 * (2 * HARR + 2 * 64 * HSTRB))    // 61440

// -------------------- AV GEMM (fp32 A=probs, fp32 B=[k][n]) -----------------
#define ASTR 40
#define BSTRN 132
#define ASZ (128*ASTR)
#define BSZn (32*BSTRN)
#define GEMM_SMEM_N ((2*ASZ + 2*BSZn)*4)

__global__ __launch_bounds__(256) void gemm_av(
    const float* __restrict__ A, const float* __restrict__ B,
    __half* __restrict__ Ch, __half* __restrict__ Cl,
    int M, int N, int K, int lda, int ldb, int ldc,
    long long aS1, long long aS2, int aDiv,
    long long bS1, long long bS2, int bDiv,
    long long cS1, long long cS2, int cDiv)
{
    extern __shared__ float sm[];
    const int z = blockIdx.z;
    const float* Ab  = A + (long long)(z / aDiv) * aS1 + (long long)(z % aDiv) * aS2;
    const float* Bbp = B + (long long)(z / bDiv) * bS1 + (long long)(z % bDiv) * bS2;
    const long long cOff = (long long)(z / cDiv) * cS1 + (long long)(z % cDiv) * cS2;

    float* As = sm;
    float* Bs = sm + 2 * ASZ;

    const int tid  = threadIdx.x;
    const int wid  = tid >> 5, lane = tid & 31;
    const int wm   = wid & 3,  wn   = wid >> 2;
    const int g    = lane >> 2, t   = lane & 3;
    const int m0   = blockIdx.y * 128, n0 = blockIdx.x * 128;

    const uint32_t asA = (uint32_t)__cvta_generic_to_shared(As);
    const uint32_t asB = (uint32_t)__cvta_generic_to_shared(Bs);

    float acc[2][8][4];
#pragma unroll
    for (int i = 0; i < 2; i++)
#pragma unroll
        for (int j = 0; j < 8; j++)
#pragma unroll
            for (int r = 0; r < 4; r++) acc[i][j][r] = 0.f;

    const int nIter = K >> 5;

    auto doCopy = [&](int it, int buf) {
        const int k0 = it << 5;
#pragma unroll
        for (int j = 0; j < 4; j++) {
            int i   = tid + (j << 8);
            int row = i >> 3, kq = (i & 7) << 2;
            const float* src = Ab + (long long)(m0 + row) * lda + (k0 + kq);
            cpasync16(asA + (uint32_t)((buf * ASZ + row * ASTR + kq) << 2), src);
        }
#pragma unroll
        for (int j = 0; j < 4; j++) {
            int i  = tid + (j << 8);
            int kr = i >> 5, nc = (i & 31) << 2;
            int gn = n0 + nc;
            if (gn < N) {
                const float* src = Bbp + (long long)(k0 + kr) * ldb + gn;
                cpasync16(asB + (uint32_t)((buf * BSZn + kr * BSTRN + nc) << 2), src);
            }
        }
    };

    doCopy(0, 0); cpcommit();

    for (int it = 0; it < nIter; ++it) {
        const int cur = it & 1;
        if (it + 1 < nIter) { doCopy(it + 1, cur ^ 1); cpcommit(); cpwait<1>(); }
        else                { cpwait<0>(); }
        __syncthreads();

        const float* pa = As + cur * ASZ;
        const float* pb = Bs + cur * BSZn;

#pragma unroll
        for (int kk = 0; kk < 32; kk += 16) {
            uint32_t ah[2][4], al[2][4];
#pragma unroll
            for (int mt = 0; mt < 2; mt++) {
                int r0 = (wm * 32 + mt * 16 + g) * ASTR + kk + 2 * t;
                int r1 = r0 + 8 * ASTR;
                split2(*(const float2*)&pa[r0],     ah[mt][0], al[mt][0]);
                split2(*(const float2*)&pa[r1],     ah[mt][1], al[mt][1]);
                split2(*(const float2*)&pa[r0 + 8], ah[mt][2], al[mt][2]);
                split2(*(const float2*)&pa[r1 + 8], ah[mt][3], al[mt][3]);
            }
            uint32_t bh[8][2], bl[8][2];
#pragma unroll
            for (int nt = 0; nt < 8; nt++) {
                int nc = wn * 64 + nt * 8 + g;
                const float* base = pb + (long long)(kk + 2 * t) * BSTRN + nc;
                float2 y0 = make_float2(base[0], base[BSTRN]);
                float2 y1 = make_float2(base[8 * BSTRN], base[9 * BSTRN]);
                split2(y0, bh[nt][0], bl[nt][0]);
                split2(y1, bh[nt][1], bl[nt][1]);
            }
#pragma unroll
            for (int mt = 0; mt < 2; mt++)
#pragma unroll
                for (int nt = 0; nt < 8; nt++) {
                    mma16(acc[mt][nt], ah[mt], bh[nt]);
                    mma16(acc[mt][nt], al[mt], bh[nt]);
                    mma16(acc[mt][nt], ah[mt], bl[nt]);
                }
        }
        __syncthreads();
    }

#pragma unroll
    for (int mt = 0; mt < 2; mt++) {
#pragma unroll
        for (int hrow = 0; hrow < 2; hrow++) {
            int m = m0 + wm * 32 + mt * 16 + g + hrow * 8;
            long long rowo = cOff + (long long)m * ldc;
#pragma unroll
            for (int nt = 0; nt < 8; nt++) {
                int n = n0 + wn * 64 + nt * 8 + 2 * t;
                if (n < N) {
                    uint32_t hi, lo;
                    split2(make_float2(acc[mt][nt][hrow * 2], acc[mt][nt][hrow * 2 + 1]), hi, lo);
                    *(uint32_t*)(Ch + rowo + n) = hi;
                    *(uint32_t*)(Cl + rowo + n) = lo;
                }
            }
        }
    }
}

// --------------------------- conversion kernels -----------------------------
// Transpose-convert: W [K,N] fp32 -> hi/lo [Npad,K] halves. Tile 32k x 64n.
__global__ void convw_kernel(const float* __restrict__ W,
                             __half* __restrict__ hi, __half* __restrict__ lo,
                             int K, int N, int Npad, long long inS, long long outS)
{
    __shared__ float tile[32][65];
    int z = blockIdx.z;
    const float* Wz = W + (long long)z * inS;
    int k0 = blockIdx.y * 32, n0 = blockIdx.x * 64;
    int tid = threadIdx.x;

#pragma unroll
    for (int j = 0; j < 2; j++) {                // 512 float4 loads
        int idx = tid + (j << 8);
        int k = idx >> 4, nq = (idx & 15) << 2;
        int n = n0 + nq;
        float4 v = make_float4(0.f, 0.f, 0.f, 0.f);
        const float* p = Wz + (long long)(k0 + k) * N;
        if (n + 3 < N) v = *(const float4*)(p + n);
        else {
            if (n + 0 < N) v.x = p[n + 0];
            if (n + 1 < N) v.y = p[n + 1];
            if (n + 2 < N) v.z = p[n + 2];
            if (n + 3 < N) v.w = p[n + 3];
        }
        tile[k][nq + 0] = v.x; tile[k][nq + 1] = v.y;
        tile[k][nq + 2] = v.z; tile[k][nq + 3] = v.w;
    }
    __syncthreads();

#pragma unroll
    for (int j = 0; j < 4; j++) {                // 1024 half2 pairs
        int idx = tid + (j << 8);
        int n = idx >> 4, tq = (idx & 15) << 1;
        int gn = n0 + n;
        if (gn < Npad) {
            float v0 = tile[tq][n], v1 = tile[tq + 1][n];
            __half2 h = __floats2half2_rn(v0, v1);
            float2 hf = __half22float2(h);
            __half2 l = __floats2half2_rn(v0 - hf.x, v1 - hf.y);
            long long o = (long long)z * outS + (long long)gn * K + k0 + tq;
            *(__half2*)(hi + o) = h;
            *(__half2*)(lo + o) = l;
        }
    }
}

// Fused QKV pack+convert: Wq/Wk/Wv [H,512,64] -> wtT [1536][512] halves.
// grid (16 k-tiles, 24 = sel*8+h), block 256.
__global__ void convqkv_kernel(const float* __restrict__ Wq, const float* __restrict__ Wk,
                               const float* __restrict__ Wv,
                               __half* __restrict__ hi, __half* __restrict__ lo)
{
    __shared__ float tile[32][65];
    int kt = blockIdx.x, sh = blockIdx.y;
    int sel = sh >> 3, h = sh & 7;
    const float* W = (sel == 0) ? Wq : (sel == 1) ? Wk : Wv;
    const float* src = W + ((long long)h * 512 + kt * 32) * 64;
    int tid = threadIdx.x;

#pragma unroll
    for (int j = 0; j < 2; j++) {
        int idx = tid + (j << 8);
        int k = idx >> 4, eq = (idx & 15) << 2;
        float4 v = *(const float4*)(src + k * 64 + eq);
        tile[k][eq + 0] = v.x; tile[k][eq + 1] = v.y;
        tile[k][eq + 2] = v.z; tile[k][eq + 3] = v.w;
    }
    __syncthreads();

#pragma unroll
    for (int j = 0; j < 4; j++) {
        int idx = tid + (j << 8);
        int e = idx >> 4, tq = (idx & 15) << 1;
        int n = sel * 512 + h * 64 + e;
        float v0 = tile[tq][e], v1 = tile[tq + 1][e];
        __half2 hh = __floats2half2_rn(v0, v1);
        float2 hf = __half22float2(hh);
        __half2 ll = __floats2half2_rn(v0 - hf.x, v1 - hf.y);
        long long o = (long long)n * 512 + kt * 32 + tq;
        *(__half2*)(hi + o) = hh;
        *(__half2*)(lo + o) = ll;
    }
}

__global__ void conva_kernel(const float* __restrict__ src,
                             __half* __restrict__ hi, __half* __restrict__ lo, int n) {
    int i = blockIdx.x * 256 + threadIdx.x;
    if (i < n) {
        float v = src[i];
        __half h = __float2half_rn(v);
        hi[i] = h;
        lo[i] = __float2half_rn(v - __half2float(h));
    }
}

// --------------------------- elementwise kernels ---------------------------
__global__ void embed_kernel(const int* __restrict__ tok, const float* __restrict__ emb,
                             float* __restrict__ x,
                             __half* __restrict__ xh, __half* __restrict__ xl) {
    int idx = blockIdx.x * 256 + threadIdx.x;
    int t = tok[idx >> 9];
    float v = emb[(long long)t * Dm_ + (idx & 511)] * 8.0f;
    x[idx] = v;
    __half h = __float2half_rn(v);
    xh[idx] = h;
    xl[idx] = __float2half_rn(v - __half2float(h));
}

__global__ void bn_stats_kernel(const float* __restrict__ x,
                                float* __restrict__ mu, float* __restrict__ rstd) {
    int d = blockIdx.x * 32 + threadIdx.x;
    float s = 0.f, s2 = 0.f;
    for (int i = threadIdx.y; i < BS_; i += 8) {
        float v = x[(long long)i * Dm_ + d];
        s += v; s2 += v * v;
    }
    __shared__ float sh[8][33], sh2[8][33];
    sh[threadIdx.y][threadIdx.x] = s;
    sh2[threadIdx.y][threadIdx.x] = s2;
    __syncthreads();
    if (threadIdx.y == 0) {
#pragma unroll
        for (int r = 1; r < 8; r++) { s += sh[r][threadIdx.x]; s2 += sh2[r][threadIdx.x]; }
        float m = s * (1.f / BS_);
        float var = s2 * (1.f / BS_) - m * m;
        mu[d] = m;
        rstd[d] = rsqrtf(var + 1e-5f);
    }
}

__global__ void bn_apply_kernel(const float* __restrict__ xin, float* __restrict__ xout,
                                __half* __restrict__ xh, __half* __restrict__ xl,
                                const float* __restrict__ mu, const float* __restrict__ rstd,
                                const float* __restrict__ gamma, const float* __restrict__ beta) {
    int idx = blockIdx.x * 256 + threadIdx.x;
    int d = idx & 511;
    float v = (xin[idx] - mu[d]) * rstd[d] * gamma[d] + beta[d];
    xout[idx] = v;
    __half h = __float2half_rn(v);
    xh[idx] = h;
    xl[idx] = __float2half_rn(v - __half2float(h));
}

// Online row softmax. Causal masks t > (row & 511).
__global__ void softmax_kernel(float* __restrict__ p, int T, int causal) {
    extern __shared__ float red[];
    float* mred = red;
    float* sred = red + blockDim.x;
    long long row = blockIdx.x;
    float* x = p + row * (long long)T;
    int s = (int)(row & 511);
    int nt = blockDim.x;
    int tmax = causal ? s : (T - 1);

    float m = -1e30f, sum = 0.f;
    for (int t = threadIdx.x; t <= tmax; t += nt) {
        float v = x[t];
        if (v > m) { sum = sum * __expf(m - v) + 1.f; m = v; }
        else       { sum += __expf(v - m); }
    }
    mred[threadIdx.x] = m; sred[threadIdx.x] = sum;
    __syncthreads();
    for (int o = nt >> 1; o > 0; o >>= 1) {
        if ((int)threadIdx.x < o) {
            float m2 = mred[threadIdx.x + o], s2 = sred[threadIdx.x + o];
            float m1 = mred[threadIdx.x],     s1 = sred[threadIdx.x];
            float M = fmaxf(m1, m2);
            sred[threadIdx.x] = s1 * __expf(m1 - M) + s2 * __expf(m2 - M);
            mred[threadIdx.x] = M;
        }
        __syncthreads();
    }
    float M = mred[0];
    float inv = 1.f / sred[0];
    for (int t = threadIdx.x; t < T; t += nt) {
        float v = (causal && t > s) ? 0.f : __expf(x[t] - M) * inv;
        x[t] = v;
    }
}

// ------------------------------- host side ---------------------------------
static inline int cdiv(int a, int b) { return (a + b - 1) / b; }

// plain (non-batched) half GEMM, BN=128
static void gh8(const __half* Ah, const __half* Al, const __half* Bh, const __half* Bl,
                float* C, __half* Ch, __half* Cl,
                const float* bias, const float* res,
                int M, int N, int K, int lda, int ldb, int ldc, int flags)
{
    dim3 g(cdiv(N, 128), M / 128, 1);
    gemm_h<8><<<g, 256, GH_SMEM8>>>(Ah, Al, Bh, Bl, C, Ch, Cl, bias, res,
                                    M, N, K, lda, ldb, ldc,
                                    0, 0, 1, 0, 0, 1, 0, 0, 1, 1.f, flags);
}
// BN=64 variant for small-N shapes (better chip fill)
static void gh4(const __half* Ah, const __half* Al, const __half* Bh, const __half* Bl,
                float* C, __half* Ch, __half* Cl,
                const float* bias, const float* res,
                int M, int N, int K, int lda, int ldb, int ldc, int flags)
{
    dim3 g(cdiv(N, 64), M / 128, 1);
    gemm_h<4><<<g, 256, GH_SMEM4>>>(Ah, Al, Bh, Bl, C, Ch, Cl, bias, res,
                                    M, N, K, lda, ldb, ldc,
                                    0, 0, 1, 0, 0, 1, 0, 0, 1, 1.f, flags);
}

extern "C" void kernel_launch(void* const* d_in, const int* in_sizes, int n_in,
                              void* d_out, int out_size)
{
    const int*   tok   = (const int*)  d_in[0];
    const float* enc   = (const float*)d_in[1];
    const float* emb   = (const float*)d_in[2];
    const float* Wq1   = (const float*)d_in[3];
    const float* Wk1   = (const float*)d_in[4];
    const float* Wv1   = (const float*)d_in[5];
    const float* Wo1   = (const float*)d_in[6];
    const float* Wq2   = (const float*)d_in[7];
    const float* Wk2   = (const float*)d_in[8];
    const float* Wv2   = (const float*)d_in[9];
    const float* Wo2   = (const float*)d_in[10];
    const float* gamma = (const float*)d_in[11];
    const float* beta  = (const float*)d_in[12];
    const float* W1    = (const float*)d_in[13];
    const float* b1    = (const float*)d_in[14];
    const float* W2    = (const float*)d_in[15];
    const float* b2    = (const float*)d_in[16];
    const float* Wout  = (const float*)d_in[17];
    const float* bout  = (const float*)d_in[18];
    float* out = (float*)d_out;

    cudaFuncSetAttribute(gemm_h<8>, cudaFuncAttributeMaxDynamicSharedMemorySize, GH_SMEM8);
    cudaFuncSetAttribute(gemm_h<4>, cudaFuncAttributeMaxDynamicSharedMemorySize, GH_SMEM4);
    cudaFuncSetAttribute(gemm_av,   cudaFuncAttributeMaxDynamicSharedMemorySize, GEMM_SMEM_N);

    float *x, *tmp, *qkv, *sc, *mu, *rstd;
    cudaGetSymbolAddress((void**)&x,    g_x);
    cudaGetSymbolAddress((void**)&tmp,  g_tmp);
    cudaGetSymbolAddress((void**)&qkv,  g_qkv);
    cudaGetSymbolAddress((void**)&sc,   g_sc);
    cudaGetSymbolAddress((void**)&mu,   g_mu);
    cudaGetSymbolAddress((void**)&rstd, g_rstd);

    __half *xh, *xl, *qkvh, *qkvl, *attnh, *attnl, *ffh, *ffl, *ench, *encl;
    cudaGetSymbolAddress((void**)&xh,    g_xh);
    cudaGetSymbolAddress((void**)&xl,    g_xl);
    cudaGetSymbolAddress((void**)&qkvh,  g_qkvh);
    cudaGetSymbolAddress((void**)&qkvl,  g_qkvl);
    cudaGetSymbolAddress((void**)&attnh, g_attnh);
    cudaGetSymbolAddress((void**)&attnl, g_attnl);
    cudaGetSymbolAddress((void**)&ffh,   g_ffh);
    cudaGetSymbolAddress((void**)&ffl,   g_ffl);
    cudaGetSymbolAddress((void**)&ench,  g_ench);
    cudaGetSymbolAddress((void**)&encl,  g_encl);

    __half *wtT_h, *wtT_l, *w1T_h, *w1T_l, *w2T_h, *w2T_l;
    __half *wo1T_h, *wo1T_l, *wo2T_h, *wo2T_l, *woutT_h, *woutT_l;
    cudaGetSymbolAddress((void**)&wtT_h,  g_wtT_h);
    cudaGetSymbolAddress((void**)&wtT_l,  g_wtT_l);
    cudaGetSymbolAddress((void**)&w1T_h,  g_w1T_h);
    cudaGetSymbolAddress((void**)&w1T_l,  g_w1T_l);
    cudaGetSymbolAddress((void**)&w2T_h,  g_w2T_h);
    cudaGetSymbolAddress((void**)&w2T_l,  g_w2T_l);
    cudaGetSymbolAddress((void**)&wo1T_h, g_wo1T_h);
    cudaGetSymbolAddress((void**)&wo1T_l, g_wo1T_l);
    cudaGetSymbolAddress((void**)&wo2T_h, g_wo2T_h);
    cudaGetSymbolAddress((void**)&wo2T_l, g_wo2T_l);
    cudaGetSymbolAddress((void**)&woutT_h, g_woutT_h);
    cudaGetSymbolAddress((void**)&woutT_l, g_woutT_l);

    const long long HW  = (long long)Dm_ * Dk_;
    const long long QBh = (long long)Ss_ * 1536;
    const long long SCZ = (long long)Ss_ * Ss_;
    const float     isq = 0.125f;

    // ---- weight conversion (fused + vectorized) ----
    convw_kernel<<<dim3(Ff_/64, Dm_/32, Nx_), 256>>>(W1, w1T_h, w1T_l, Dm_, Ff_, Ff_,
                                                     (long long)Dm_*Ff_, (long long)Ff_*Dm_);
    convw_kernel<<<dim3(Dm_/64, Ff_/32, Nx_), 256>>>(W2, w2T_h, w2T_l, Ff_, Dm_, Dm_,
                                                     (long long)Ff_*Dm_, (long long)Dm_*Ff_);
    convw_kernel<<<dim3(Dm_/64, Dm_/32, Nx_), 256>>>(Wo1, wo1T_h, wo1T_l, Dm_, Dm_, Dm_,
                                                     (long long)Dm_*Dm_, (long long)Dm_*Dm_);
    convw_kernel<<<dim3(Dm_/64, Dm_/32, Nx_), 256>>>(Wo2, wo2T_h, wo2T_l, Dm_, Dm_, Dm_,
                                                     (long long)Dm_*Dm_, (long long)Dm_*Dm_);
    convw_kernel<<<dim3(VvP_/64, Dm_/32, 1), 256>>>(Wout, woutT_h, woutT_l, Dm_, Vv_, VvP_, 0, 0);
    for (int s = 0; s < 12; s++) {
        int i = s >> 1, pass = s & 1;
        const float* wq = pass ? Wq2 : Wq1;
        const float* wk = pass ? Wk2 : Wk1;
        const float* wv = pass ? Wv2 : Wv1;
        convqkv_kernel<<<dim3(16, 24), 256>>>(wq + (long long)i*Hh_*HW,
                                              wk + (long long)i*Hh_*HW,
                                              wv + (long long)i*Hh_*HW,
                                              wtT_h + (long long)s*1536*512,
                                              wtT_l + (long long)s*1536*512);
    }
    conva_kernel<<<cdiv(BS_*Dm_, 256), 256>>>(enc, ench, encl, BS_*Dm_);

    embed_kernel<<<BS_ * Dm_ / 256, 256>>>(tok, emb, x, xh, xl);

    for (int i = 0; i < Nx_; i++) {
        const float* bb1 = b1 + (long long)i * Ff_;
        const float* bb2 = b2 + (long long)i * Dm_;

        for (int attn_pass = 0; attn_pass < 2; attn_pass++) {
            const int self = (attn_pass == 0);
            const int s = i * 2 + attn_pass;
            const __half* wth = wtT_h + (long long)s * 1536 * 512;
            const __half* wtl = wtT_l + (long long)s * 1536 * 512;

            if (self) {
                gh8(xh, xl, wth, wtl, qkv, qkvh, qkvl, nullptr, nullptr,
                    BS_, 1536, Dm_, Dm_, Dm_, 1536, 0);
            } else {
                // Q projection: N=512 -> BN=64 variant (128 CTAs)
                gh4(xh, xl, wth, wtl, qkv, qkvh, qkvl, nullptr, nullptr,
                    BS_, 512, Dm_, Dm_, Dm_, 1536, 0);
                // KV from encoder (wt rows 512..1535)
                dim3 g(8, 16, 1);
                gemm_h<8><<<g, 256, GH_SMEM8>>>(ench, encl,
                                                wth + 512LL*512, wtl + 512LL*512,
                                                qkv + 512, qkvh + 512, qkvl + 512,
                                                nullptr, nullptr,
                                                BS_, 1024, Dm_, Dm_, Dm_, 1536,
                                                0, 0, 1, 0, 0, 1, 0, 0, 1, 1.f, 0);
            }
            // scores[z=b*8+h] = Q @ K^T * isq  (causal skip for self)
            {
                dim3 g(4, 4, Bb_ * Hh_);
                gemm_h<8><<<g, 256, GH_SMEM8>>>(qkvh, qkvl, qkvh + 512, qkvl + 512,
                                                sc, nullptr, nullptr, nullptr, nullptr,
                                                Ss_, Ss_, Dk_, 1536, 1536, Ss_,
                                                QBh, 64, Hh_,  QBh, 64, Hh_,  SCZ, 0, 1,
                                                isq, self ? 2 : 0);
            }
            softmax_kernel<<<Bb_*Hh_*Ss_, 256, 2*256*4>>>(sc, Ss_, self ? 1 : 0);
            // attn[b,s,h*64+e] = probs @ V
            {
                dim3 g(1, 4, Bb_ * Hh_);
                gemm_av<<<g, 256, GEMM_SMEM_N>>>(sc, qkv + 1024, attnh, attnl,
                                                 Ss_, Dk_, Ss_, Ss_, 1536, Dm_,
                                                 SCZ, 0, 1,  QBh, 64, Hh_,
                                                 (long long)Ss_*Dm_, Dk_, Hh_);
            }
            // tmp = attn @ Wo + x  (N=512 -> BN=64 variant)
            const __half* woh = (self ? wo1T_h : wo2T_h) + (long long)i*512*512;
            const __half* wol = (self ? wo1T_l : wo2T_l) + (long long)i*512*512;
            gh4(attnh, attnl, woh, wol, tmp, nullptr, nullptr, nullptr, x,
                BS_, Dm_, Dm_, Dm_, Dm_, Dm_, 0);
            bn_stats_kernel<<<Dm_/32, dim3(32, 8)>>>(tmp, mu, rstd);
            bn_apply_kernel<<<BS_*Dm_/256, 256>>>(tmp, x, xh, xl, mu, rstd,
                                                  gamma + (long long)(i*3 + attn_pass)*Dm_,
                                                  beta  + (long long)(i*3 + attn_pass)*Dm_);
        }

        // ---- feed-forward
        gh8(xh, xl, w1T_h + (long long)i*Ff_*512, w1T_l + (long long)i*Ff_*512,
            nullptr, ffh, ffl, bb1, nullptr, BS_, Ff_, Dm_, Dm_, Dm_, Ff_, 1);
        gh4(ffh, ffl, w2T_h + (long long)i*512LL*Ff_, w2T_l + (long long)i*512LL*Ff_,
            tmp, nullptr, nullptr, bb2, x, BS_, Dm_, Ff_, Ff_, Ff_, Dm_, 0);
        bn_stats_kernel<<<Dm_/32, dim3(32, 8)>>>(tmp, mu, rstd);
        bn_apply_kernel<<<BS_*Dm_/256, 256>>>(tmp, x, xh, xl, mu, rstd,
                                              gamma + (long long)(i*3 + 2)*Dm_,
                                              beta  + (long long)(i*3 + 2)*Dm_);
    }

    // ---- output projection + vocab softmax
    gh8(xh, xl, woutT_h, woutT_l, out, nullptr, nullptr, bout, nullptr,
        BS_, Vv_, Dm_, Dm_, Dm_, Vv_, 0);
    softmax_kernel<<<BS_, 1024, 2*1024*4>>>(out, Vv_, 0);

    (void)in_sizes; (void)n_in; (void)out_size;
}

// round 9
// speedup vs baseline: 1.2907x; 1.1267x over previous
#include <cuda_runtime.h>
#include <cuda_fp16.h>
#include <math.h>
#include <stdint.h>

// ---------------------------------------------------------------------------
// Decoder — Round 9: 3-stage swizzled-smem pipeline in gemm_h (1 barrier/tile)
// ---------------------------------------------------------------------------

#define Bb_ 4
#define Ss_ 512
#define Dm_ 512
#define Hh_ 8
#define Dk_ 64
#define Ff_ 2048
#define Vv_ 37000
#define VvP_ 37120
#define Nx_ 6
#define BS_ 2048

// ------------------------- scratch (static device globals) -----------------
__device__ __align__(16) float g_x    [BS_*Dm_];
__device__ __align__(16) float g_tmp  [BS_*Dm_];
__device__ __align__(16) float g_qkv  [BS_*3*Dm_];     // fp32 (V read by AV gemm)
__device__ __align__(16) float g_sc   [Bb_*Hh_*Ss_*Ss_];
__device__ float g_mu   [Dm_];
__device__ float g_rstd [Dm_];

// hi/lo half activations
__device__ __align__(16) __half g_xh   [BS_*Dm_];
__device__ __align__(16) __half g_xl   [BS_*Dm_];
__device__ __align__(16) __half g_qkvh [BS_*3*Dm_];
__device__ __align__(16) __half g_qkvl [BS_*3*Dm_];
__device__ __align__(16) __half g_attnh[BS_*Dm_];
__device__ __align__(16) __half g_attnl[BS_*Dm_];
__device__ __align__(16) __half g_ffh  [BS_*Ff_];
__device__ __align__(16) __half g_ffl  [BS_*Ff_];
__device__ __align__(16) __half g_ench [BS_*Dm_];
__device__ __align__(16) __half g_encl [BS_*Dm_];

// hi/lo half weights, [N, K] K-major
__device__ __align__(16) __half g_wtT_h [12L*1536*512];
__device__ __align__(16) __half g_wtT_l [12L*1536*512];
__device__ __align__(16) __half g_w1T_h [6L*2048*512];
__device__ __align__(16) __half g_w1T_l [6L*2048*512];
__device__ __align__(16) __half g_w2T_h [6L*512*2048];
__device__ __align__(16) __half g_w2T_l [6L*512*2048];
__device__ __align__(16) __half g_wo1T_h[6L*512*512];
__device__ __align__(16) __half g_wo1T_l[6L*512*512];
__device__ __align__(16) __half g_wo2T_h[6L*512*512];
__device__ __align__(16) __half g_wo2T_l[6L*512*512];
__device__ __align__(16) __half g_woutT_h[(long long)VvP_*512];
__device__ __align__(16) __half g_woutT_l[(long long)VvP_*512];

// ------------------------------- helpers -----------------------------------
__device__ __forceinline__ void split2(float2 x, uint32_t& hi, uint32_t& lo) {
    __half2 h = __float22half2_rn(x);
    float2 hf = __half22float2(h);
    __half2 l = __float22half2_rn(make_float2(x.x - hf.x, x.y - hf.y));
    hi = *reinterpret_cast<uint32_t*>(&h);
    lo = *reinterpret_cast<uint32_t*>(&l);
}
__device__ __forceinline__ void cpasync16(uint32_t dst, const void* src) {
    asm volatile("cp.async.cg.shared.global [%0], [%1], 16;"
                 :: "r"(dst), "l"(src));
}
__device__ __forceinline__ void cpcommit() { asm volatile("cp.async.commit_group;"); }
template <int NN> __device__ __forceinline__ void cpwait() {
    asm volatile("cp.async.wait_group %0;" :: "n"(NN));
}
__device__ __forceinline__ void mma16(float* d, const uint32_t* a, const uint32_t* b) {
    asm volatile(
        "mma.sync.aligned.m16n8k16.row.col.f32.f16.f16.f32 "
        "{%0,%1,%2,%3}, {%4,%5,%6,%7}, {%8,%9}, {%0,%1,%2,%3};"
        : "+f"(d[0]), "+f"(d[1]), "+f"(d[2]), "+f"(d[3])
        : "r"(a[0]), "r"(a[1]), "r"(a[2]), "r"(a[3]), "r"(b[0]), "r"(b[1]));
}
__device__ __forceinline__ void ldsm4(uint32_t* r, uint32_t addr) {
    asm volatile("ldmatrix.sync.aligned.m8n8.x4.shared.b16 {%0,%1,%2,%3}, [%4];"
                 : "=r"(r[0]), "=r"(r[1]), "=r"(r[2]), "=r"(r[3]) : "r"(addr));
}

// 64B rows; chunk (16B) swizzle keeps ldmatrix 8-row phases conflict-free.
#define SWZ(row, cb) ((uint32_t)((cb) ^ ((((row) >> 1) & 3) << 4)))

// ------------------------ GEMM: pure-half operands --------------------------
// C[z] = alpha * A @ B^T (+bias)(+res)(relu). A: hi/lo half [M,K]; B: hi/lo
// half [N,K]. Tile 128 x BN x 32, 8 warps (4m x 2n), ldmatrix fragments,
// 3-pass hi/lo fp16 split => fp32 accuracy. 3-stage cp.async pipeline,
// swizzled 64B-row smem, one __syncthreads per k-tile.
// flags: bit0 relu, bit1 causal-skip.
#define AARR (128*64)                 // one A array: 8192 B

template <int NT>
__global__ __launch_bounds__(256) void gemm_h(
    const __half* __restrict__ Ah, const __half* __restrict__ Al,
    const __half* __restrict__ Bh, const __half* __restrict__ Bl,
    float* __restrict__ C, __half* __restrict__ Ch, __half* __restrict__ Cl,
    const float* __restrict__ bias, const float* __restrict__ res,
    int M, int N, int K, int lda, int ldb, int ldc,
    long long aS1, long long aS2, int aDiv,
    long long bS1, long long bS2, int bDiv,
    long long cS1, long long cS2, int cDiv,
    float alpha, int flags)
{
    constexpr int BN   = NT * 16;
    constexpr int BARR = BN * 64;
    constexpr int STG  = 2 * AARR + 2 * BARR;

    extern __shared__ char smh[];
    const int m0 = blockIdx.y * 128, n0 = blockIdx.x * BN;
    if ((flags & 2) && n0 >= m0 + 128) return;      // causal: fully-masked tile

    const int z = blockIdx.z;
    const long long aOff = (long long)(z / aDiv) * aS1 + (long long)(z % aDiv) * aS2;
    const long long bOff = (long long)(z / bDiv) * bS1 + (long long)(z % bDiv) * bS2;
    const long long cOff = (long long)(z / cDiv) * cS1 + (long long)(z % cDiv) * cS2;
    const __half* Ahb = Ah + aOff;
    const __half* Alb = Al + aOff;
    const __half* Bhb = Bh + bOff;
    const __half* Blb = Bl + bOff;

    const uint32_t sb = (uint32_t)__cvta_generic_to_shared(smh);
    const int tid = threadIdx.x;
    const int wid = tid >> 5, lane = tid & 31;
    const int wm = wid & 3, wn = wid >> 2;
    const int g = lane >> 2, t = lane & 3;

    const int aRow = lane & 15, aChk = lane >> 4;
    const int bRow = (lane & 7) + ((lane >> 4) << 3);
    const int bChk = (lane >> 3) & 1;

    // per-lane row bases + swizzle XORs (row-dependent only)
    uint32_t aBase[2], aXor[2];
#pragma unroll
    for (int mt = 0; mt < 2; mt++) {
        int r = wm * 32 + mt * 16 + aRow;
        aBase[mt] = (uint32_t)(r * 64);
        aXor[mt]  = (uint32_t)(((r >> 1) & 3) << 4);
    }
    uint32_t bBase[NT / 2], bXor[NT / 2];
#pragma unroll
    for (int p = 0; p < NT / 2; p++) {
        int r = wn * (NT * 8) + p * 16 + bRow;
        bBase[p] = (uint32_t)(r * 64);
        bXor[p]  = (uint32_t)(((r >> 1) & 3) << 4);
    }

    float acc[2][NT][4];
#pragma unroll
    for (int i = 0; i < 2; i++)
#pragma unroll
        for (int j = 0; j < NT; j++)
#pragma unroll
            for (int r = 0; r < 4; r++) acc[i][j][r] = 0.f;

    const int T = K >> 5;                 // 32-half k-tiles (always >= 2 here)

    auto stage = [&](int it, int buf) {
        const int k0 = it << 5;
        uint32_t dst = sb + buf * STG;
#pragma unroll
        for (int j = 0; j < 2; j++) {               // A: 512 16B chunks
            int idx = tid + (j << 8);
            int row = idx >> 2, c = idx & 3;
            long long asrc = (long long)(m0 + row) * lda + k0 + c * 8;
            uint32_t so = (uint32_t)(row * 64) + SWZ(row, c * 16);
            cpasync16(dst + 0 * AARR + so, Ahb + asrc);
            cpasync16(dst + 1 * AARR + so, Alb + asrc);
        }
#pragma unroll
        for (int j = 0; j < NT / 4; j++) {          // B: BN*4 chunks
            int idx = tid + (j << 8);
            int row = idx >> 2, c = idx & 3;
            long long bsrc = (long long)(n0 + row) * ldb + k0 + c * 8;
            uint32_t so = (uint32_t)(row * 64) + SWZ(row, c * 16);
            cpasync16(dst + 2 * AARR + so, Bhb + bsrc);
            cpasync16(dst + 2 * AARR + BARR + so, Blb + bsrc);
        }
    };

    stage(0, 0); cpcommit();
    stage(1, 1); cpcommit();

    for (int it = 0; it < T; ++it) {
        if (it + 1 < T) cpwait<1>(); else cpwait<0>();
        __syncthreads();

        const uint32_t base = sb + (uint32_t)(it % 3) * STG;
        const uint32_t aHb0 = base + 0 * AARR;
        const uint32_t aLb0 = base + 1 * AARR;
        const uint32_t bHb0 = base + 2 * AARR;
        const uint32_t bLb0 = base + 2 * AARR + BARR;

#pragma unroll
        for (int kk = 0; kk < 2; kk++) {            // two k16 steps
            const uint32_t cbA = (uint32_t)(aChk * 16 + kk * 32);
            const uint32_t cbB = (uint32_t)(bChk * 16 + kk * 32);
            uint32_t ah[2][4], al[2][4];
#pragma unroll
            for (int mt = 0; mt < 2; mt++) {
                uint32_t off = aBase[mt] + (cbA ^ aXor[mt]);
                ldsm4(ah[mt], aHb0 + off);
                ldsm4(al[mt], aLb0 + off);
            }
            uint32_t bh[NT / 2][4], bl[NT / 2][4];
#pragma unroll
            for (int p = 0; p < NT / 2; p++) {
                uint32_t off = bBase[p] + (cbB ^ bXor[p]);
                ldsm4(bh[p], bHb0 + off);
                ldsm4(bl[p], bLb0 + off);
            }
#pragma unroll
            for (int mt = 0; mt < 2; mt++)
#pragma unroll
                for (int p = 0; p < NT / 2; p++) {
                    mma16(acc[mt][2*p],   ah[mt], &bh[p][0]);
                    mma16(acc[mt][2*p],   al[mt], &bh[p][0]);
                    mma16(acc[mt][2*p],   ah[mt], &bl[p][0]);
                    mma16(acc[mt][2*p+1], ah[mt], &bh[p][2]);
                    mma16(acc[mt][2*p+1], al[mt], &bh[p][2]);
                    mma16(acc[mt][2*p+1], ah[mt], &bl[p][2]);
                }
        }

        if (it + 2 < T) { stage(it + 2, (it + 2) % 3); cpcommit(); }
    }

    // ------------------------------ epilogue --------------------------------
    const bool relu = flags & 1;
#pragma unroll
    for (int mt = 0; mt < 2; mt++) {
#pragma unroll
        for (int hrow = 0; hrow < 2; hrow++) {
            int m = m0 + wm * 32 + mt * 16 + g + hrow * 8;
            long long rowo = cOff + (long long)m * ldc;
#pragma unroll
            for (int nt = 0; nt < NT; nt++) {
                int n = n0 + wn * (NT * 8) + nt * 8 + 2 * t;
                if (n < N) {
                    float v0 = acc[mt][nt][hrow * 2 + 0] * alpha;
                    float v1 = acc[mt][nt][hrow * 2 + 1] * alpha;
                    if (bias) { v0 += bias[n]; v1 += bias[n + 1]; }
                    if (res) {
                        const float* rp = res + rowo;
                        v0 += rp[n]; v1 += rp[n + 1];
                    }
                    if (relu) { v0 = fmaxf(v0, 0.f); v1 = fmaxf(v1, 0.f); }
                    if (C) {
                        float2 vv; vv.x = v0; vv.y = v1;
                        *(float2*)(C + rowo + n) = vv;
                    }
                    if (Ch) {
                        uint32_t hi, lo;
                        split2(make_float2(v0, v1), hi, lo);
                        *(uint32_t*)(Ch + rowo + n) = hi;
                        *(uint32_t*)(Cl + rowo + n) = lo;
                    }
                }
            }
        }
    }
}

#define GH_SMEM8 (3 * (2 * AARR + 2 * 128 * 64))   // 98304
#define GH_SMEM4 (3 * (2 * AARR + 2 * 64 * 64))    // 73728

// -------------------- AV GEMM (fp32 A=probs, fp32 B=[k][n]) -----------------
#define ASTR 40
#define BSTRN 132
#define ASZ (128*ASTR)
#define BSZn (32*BSTRN)
#define GEMM_SMEM_N ((2*ASZ + 2*BSZn)*4)

__global__ __launch_bounds__(256) void gemm_av(
    const float* __restrict__ A, const float* __restrict__ B,
    __half* __restrict__ Ch, __half* __restrict__ Cl,
    int M, int N, int K, int lda, int ldb, int ldc,
    long long aS1, long long aS2, int aDiv,
    long long bS1, long long bS2, int bDiv,
    long long cS1, long long cS2, int cDiv)
{
    extern __shared__ float sm[];
    const int z = blockIdx.z;
    const float* Ab  = A + (long long)(z / aDiv) * aS1 + (long long)(z % aDiv) * aS2;
    const float* Bbp = B + (long long)(z / bDiv) * bS1 + (long long)(z % bDiv) * bS2;
    const long long cOff = (long long)(z / cDiv) * cS1 + (long long)(z % cDiv) * cS2;

    float* As = sm;
    float* Bs = sm + 2 * ASZ;

    const int tid  = threadIdx.x;
    const int wid  = tid >> 5, lane = tid & 31;
    const int wm   = wid & 3,  wn   = wid >> 2;
    const int g    = lane >> 2, t   = lane & 3;
    const int m0   = blockIdx.y * 128, n0 = blockIdx.x * 128;

    const uint32_t asA = (uint32_t)__cvta_generic_to_shared(As);
    const uint32_t asB = (uint32_t)__cvta_generic_to_shared(Bs);

    float acc[2][8][4];
#pragma unroll
    for (int i = 0; i < 2; i++)
#pragma unroll
        for (int j = 0; j < 8; j++)
#pragma unroll
            for (int r = 0; r < 4; r++) acc[i][j][r] = 0.f;

    const int nIter = K >> 5;

    auto doCopy = [&](int it, int buf) {
        const int k0 = it << 5;
#pragma unroll
        for (int j = 0; j < 4; j++) {
            int i   = tid + (j << 8);
            int row = i >> 3, kq = (i & 7) << 2;
            const float* src = Ab + (long long)(m0 + row) * lda + (k0 + kq);
            cpasync16(asA + (uint32_t)((buf * ASZ + row * ASTR + kq) << 2), src);
        }
#pragma unroll
        for (int j = 0; j < 4; j++) {
            int i  = tid + (j << 8);
            int kr = i >> 5, nc = (i & 31) << 2;
            int gn = n0 + nc;
            if (gn < N) {
                const float* src = Bbp + (long long)(k0 + kr) * ldb + gn;
                cpasync16(asB + (uint32_t)((buf * BSZn + kr * BSTRN + nc) << 2), src);
            }
        }
    };

    doCopy(0, 0); cpcommit();

    for (int it = 0; it < nIter; ++it) {
        const int cur = it & 1;
        if (it + 1 < nIter) { doCopy(it + 1, cur ^ 1); cpcommit(); cpwait<1>(); }
        else                { cpwait<0>(); }
        __syncthreads();

        const float* pa = As + cur * ASZ;
        const float* pb = Bs + cur * BSZn;

#pragma unroll
        for (int kk = 0; kk < 32; kk += 16) {
            uint32_t ah[2][4], al[2][4];
#pragma unroll
            for (int mt = 0; mt < 2; mt++) {
                int r0 = (wm * 32 + mt * 16 + g) * ASTR + kk + 2 * t;
                int r1 = r0 + 8 * ASTR;
                split2(*(const float2*)&pa[r0],     ah[mt][0], al[mt][0]);
                split2(*(const float2*)&pa[r1],     ah[mt][1], al[mt][1]);
                split2(*(const float2*)&pa[r0 + 8], ah[mt][2], al[mt][2]);
                split2(*(const float2*)&pa[r1 + 8], ah[mt][3], al[mt][3]);
            }
            uint32_t bh[8][2], bl[8][2];
#pragma unroll
            for (int nt = 0; nt < 8; nt++) {
                int nc = wn * 64 + nt * 8 + g;
                const float* base = pb + (long long)(kk + 2 * t) * BSTRN + nc;
                float2 y0 = make_float2(base[0], base[BSTRN]);
                float2 y1 = make_float2(base[8 * BSTRN], base[9 * BSTRN]);
                split2(y0, bh[nt][0], bl[nt][0]);
                split2(y1, bh[nt][1], bl[nt][1]);
            }
#pragma unroll
            for (int mt = 0; mt < 2; mt++)
#pragma unroll
                for (int nt = 0; nt < 8; nt++) {
                    mma16(acc[mt][nt], ah[mt], bh[nt]);
                    mma16(acc[mt][nt], al[mt], bh[nt]);
                    mma16(acc[mt][nt], ah[mt], bl[nt]);
                }
        }
        __syncthreads();
    }

#pragma unroll
    for (int mt = 0; mt < 2; mt++) {
#pragma unroll
        for (int hrow = 0; hrow < 2; hrow++) {
            int m = m0 + wm * 32 + mt * 16 + g + hrow * 8;
            long long rowo = cOff + (long long)m * ldc;
#pragma unroll
            for (int nt = 0; nt < 8; nt++) {
                int n = n0 + wn * 64 + nt * 8 + 2 * t;
                if (n < N) {
                    uint32_t hi, lo;
                    split2(make_float2(acc[mt][nt][hrow * 2], acc[mt][nt][hrow * 2 + 1]), hi, lo);
                    *(uint32_t*)(Ch + rowo + n) = hi;
                    *(uint32_t*)(Cl + rowo + n) = lo;
                }
            }
        }
    }
}

// --------------------------- conversion kernels -----------------------------
__global__ void convw_kernel(const float* __restrict__ W,
                             __half* __restrict__ hi, __half* __restrict__ lo,
                             int K, int N, int Npad, long long inS, long long outS)
{
    __shared__ float tile[32][65];
    int z = blockIdx.z;
    const float* Wz = W + (long long)z * inS;
    int k0 = blockIdx.y * 32, n0 = blockIdx.x * 64;
    int tid = threadIdx.x;

#pragma unroll
    for (int j = 0; j < 2; j++) {
        int idx = tid + (j << 8);
        int k = idx >> 4, nq = (idx & 15) << 2;
        int n = n0 + nq;
        float4 v = make_float4(0.f, 0.f, 0.f, 0.f);
        const float* p = Wz + (long long)(k0 + k) * N;
        if (n + 3 < N) v = *(const float4*)(p + n);
        else {
            if (n + 0 < N) v.x = p[n + 0];
            if (n + 1 < N) v.y = p[n + 1];
            if (n + 2 < N) v.z = p[n + 2];
            if (n + 3 < N) v.w = p[n + 3];
        }
        tile[k][nq + 0] = v.x; tile[k][nq + 1] = v.y;
        tile[k][nq + 2] = v.z; tile[k][nq + 3] = v.w;
    }
    __syncthreads();

#pragma unroll
    for (int j = 0; j < 4; j++) {
        int idx = tid + (j << 8);
        int n = idx >> 4, tq = (idx & 15) << 1;
        int gn = n0 + n;
        if (gn < Npad) {
            float v0 = tile[tq][n], v1 = tile[tq + 1][n];
            __half2 h = __floats2half2_rn(v0, v1);
            float2 hf = __half22float2(h);
            __half2 l = __floats2half2_rn(v0 - hf.x, v1 - hf.y);
            long long o = (long long)z * outS + (long long)gn * K + k0 + tq;
            *(__half2*)(hi + o) = h;
            *(__half2*)(lo + o) = l;
        }
    }
}

__global__ void convqkv_kernel(const float* __restrict__ Wq, const float* __restrict__ Wk,
                               const float* __restrict__ Wv,
                               __half* __restrict__ hi, __half* __restrict__ lo)
{
    __shared__ float tile[32][65];
    int kt = blockIdx.x, sh = blockIdx.y;
    int sel = sh >> 3, h = sh & 7;
    const float* W = (sel == 0) ? Wq : (sel == 1) ? Wk : Wv;
    const float* src = W + ((long long)h * 512 + kt * 32) * 64;
    int tid = threadIdx.x;

#pragma unroll
    for (int j = 0; j < 2; j++) {
        int idx = tid + (j << 8);
        int k = idx >> 4, eq = (idx & 15) << 2;
        float4 v = *(const float4*)(src + k * 64 + eq);
        tile[k][eq + 0] = v.x; tile[k][eq + 1] = v.y;
        tile[k][eq + 2] = v.z; tile[k][eq + 3] = v.w;
    }
    __syncthreads();

#pragma unroll
    for (int j = 0; j < 4; j++) {
        int idx = tid + (j << 8);
        int e = idx >> 4, tq = (idx & 15) << 1;
        int n = sel * 512 + h * 64 + e;
        float v0 = tile[tq][e], v1 = tile[tq + 1][e];
        __half2 hh = __floats2half2_rn(v0, v1);
        float2 hf = __half22float2(hh);
        __half2 ll = __floats2half2_rn(v0 - hf.x, v1 - hf.y);
        long long o = (long long)n * 512 + kt * 32 + tq;
        *(__half2*)(hi + o) = hh;
        *(__half2*)(lo + o) = ll;
    }
}

__global__ void conva_kernel(const float* __restrict__ src,
                             __half* __restrict__ hi, __half* __restrict__ lo, int n) {
    int i = blockIdx.x * 256 + threadIdx.x;
    if (i < n) {
        float v = src[i];
        __half h = __float2half_rn(v);
        hi[i] = h;
        lo[i] = __float2half_rn(v - __half2float(h));
    }
}

// --------------------------- elementwise kernels ---------------------------
__global__ void embed_kernel(const int* __restrict__ tok, const float* __restrict__ emb,
                             float* __restrict__ x,
                             __half* __restrict__ xh, __half* __restrict__ xl) {
    int idx = blockIdx.x * 256 + threadIdx.x;
    int t = tok[idx >> 9];
    float v = emb[(long long)t * Dm_ + (idx & 511)] * 8.0f;
    x[idx] = v;
    __half h = __float2half_rn(v);
    xh[idx] = h;
    xl[idx] = __float2half_rn(v - __half2float(h));
}

__global__ void bn_stats_kernel(const float* __restrict__ x,
                                float* __restrict__ mu, float* __restrict__ rstd) {
    int d = blockIdx.x * 32 + threadIdx.x;
    float s = 0.f, s2 = 0.f;
    for (int i = threadIdx.y; i < BS_; i += 8) {
        float v = x[(long long)i * Dm_ + d];
        s += v; s2 += v * v;
    }
    __shared__ float sh[8][33], sh2[8][33];
    sh[threadIdx.y][threadIdx.x] = s;
    sh2[threadIdx.y][threadIdx.x] = s2;
    __syncthreads();
    if (threadIdx.y == 0) {
#pragma unroll
        for (int r = 1; r < 8; r++) { s += sh[r][threadIdx.x]; s2 += sh2[r][threadIdx.x]; }
        float m = s * (1.f / BS_);
        float var = s2 * (1.f / BS_) - m * m;
        mu[d] = m;
        rstd[d] = rsqrtf(var + 1e-5f);
    }
}

__global__ void bn_apply_kernel(const float* __restrict__ xin, float* __restrict__ xout,
                                __half* __restrict__ xh, __half* __restrict__ xl,
                                const float* __restrict__ mu, const float* __restrict__ rstd,
                                const float* __restrict__ gamma, const float* __restrict__ beta) {
    int idx = blockIdx.x * 256 + threadIdx.x;
    int d = idx & 511;
    float v = (xin[idx] - mu[d]) * rstd[d] * gamma[d] + beta[d];
    xout[idx] = v;
    __half h = __float2half_rn(v);
    xh[idx] = h;
    xl[idx] = __float2half_rn(v - __half2float(h));
}

// Online row softmax. Causal masks t > (row & 511).
__global__ void softmax_kernel(float* __restrict__ p, int T, int causal) {
    extern __shared__ float red[];
    float* mred = red;
    float* sred = red + blockDim.x;
    long long row = blockIdx.x;
    float* x = p + row * (long long)T;
    int s = (int)(row & 511);
    int nt = blockDim.x;
    int tmax = causal ? s : (T - 1);

    float m = -1e30f, sum = 0.f;
    for (int t = threadIdx.x; t <= tmax; t += nt) {
        float v = x[t];
        if (v > m) { sum = sum * __expf(m - v) + 1.f; m = v; }
        else       { sum += __expf(v - m); }
    }
    mred[threadIdx.x] = m; sred[threadIdx.x] = sum;
    __syncthreads();
    for (int o = nt >> 1; o > 0; o >>= 1) {
        if ((int)threadIdx.x < o) {
            float m2 = mred[threadIdx.x + o], s2 = sred[threadIdx.x + o];
            float m1 = mred[threadIdx.x],     s1 = sred[threadIdx.x];
            float M = fmaxf(m1, m2);
            sred[threadIdx.x] = s1 * __expf(m1 - M) + s2 * __expf(m2 - M);
            mred[threadIdx.x] = M;
        }
        __syncthreads();
    }
    float M = mred[0];
    float inv = 1.f / sred[0];
    for (int t = threadIdx.x; t < T; t += nt) {
        float v = (causal && t > s) ? 0.f : __expf(x[t] - M) * inv;
        x[t] = v;
    }
}

// ------------------------------- host side ---------------------------------
static inline int cdiv(int a, int b) { return (a + b - 1) / b; }

static void gh8(const __half* Ah, const __half* Al, const __half* Bh, const __half* Bl,
                float* C, __half* Ch, __half* Cl,
                const float* bias, const float* res,
                int M, int N, int K, int lda, int ldb, int ldc, int flags)
{
    dim3 g(cdiv(N, 128), M / 128, 1);
    gemm_h<8><<<g, 256, GH_SMEM8>>>(Ah, Al, Bh, Bl, C, Ch, Cl, bias, res,
                                    M, N, K, lda, ldb, ldc,
                                    0, 0, 1, 0, 0, 1, 0, 0, 1, 1.f, flags);
}
static void gh4(const __half* Ah, const __half* Al, const __half* Bh, const __half* Bl,
                float* C, __half* Ch, __half* Cl,
                const float* bias, const float* res,
                int M, int N, int K, int lda, int ldb, int ldc, int flags)
{
    dim3 g(cdiv(N, 64), M / 128, 1);
    gemm_h<4><<<g, 256, GH_SMEM4>>>(Ah, Al, Bh, Bl, C, Ch, Cl, bias, res,
                                    M, N, K, lda, ldb, ldc,
                                    0, 0, 1, 0, 0, 1, 0, 0, 1, 1.f, flags);
}

extern "C" void kernel_launch(void* const* d_in, const int* in_sizes, int n_in,
                              void* d_out, int out_size)
{
    const int*   tok   = (const int*)  d_in[0];
    const float* enc   = (const float*)d_in[1];
    const float* emb   = (const float*)d_in[2];
    const float* Wq1   = (const float*)d_in[3];
    const float* Wk1   = (const float*)d_in[4];
    const float* Wv1   = (const float*)d_in[5];
    const float* Wo1   = (const float*)d_in[6];
    const float* Wq2   = (const float*)d_in[7];
    const float* Wk2   = (const float*)d_in[8];
    const float* Wv2   = (const float*)d_in[9];
    const float* Wo2   = (const float*)d_in[10];
    const float* gamma = (const float*)d_in[11];
    const float* beta  = (const float*)d_in[12];
    const float* W1    = (const float*)d_in[13];
    const float* b1    = (const float*)d_in[14];
    const float* W2    = (const float*)d_in[15];
    const float* b2    = (const float*)d_in[16];
    const float* Wout  = (const float*)d_in[17];
    const float* bout  = (const float*)d_in[18];
    float* out = (float*)d_out;

    cudaFuncSetAttribute(gemm_h<8>, cudaFuncAttributeMaxDynamicSharedMemorySize, GH_SMEM8);
    cudaFuncSetAttribute(gemm_h<4>, cudaFuncAttributeMaxDynamicSharedMemorySize, GH_SMEM4);
    cudaFuncSetAttribute(gemm_av,   cudaFuncAttributeMaxDynamicSharedMemorySize, GEMM_SMEM_N);

    float *x, *tmp, *qkv, *sc, *mu, *rstd;
    cudaGetSymbolAddress((void**)&x,    g_x);
    cudaGetSymbolAddress((void**)&tmp,  g_tmp);
    cudaGetSymbolAddress((void**)&qkv,  g_qkv);
    cudaGetSymbolAddress((void**)&sc,   g_sc);
    cudaGetSymbolAddress((void**)&mu,   g_mu);
    cudaGetSymbolAddress((void**)&rstd, g_rstd);

    __half *xh, *xl, *qkvh, *qkvl, *attnh, *attnl, *ffh, *ffl, *ench, *encl;
    cudaGetSymbolAddress((void**)&xh,    g_xh);
    cudaGetSymbolAddress((void**)&xl,    g_xl);
    cudaGetSymbolAddress((void**)&qkvh,  g_qkvh);
    cudaGetSymbolAddress((void**)&qkvl,  g_qkvl);
    cudaGetSymbolAddress((void**)&attnh, g_attnh);
    cudaGetSymbolAddress((void**)&attnl, g_attnl);
    cudaGetSymbolAddress((void**)&ffh,   g_ffh);
    cudaGetSymbolAddress((void**)&ffl,   g_ffl);
    cudaGetSymbolAddress((void**)&ench,  g_ench);
    cudaGetSymbolAddress((void**)&encl,  g_encl);

    __half *wtT_h, *wtT_l, *w1T_h, *w1T_l, *w2T_h, *w2T_l;
    __half *wo1T_h, *wo1T_l, *wo2T_h, *wo2T_l, *woutT_h, *woutT_l;
    cudaGetSymbolAddress((void**)&wtT_h,  g_wtT_h);
    cudaGetSymbolAddress((void**)&wtT_l,  g_wtT_l);
    cudaGetSymbolAddress((void**)&w1T_h,  g_w1T_h);
    cudaGetSymbolAddress((void**)&w1T_l,  g_w1T_l);
    cudaGetSymbolAddress((void**)&w2T_h,  g_w2T_h);
    cudaGetSymbolAddress((void**)&w2T_l,  g_w2T_l);
    cudaGetSymbolAddress((void**)&wo1T_h, g_wo1T_h);
    cudaGetSymbolAddress((void**)&wo1T_l, g_wo1T_l);
    cudaGetSymbolAddress((void**)&wo2T_h, g_wo2T_h);
    cudaGetSymbolAddress((void**)&wo2T_l, g_wo2T_l);
    cudaGetSymbolAddress((void**)&woutT_h, g_woutT_h);
    cudaGetSymbolAddress((void**)&woutT_l, g_woutT_l);

    const long long HW  = (long long)Dm_ * Dk_;
    const long long QBh = (long long)Ss_ * 1536;
    const long long SCZ = (long long)Ss_ * Ss_;
    const float     isq = 0.125f;

    // ---- weight conversion (fused + vectorized) ----
    convw_kernel<<<dim3(Ff_/64, Dm_/32, Nx_), 256>>>(W1, w1T_h, w1T_l, Dm_, Ff_, Ff_,
                                                     (long long)Dm_*Ff_, (long long)Ff_*Dm_);
    convw_kernel<<<dim3(Dm_/64, Ff_/32, Nx_), 256>>>(W2, w2T_h, w2T_l, Ff_, Dm_, Dm_,
                                                     (long long)Ff_*Dm_, (long long)Dm_*Ff_);
    convw_kernel<<<dim3(Dm_/64, Dm_/32, Nx_), 256>>>(Wo1, wo1T_h, wo1T_l, Dm_, Dm_, Dm_,
                                                     (long long)Dm_*Dm_, (long long)Dm_*Dm_);
    convw_kernel<<<dim3(Dm_/64, Dm_/32, Nx_), 256>>>(Wo2, wo2T_h, wo2T_l, Dm_, Dm_, Dm_,
                                                     (long long)Dm_*Dm_, (long long)Dm_*Dm_);
    convw_kernel<<<dim3(VvP_/64, Dm_/32, 1), 256>>>(Wout, woutT_h, woutT_l, Dm_, Vv_, VvP_, 0, 0);
    for (int s = 0; s < 12; s++) {
        int i = s >> 1, pass = s & 1;
        const float* wq = pass ? Wq2 : Wq1;
        const float* wk = pass ? Wk2 : Wk1;
        const float* wv = pass ? Wv2 : Wv1;
        convqkv_kernel<<<dim3(16, 24), 256>>>(wq + (long long)i*Hh_*HW,
                                              wk + (long long)i*Hh_*HW,
                                              wv + (long long)i*Hh_*HW,
                                              wtT_h + (long long)s*1536*512,
                                              wtT_l + (long long)s*1536*512);
    }
    conva_kernel<<<cdiv(BS_*Dm_, 256), 256>>>(enc, ench, encl, BS_*Dm_);

    embed_kernel<<<BS_ * Dm_ / 256, 256>>>(tok, emb, x, xh, xl);

    for (int i = 0; i < Nx_; i++) {
        const float* bb1 = b1 + (long long)i * Ff_;
        const float* bb2 = b2 + (long long)i * Dm_;

        for (int attn_pass = 0; attn_pass < 2; attn_pass++) {
            const int self = (attn_pass == 0);
            const int s = i * 2 + attn_pass;
            const __half* wth = wtT_h + (long long)s * 1536 * 512;
            const __half* wtl = wtT_l + (long long)s * 1536 * 512;

            if (self) {
                gh8(xh, xl, wth, wtl, qkv, qkvh, qkvl, nullptr, nullptr,
                    BS_, 1536, Dm_, Dm_, Dm_, 1536, 0);
            } else {
                gh4(xh, xl, wth, wtl, qkv, qkvh, qkvl, nullptr, nullptr,
                    BS_, 512, Dm_, Dm_, Dm_, 1536, 0);
                dim3 g(8, 16, 1);
                gemm_h<8><<<g, 256, GH_SMEM8>>>(ench, encl,
                                                wth + 512LL*512, wtl + 512LL*512,
                                                qkv + 512, qkvh + 512, qkvl + 512,
                                                nullptr, nullptr,
                                                BS_, 1024, Dm_, Dm_, Dm_, 1536,
                                                0, 0, 1, 0, 0, 1, 0, 0, 1, 1.f, 0);
            }
            // scores[z=b*8+h] = Q @ K^T * isq  (causal skip for self)
            {
                dim3 g(4, 4, Bb_ * Hh_);
                gemm_h<8><<<g, 256, GH_SMEM8>>>(qkvh, qkvl, qkvh + 512, qkvl + 512,
                                                sc, nullptr, nullptr, nullptr, nullptr,
                                                Ss_, Ss_, Dk_, 1536, 1536, Ss_,
                                                QBh, 64, Hh_,  QBh, 64, Hh_,  SCZ, 0, 1,
                                                isq, self ? 2 : 0);
            }
            softmax_kernel<<<Bb_*Hh_*Ss_, 256, 2*256*4>>>(sc, Ss_, self ? 1 : 0);
            // attn[b,s,h*64+e] = probs @ V
            {
                dim3 g(1, 4, Bb_ * Hh_);
                gemm_av<<<g, 256, GEMM_SMEM_N>>>(sc, qkv + 1024, attnh, attnl,
                                                 Ss_, Dk_, Ss_, Ss_, 1536, Dm_,
                                                 SCZ, 0, 1,  QBh, 64, Hh_,
                                                 (long long)Ss_*Dm_, Dk_, Hh_);
            }
            // tmp = attn @ Wo + x
            const __half* woh = (self ? wo1T_h : wo2T_h) + (long long)i*512*512;
            const __half* wol = (self ? wo1T_l : wo2T_l) + (long long)i*512*512;
            gh4(attnh, attnl, woh, wol, tmp, nullptr, nullptr, nullptr, x,
                BS_, Dm_, Dm_, Dm_, Dm_, Dm_, 0);
            bn_stats_kernel<<<Dm_/32, dim3(32, 8)>>>(tmp, mu, rstd);
            bn_apply_kernel<<<BS_*Dm_/256, 256>>>(tmp, x, xh, xl, mu, rstd,
                                                  gamma + (long long)(i*3 + attn_pass)*Dm_,
                                                  beta  + (long long)(i*3 + attn_pass)*Dm_);
        }

        // ---- feed-forward
        gh8(xh, xl, w1T_h + (long long)i*Ff_*512, w1T_l + (long long)i*Ff_*512,
            nullptr, ffh, ffl, bb1, nullptr, BS_, Ff_, Dm_, Dm_, Dm_, Ff_, 1);
        gh4(ffh, ffl, w2T_h + (long long)i*512LL*Ff_, w2T_l + (long long)i*512LL*Ff_,
            tmp, nullptr, nullptr, bb2, x, BS_, Dm_, Ff_, Ff_, Ff_, Dm_, 0);
        bn_stats_kernel<<<Dm_/32, dim3(32, 8)>>>(tmp, mu, rstd);
        bn_apply_kernel<<<BS_*Dm_/256, 256>>>(tmp, x, xh, xl, mu, rstd,
                                              gamma + (long long)(i*3 + 2)*Dm_,
                                              beta  + (long long)(i*3 + 2)*Dm_);
    }

    // ---- output projection + vocab softmax
    gh8(xh, xl, woutT_h, woutT_l, out, nullptr, nullptr, bout, nullptr,
        BS_, Vv_, Dm_, Dm_, Dm_, Vv_, 0);
    softmax_kernel<<<BS_, 1024, 2*1024*4>>>(out, Vv_, 0);

    (void)in_sizes; (void)n_in; (void)out_size;
}

// round 11
// speedup vs baseline: 1.3783x; 1.0679x over previous
#include <cuda_runtime.h>
#include <cuda_fp16.h>
#include <math.h>
#include <stdint.h>

// ---------------------------------------------------------------------------
// Decoder — Round 11: R10 fixes + launch-bounded vocab softmax
// ---------------------------------------------------------------------------

#define Bb_ 4
#define Ss_ 512
#define Dm_ 512
#define Hh_ 8
#define Dk_ 64
#define Ff_ 2048
#define Vv_ 37000
#define VvP_ 37120
#define Nx_ 6
#define BS_ 2048

// ------------------------- scratch (static device globals) -----------------
__device__ __align__(16) float g_x    [BS_*Dm_];
__device__ __align__(16) float g_tmp  [BS_*Dm_];
__device__ __align__(16) float g_qkv  [BS_*3*Dm_];     // fp32 (V read by AV gemm)
__device__ __align__(16) float g_sc   [Bb_*Hh_*Ss_*Ss_];
__device__ float g_mu   [Dm_];
__device__ float g_rstd [Dm_];

// hi/lo half activations
__device__ __align__(16) __half g_xh   [BS_*Dm_];
__device__ __align__(16) __half g_xl   [BS_*Dm_];
__device__ __align__(16) __half g_qkvh [BS_*3*Dm_];
__device__ __align__(16) __half g_qkvl [BS_*3*Dm_];
__device__ __align__(16) __half g_attnh[BS_*Dm_];
__device__ __align__(16) __half g_attnl[BS_*Dm_];
__device__ __align__(16) __half g_ffh  [BS_*Ff_];
__device__ __align__(16) __half g_ffl  [BS_*Ff_];
__device__ __align__(16) __half g_ench [BS_*Dm_];
__device__ __align__(16) __half g_encl [BS_*Dm_];

// hi/lo half weights, [N, K] K-major
__device__ __align__(16) __half g_wtT_h [12L*1536*512];
__device__ __align__(16) __half g_wtT_l [12L*1536*512];
__device__ __align__(16) __half g_w1T_h [6L*2048*512];
__device__ __align__(16) __half g_w1T_l [6L*2048*512];
__device__ __align__(16) __half g_w2T_h [6L*512*2048];
__device__ __align__(16) __half g_w2T_l [6L*512*2048];
__device__ __align__(16) __half g_wo1T_h[6L*512*512];
__device__ __align__(16) __half g_wo1T_l[6L*512*512];
__device__ __align__(16) __half g_wo2T_h[6L*512*512];
__device__ __align__(16) __half g_wo2T_l[6L*512*512];
__device__ __align__(16) __half g_woutT_h[(long long)VvP_*512];
__device__ __align__(16) __half g_woutT_l[(long long)VvP_*512];

// ------------------------------- helpers -----------------------------------
__device__ __forceinline__ void split2(float2 x, uint32_t& hi, uint32_t& lo) {
    __half2 h = __float22half2_rn(x);
    float2 hf = __half22float2(h);
    __half2 l = __float22half2_rn(make_float2(x.x - hf.x, x.y - hf.y));
    hi = *reinterpret_cast<uint32_t*>(&h);
    lo = *reinterpret_cast<uint32_t*>(&l);
}
__device__ __forceinline__ void cpasync16(uint32_t dst, const void* src) {
    asm volatile("cp.async.cg.shared.global [%0], [%1], 16;"
                 :: "r"(dst), "l"(src));
}
__device__ __forceinline__ void cpcommit() { asm volatile("cp.async.commit_group;"); }
template <int NN> __device__ __forceinline__ void cpwait() {
    asm volatile("cp.async.wait_group %0;" :: "n"(NN));
}
__device__ __forceinline__ void mma16(float* d, const uint32_t* a, const uint32_t* b) {
    asm volatile(
        "mma.sync.aligned.m16n8k16.row.col.f32.f16.f16.f32 "
        "{%0,%1,%2,%3}, {%4,%5,%6,%7}, {%8,%9}, {%0,%1,%2,%3};"
        : "+f"(d[0]), "+f"(d[1]), "+f"(d[2]), "+f"(d[3])
        : "r"(a[0]), "r"(a[1]), "r"(a[2]), "r"(a[3]), "r"(b[0]), "r"(b[1]));
}
__device__ __forceinline__ void ldsm4(uint32_t* r, uint32_t addr) {
    asm volatile("ldmatrix.sync.aligned.m8n8.x4.shared.b16 {%0,%1,%2,%3}, [%4];"
                 : "=r"(r[0]), "=r"(r[1]), "=r"(r[2]), "=r"(r[3]) : "r"(addr));
}

// 64B rows; chunk (16B) swizzle keeps ldmatrix 8-row phases conflict-free.
#define SWZ(row, cb) ((uint32_t)((cb) ^ ((((row) >> 1) & 3) << 4)))

// ------------------------ GEMM: pure-half operands --------------------------
// (unchanged from R9) 3-stage cp.async pipeline, swizzled 64B-row smem.
#define AARR (128*64)                 // one A array: 8192 B

template <int NT>
__global__ __launch_bounds__(256) void gemm_h(
    const __half* __restrict__ Ah, const __half* __restrict__ Al,
    const __half* __restrict__ Bh, const __half* __restrict__ Bl,
    float* __restrict__ C, __half* __restrict__ Ch, __half* __restrict__ Cl,
    const float* __restrict__ bias, const float* __restrict__ res,
    int M, int N, int K, int lda, int ldb, int ldc,
    long long aS1, long long aS2, int aDiv,
    long long bS1, long long bS2, int bDiv,
    long long cS1, long long cS2, int cDiv,
    float alpha, int flags)
{
    constexpr int BN   = NT * 16;
    constexpr int BARR = BN * 64;
    constexpr int STG  = 2 * AARR + 2 * BARR;

    extern __shared__ char smh[];
    const int m0 = blockIdx.y * 128, n0 = blockIdx.x * BN;
    if ((flags & 2) && n0 >= m0 + 128) return;      // causal: fully-masked tile

    const int z = blockIdx.z;
    const long long aOff = (long long)(z / aDiv) * aS1 + (long long)(z % aDiv) * aS2;
    const long long bOff = (long long)(z / bDiv) * bS1 + (long long)(z % bDiv) * bS2;
    const long long cOff = (long long)(z / cDiv) * cS1 + (long long)(z % cDiv) * cS2;
    const __half* Ahb = Ah + aOff;
    const __half* Alb = Al + aOff;
    const __half* Bhb = Bh + bOff;
    const __half* Blb = Bl + bOff;

    const uint32_t sb = (uint32_t)__cvta_generic_to_shared(smh);
    const int tid = threadIdx.x;
    const int wid = tid >> 5, lane = tid & 31;
    const int wm = wid & 3, wn = wid >> 2;
    const int g = lane >> 2, t = lane & 3;

    const int aRow = lane & 15, aChk = lane >> 4;
    const int bRow = (lane & 7) + ((lane >> 4) << 3);
    const int bChk = (lane >> 3) & 1;

    uint32_t aBase[2], aXor[2];
#pragma unroll
    for (int mt = 0; mt < 2; mt++) {
        int r = wm * 32 + mt * 16 + aRow;
        aBase[mt] = (uint32_t)(r * 64);
        aXor[mt]  = (uint32_t)(((r >> 1) & 3) << 4);
    }
    uint32_t bBase[NT / 2], bXor[NT / 2];
#pragma unroll
    for (int p = 0; p < NT / 2; p++) {
        int r = wn * (NT * 8) + p * 16 + bRow;
        bBase[p] = (uint32_t)(r * 64);
        bXor[p]  = (uint32_t)(((r >> 1) & 3) << 4);
    }

    float acc[2][NT][4];
#pragma unroll
    for (int i = 0; i < 2; i++)
#pragma unroll
        for (int j = 0; j < NT; j++)
#pragma unroll
            for (int r = 0; r < 4; r++) acc[i][j][r] = 0.f;

    const int T = K >> 5;

    auto stage = [&](int it, int buf) {
        const int k0 = it << 5;
        uint32_t dst = sb + buf * STG;
#pragma unroll
        for (int j = 0; j < 2; j++) {
            int idx = tid + (j << 8);
            int row = idx >> 2, c = idx & 3;
            long long asrc = (long long)(m0 + row) * lda + k0 + c * 8;
            uint32_t so = (uint32_t)(row * 64) + SWZ(row, c * 16);
            cpasync16(dst + 0 * AARR + so, Ahb + asrc);
            cpasync16(dst + 1 * AARR + so, Alb + asrc);
        }
#pragma unroll
        for (int j = 0; j < NT / 4; j++) {
            int idx = tid + (j << 8);
            int row = idx >> 2, c = idx & 3;
            long long bsrc = (long long)(n0 + row) * ldb + k0 + c * 8;
            uint32_t so = (uint32_t)(row * 64) + SWZ(row, c * 16);
            cpasync16(dst + 2 * AARR + so, Bhb + bsrc);
            cpasync16(dst + 2 * AARR + BARR + so, Blb + bsrc);
        }
    };

    stage(0, 0); cpcommit();
    stage(1, 1); cpcommit();

    for (int it = 0; it < T; ++it) {
        if (it + 1 < T) cpwait<1>(); else cpwait<0>();
        __syncthreads();

        const uint32_t base = sb + (uint32_t)(it % 3) * STG;
        const uint32_t aHb0 = base + 0 * AARR;
        const uint32_t aLb0 = base + 1 * AARR;
        const uint32_t bHb0 = base + 2 * AARR;
        const uint32_t bLb0 = base + 2 * AARR + BARR;

#pragma unroll
        for (int kk = 0; kk < 2; kk++) {
            const uint32_t cbA = (uint32_t)(aChk * 16 + kk * 32);
            const uint32_t cbB = (uint32_t)(bChk * 16 + kk * 32);
            uint32_t ah[2][4], al[2][4];
#pragma unroll
            for (int mt = 0; mt < 2; mt++) {
                uint32_t off = aBase[mt] + (cbA ^ aXor[mt]);
                ldsm4(ah[mt], aHb0 + off);
                ldsm4(al[mt], aLb0 + off);
            }
            uint32_t bh[NT / 2][4], bl[NT / 2][4];
#pragma unroll
            for (int p = 0; p < NT / 2; p++) {
                uint32_t off = bBase[p] + (cbB ^ bXor[p]);
                ldsm4(bh[p], bHb0 + off);
                ldsm4(bl[p], bLb0 + off);
            }
#pragma unroll
            for (int mt = 0; mt < 2; mt++)
#pragma unroll
                for (int p = 0; p < NT / 2; p++) {
                    mma16(acc[mt][2*p],   ah[mt], &bh[p][0]);
                    mma16(acc[mt][2*p],   al[mt], &bh[p][0]);
                    mma16(acc[mt][2*p],   ah[mt], &bl[p][0]);
                    mma16(acc[mt][2*p+1], ah[mt], &bh[p][2]);
                    mma16(acc[mt][2*p+1], al[mt], &bh[p][2]);
                    mma16(acc[mt][2*p+1], ah[mt], &bl[p][2]);
                }
        }

        if (it + 2 < T) { stage(it + 2, (it + 2) % 3); cpcommit(); }
    }

    const bool relu = flags & 1;
#pragma unroll
    for (int mt = 0; mt < 2; mt++) {
#pragma unroll
        for (int hrow = 0; hrow < 2; hrow++) {
            int m = m0 + wm * 32 + mt * 16 + g + hrow * 8;
            long long rowo = cOff + (long long)m * ldc;
#pragma unroll
            for (int nt = 0; nt < NT; nt++) {
                int n = n0 + wn * (NT * 8) + nt * 8 + 2 * t;
                if (n < N) {
                    float v0 = acc[mt][nt][hrow * 2 + 0] * alpha;
                    float v1 = acc[mt][nt][hrow * 2 + 1] * alpha;
                    if (bias) { v0 += bias[n]; v1 += bias[n + 1]; }
                    if (res) {
                        const float* rp = res + rowo;
                        v0 += rp[n]; v1 += rp[n + 1];
                    }
                    if (relu) { v0 = fmaxf(v0, 0.f); v1 = fmaxf(v1, 0.f); }
                    if (C) {
                        float2 vv; vv.x = v0; vv.y = v1;
                        *(float2*)(C + rowo + n) = vv;
                    }
                    if (Ch) {
                        uint32_t hi, lo;
                        split2(make_float2(v0, v1), hi, lo);
                        *(uint32_t*)(Ch + rowo + n) = hi;
                        *(uint32_t*)(Cl + rowo + n) = lo;
                    }
                }
            }
        }
    }
}

#define GH_SMEM8 (3 * (2 * AARR + 2 * 128 * 64))   // 98304
#define GH_SMEM4 (3 * (2 * AARR + 2 * 64 * 64))    // 73728

// -------------------- AV GEMM (fp32 A=probs, fp32 B=[k][n]) -----------------
// Remapped: 8 warps x 16 rows each, all warps cover n=0..63.
// Optional causal K-limit (probs rows zero beyond col m0+128).
#define ASTR 40
#define AVBSTR 68
#define ASZ (128*ASTR)
#define AVBSZ (32*AVBSTR)
#define GEMM_SMEM_AV ((2*ASZ + 2*AVBSZ)*4)

__global__ __launch_bounds__(256) void gemm_av(
    const float* __restrict__ A, const float* __restrict__ B,
    __half* __restrict__ Ch, __half* __restrict__ Cl,
    int M, int N, int K, int lda, int ldb, int ldc,
    long long aS1, long long aS2, int aDiv,
    long long bS1, long long bS2, int bDiv,
    long long cS1, long long cS2, int cDiv,
    int causalLim)
{
    extern __shared__ float sm[];
    const int z = blockIdx.z;
    const float* Ab  = A + (long long)(z / aDiv) * aS1 + (long long)(z % aDiv) * aS2;
    const float* Bbp = B + (long long)(z / bDiv) * bS1 + (long long)(z % bDiv) * bS2;
    const long long cOff = (long long)(z / cDiv) * cS1 + (long long)(z % cDiv) * cS2;

    float* As = sm;
    float* Bs = sm + 2 * ASZ;

    const int tid  = threadIdx.x;
    const int wid  = tid >> 5, lane = tid & 31;
    const int g    = lane >> 2, t   = lane & 3;
    const int m0   = blockIdx.y * 128, n0 = blockIdx.x * 64;

    const uint32_t asA = (uint32_t)__cvta_generic_to_shared(As);
    const uint32_t asB = (uint32_t)__cvta_generic_to_shared(Bs);

    float acc[8][4];
#pragma unroll
    for (int j = 0; j < 8; j++)
#pragma unroll
        for (int r = 0; r < 4; r++) acc[j][r] = 0.f;

    const int Keff  = causalLim ? ((m0 + 128 < K) ? m0 + 128 : K) : K;
    const int nIter = Keff >> 5;

    auto doCopy = [&](int it, int buf) {
        const int k0 = it << 5;
#pragma unroll
        for (int j = 0; j < 4; j++) {               // A: 128 rows x 32 k
            int i   = tid + (j << 8);
            int row = i >> 3, kq = (i & 7) << 2;
            const float* src = Ab + (long long)(m0 + row) * lda + (k0 + kq);
            cpasync16(asA + (uint32_t)((buf * ASZ + row * ASTR + kq) << 2), src);
        }
#pragma unroll
        for (int j = 0; j < 2; j++) {               // B: 32 k-rows x 64 n
            int i  = tid + (j << 8);
            int kr = i >> 4, nc = (i & 15) << 2;
            const float* src = Bbp + (long long)(k0 + kr) * ldb + n0 + nc;
            cpasync16(asB + (uint32_t)((buf * AVBSZ + kr * AVBSTR + nc) << 2), src);
        }
    };

    doCopy(0, 0); cpcommit();

    for (int it = 0; it < nIter; ++it) {
        const int cur = it & 1;
        if (it + 1 < nIter) { doCopy(it + 1, cur ^ 1); cpcommit(); cpwait<1>(); }
        else                { cpwait<0>(); }
        __syncthreads();

        const float* pa = As + cur * ASZ;
        const float* pb = Bs + cur * AVBSZ;

#pragma unroll
        for (int kk = 0; kk < 32; kk += 16) {
            uint32_t ah[4], al[4];
            {
                int r0 = (wid * 16 + g) * ASTR + kk + 2 * t;
                int r1 = r0 + 8 * ASTR;
                split2(*(const float2*)&pa[r0],     ah[0], al[0]);
                split2(*(const float2*)&pa[r1],     ah[1], al[1]);
                split2(*(const float2*)&pa[r0 + 8], ah[2], al[2]);
                split2(*(const float2*)&pa[r1 + 8], ah[3], al[3]);
            }
            uint32_t bh[8][2], bl[8][2];
#pragma unroll
            for (int nt = 0; nt < 8; nt++) {
                int nc = nt * 8 + g;
                const float* base = pb + (long long)(kk + 2 * t) * AVBSTR + nc;
                float2 y0 = make_float2(base[0], base[AVBSTR]);
                float2 y1 = make_float2(base[8 * AVBSTR], base[9 * AVBSTR]);
                split2(y0, bh[nt][0], bl[nt][0]);
                split2(y1, bh[nt][1], bl[nt][1]);
            }
#pragma unroll
            for (int nt = 0; nt < 8; nt++) {
                mma16(acc[nt], ah, bh[nt]);
                mma16(acc[nt], al, bh[nt]);
                mma16(acc[nt], ah, bl[nt]);
            }
        }
        __syncthreads();
    }

#pragma unroll
    for (int hrow = 0; hrow < 2; hrow++) {
        int m = m0 + wid * 16 + g + hrow * 8;
        long long rowo = cOff + (long long)m * ldc;
#pragma unroll
        for (int nt = 0; nt < 8; nt++) {
            int n = n0 + nt * 8 + 2 * t;
            if (n < N) {
                uint32_t hi, lo;
                split2(make_float2(acc[nt][hrow * 2], acc[nt][hrow * 2 + 1]), hi, lo);
                *(uint32_t*)(Ch + rowo + n) = hi;
                *(uint32_t*)(Cl + rowo + n) = lo;
            }
        }
    }
}

// --------------------------- conversion kernels -----------------------------
__global__ void convw_kernel(const float* __restrict__ W,
                             __half* __restrict__ hi, __half* __restrict__ lo,
                             int K, int N, int Npad, long long inS, long long outS)
{
    __shared__ float tile[32][65];
    int z = blockIdx.z;
    const float* Wz = W + (long long)z * inS;
    int k0 = blockIdx.y * 32, n0 = blockIdx.x * 64;
    int tid = threadIdx.x;

#pragma unroll
    for (int j = 0; j < 2; j++) {
        int idx = tid + (j << 8);
        int k = idx >> 4, nq = (idx & 15) << 2;
        int n = n0 + nq;
        float4 v = make_float4(0.f, 0.f, 0.f, 0.f);
        const float* p = Wz + (long long)(k0 + k) * N;
        if (n + 3 < N) v = *(const float4*)(p + n);
        else {
            if (n + 0 < N) v.x = p[n + 0];
            if (n + 1 < N) v.y = p[n + 1];
            if (n + 2 < N) v.z = p[n + 2];
            if (n + 3 < N) v.w = p[n + 3];
        }
        tile[k][nq + 0] = v.x; tile[k][nq + 1] = v.y;
        tile[k][nq + 2] = v.z; tile[k][nq + 3] = v.w;
    }
    __syncthreads();

#pragma unroll
    for (int j = 0; j < 4; j++) {
        int idx = tid + (j << 8);
        int n = idx >> 4, tq = (idx & 15) << 1;
        int gn = n0 + n;
        if (gn < Npad) {
            float v0 = tile[tq][n], v1 = tile[tq + 1][n];
            __half2 h = __floats2half2_rn(v0, v1);
            float2 hf = __half22float2(h);
            __half2 l = __floats2half2_rn(v0 - hf.x, v1 - hf.y);
            long long o = (long long)z * outS + (long long)gn * K + k0 + tq;
            *(__half2*)(hi + o) = h;
            *(__half2*)(lo + o) = l;
        }
    }
}

__global__ void convqkv_kernel(const float* __restrict__ Wq, const float* __restrict__ Wk,
                               const float* __restrict__ Wv,
                               __half* __restrict__ hi, __half* __restrict__ lo)
{
    __shared__ float tile[32][65];
    int kt = blockIdx.x, sh = blockIdx.y;
    int sel = sh >> 3, h = sh & 7;
    const float* W = (sel == 0) ? Wq : (sel == 1) ? Wk : Wv;
    const float* src = W + ((long long)h * 512 + kt * 32) * 64;
    int tid = threadIdx.x;

#pragma unroll
    for (int j = 0; j < 2; j++) {
        int idx = tid + (j << 8);
        int k = idx >> 4, eq = (idx & 15) << 2;
        float4 v = *(const float4*)(src + k * 64 + eq);
        tile[k][eq + 0] = v.x; tile[k][eq + 1] = v.y;
        tile[k][eq + 2] = v.z; tile[k][eq + 3] = v.w;
    }
    __syncthreads();

#pragma unroll
    for (int j = 0; j < 4; j++) {
        int idx = tid + (j << 8);
        int e = idx >> 4, tq = (idx & 15) << 1;
        int n = sel * 512 + h * 64 + e;
        float v0 = tile[tq][e], v1 = tile[tq + 1][e];
        __half2 hh = __floats2half2_rn(v0, v1);
        float2 hf = __half22float2(hh);
        __half2 ll = __floats2half2_rn(v0 - hf.x, v1 - hf.y);
        long long o = (long long)n * 512 + kt * 32 + tq;
        *(__half2*)(hi + o) = hh;
        *(__half2*)(lo + o) = ll;
    }
}

__global__ void conva_kernel(const float* __restrict__ src,
                             __half* __restrict__ hi, __half* __restrict__ lo, int n) {
    int i = blockIdx.x * 256 + threadIdx.x;
    if (i < n) {
        float v = src[i];
        __half h = __float2half_rn(v);
        hi[i] = h;
        lo[i] = __float2half_rn(v - __half2float(h));
    }
}

// --------------------------- elementwise kernels ---------------------------
__global__ void embed_kernel(const int* __restrict__ tok, const float* __restrict__ emb,
                             float* __restrict__ x,
                             __half* __restrict__ xh, __half* __restrict__ xl) {
    int idx = blockIdx.x * 256 + threadIdx.x;
    int t = tok[idx >> 9];
    float v = emb[(long long)t * Dm_ + (idx & 511)] * 8.0f;
    x[idx] = v;
    __half h = __float2half_rn(v);
    xh[idx] = h;
    xl[idx] = __float2half_rn(v - __half2float(h));
}

__global__ void bn_stats_kernel(const float* __restrict__ x,
                                float* __restrict__ mu, float* __restrict__ rstd) {
    int d = blockIdx.x * 32 + threadIdx.x;
    float s = 0.f, s2 = 0.f;
    for (int i = threadIdx.y; i < BS_; i += 8) {
        float v = x[(long long)i * Dm_ + d];
        s += v; s2 += v * v;
    }
    __shared__ float sh[8][33], sh2[8][33];
    sh[threadIdx.y][threadIdx.x] = s;
    sh2[threadIdx.y][threadIdx.x] = s2;
    __syncthreads();
    if (threadIdx.y == 0) {
#pragma unroll
        for (int r = 1; r < 8; r++) { s += sh[r][threadIdx.x]; s2 += sh2[r][threadIdx.x]; }
        float m = s * (1.f / BS_);
        float var = s2 * (1.f / BS_) - m * m;
        mu[d] = m;
        rstd[d] = rsqrtf(var + 1e-5f);
    }
}

__global__ void bn_apply_kernel(const float* __restrict__ xin, float* __restrict__ xout,
                                __half* __restrict__ xh, __half* __restrict__ xl,
                                const float* __restrict__ mu, const float* __restrict__ rstd,
                                const float* __restrict__ gamma, const float* __restrict__ beta) {
    int idx = blockIdx.x * 256 + threadIdx.x;
    int d = idx & 511;
    float v = (xin[idx] - mu[d]) * rstd[d] * gamma[d] + beta[d];
    xout[idx] = v;
    __half h = __float2half_rn(v);
    xh[idx] = h;
    xl[idx] = __float2half_rn(v - __half2float(h));
}

// Attention softmax, T=512 fixed: 2 register-resident elems/thread, 1 read.
__global__ __launch_bounds__(256) void softmax512_kernel(float* __restrict__ p, int causal) {
    __shared__ float mred[256], sred[256];
    long long row = blockIdx.x;
    float* x = p + row * 512;
    int tid = threadIdx.x;
    int tmax = causal ? (int)(row & 511) : 511;
    int t0 = tid, t1 = tid + 256;

    float v0 = (t0 <= tmax) ? x[t0] : -1e30f;
    float v1 = (t1 <= tmax) ? x[t1] : -1e30f;
    mred[tid] = fmaxf(v0, v1);
    __syncthreads();
    for (int o = 128; o > 0; o >>= 1) {
        if (tid < o) mred[tid] = fmaxf(mred[tid], mred[tid + o]);
        __syncthreads();
    }
    float M = mred[0];
    float e0 = (t0 <= tmax) ? __expf(v0 - M) : 0.f;
    float e1 = (t1 <= tmax) ? __expf(v1 - M) : 0.f;
    sred[tid] = e0 + e1;
    __syncthreads();
    for (int o = 128; o > 0; o >>= 1) {
        if (tid < o) sred[tid] += sred[tid + o];
        __syncthreads();
    }
    float inv = 1.f / sred[0];
    x[t0] = e0 * inv;
    x[t1] = e1 * inv;
}

// Vocab softmax: 37 elems/thread kept resident (ptxas may spill a few to
// L1-backed local under the 64-reg cap) — single global read of logits.
#define VITER 37
__global__ __launch_bounds__(1024, 1) void softmax_vocab_kernel(float* __restrict__ p, int T) {
    __shared__ float red[1024];
    long long row = blockIdx.x;
    float* x = p + row * (long long)T;
    int tid = threadIdx.x;

    float vals[VITER];
    float m = -1e30f;
#pragma unroll
    for (int j = 0; j < VITER; j++) {
        int t = tid + j * 1024;
        float v = (t < T) ? x[t] : -1e30f;
        vals[j] = v;
        m = fmaxf(m, v);
    }
    red[tid] = m; __syncthreads();
    for (int o = 512; o > 0; o >>= 1) {
        if (tid < o) red[tid] = fmaxf(red[tid], red[tid + o]);
        __syncthreads();
    }
    float M = red[0]; __syncthreads();

    float sum = 0.f;
#pragma unroll
    for (int j = 0; j < VITER; j++) {
        int t = tid + j * 1024;
        if (t < T) { vals[j] = __expf(vals[j] - M); sum += vals[j]; }
    }
    red[tid] = sum; __syncthreads();
    for (int o = 512; o > 0; o >>= 1) {
        if (tid < o) red[tid] += red[tid + o];
        __syncthreads();
    }
    float inv = 1.f / red[0];
#pragma unroll
    for (int j = 0; j < VITER; j++) {
        int t = tid + j * 1024;
        if (t < T) x[t] = vals[j] * inv;
    }
}

// ------------------------------- host side ---------------------------------
static inline int cdiv(int a, int b) { return (a + b - 1) / b; }

static void gh8(const __half* Ah, const __half* Al, const __half* Bh, const __half* Bl,
                float* C, __half* Ch, __half* Cl,
                const float* bias, const float* res,
                int M, int N, int K, int lda, int ldb, int ldc, int flags)
{
    dim3 g(cdiv(N, 128), M / 128, 1);
    gemm_h<8><<<g, 256, GH_SMEM8>>>(Ah, Al, Bh, Bl, C, Ch, Cl, bias, res,
                                    M, N, K, lda, ldb, ldc,
                                    0, 0, 1, 0, 0, 1, 0, 0, 1, 1.f, flags);
}
static void gh4(const __half* Ah, const __half* Al, const __half* Bh, const __half* Bl,
                float* C, __half* Ch, __half* Cl,
                const float* bias, const float* res,
                int M, int N, int K, int lda, int ldb, int ldc, int flags)
{
    dim3 g(cdiv(N, 64), M / 128, 1);
    gemm_h<4><<<g, 256, GH_SMEM4>>>(Ah, Al, Bh, Bl, C, Ch, Cl, bias, res,
                                    M, N, K, lda, ldb, ldc,
                                    0, 0, 1, 0, 0, 1, 0, 0, 1, 1.f, flags);
}

extern "C" void kernel_launch(void* const* d_in, const int* in_sizes, int n_in,
                              void* d_out, int out_size)
{
    const int*   tok   = (const int*)  d_in[0];
    const float* enc   = (const float*)d_in[1];
    const float* emb   = (const float*)d_in[2];
    const float* Wq1   = (const float*)d_in[3];
    const float* Wk1   = (const float*)d_in[4];
    const float* Wv1   = (const float*)d_in[5];
    const float* Wo1   = (const float*)d_in[6];
    const float* Wq2   = (const float*)d_in[7];
    const float* Wk2   = (const float*)d_in[8];
    const float* Wv2   = (const float*)d_in[9];
    const float* Wo2   = (const float*)d_in[10];
    const float* gamma = (const float*)d_in[11];
    const float* beta  = (const float*)d_in[12];
    const float* W1    = (const float*)d_in[13];
    const float* b1    = (const float*)d_in[14];
    const float* W2    = (const float*)d_in[15];
    const float* b2    = (const float*)d_in[16];
    const float* Wout  = (const float*)d_in[17];
    const float* bout  = (const float*)d_in[18];
    float* out = (float*)d_out;

    cudaFuncSetAttribute(gemm_h<8>, cudaFuncAttributeMaxDynamicSharedMemorySize, GH_SMEM8);
    cudaFuncSetAttribute(gemm_h<4>, cudaFuncAttributeMaxDynamicSharedMemorySize, GH_SMEM4);
    cudaFuncSetAttribute(gemm_av,   cudaFuncAttributeMaxDynamicSharedMemorySize, GEMM_SMEM_AV);

    float *x, *tmp, *qkv, *sc, *mu, *rstd;
    cudaGetSymbolAddress((void**)&x,    g_x);
    cudaGetSymbolAddress((void**)&tmp,  g_tmp);
    cudaGetSymbolAddress((void**)&qkv,  g_qkv);
    cudaGetSymbolAddress((void**)&sc,   g_sc);
    cudaGetSymbolAddress((void**)&mu,   g_mu);
    cudaGetSymbolAddress((void**)&rstd, g_rstd);

    __half *xh, *xl, *qkvh, *qkvl, *attnh, *attnl, *ffh, *ffl, *ench, *encl;
    cudaGetSymbolAddress((void**)&xh,    g_xh);
    cudaGetSymbolAddress((void**)&xl,    g_xl);
    cudaGetSymbolAddress((void**)&qkvh,  g_qkvh);
    cudaGetSymbolAddress((void**)&qkvl,  g_qkvl);
    cudaGetSymbolAddress((void**)&attnh, g_attnh);
    cudaGetSymbolAddress((void**)&attnl, g_attnl);
    cudaGetSymbolAddress((void**)&ffh,   g_ffh);
    cudaGetSymbolAddress((void**)&ffl,   g_ffl);
    cudaGetSymbolAddress((void**)&ench,  g_ench);
    cudaGetSymbolAddress((void**)&encl,  g_encl);

    __half *wtT_h, *wtT_l, *w1T_h, *w1T_l, *w2T_h, *w2T_l;
    __half *wo1T_h, *wo1T_l, *wo2T_h, *wo2T_l, *woutT_h, *woutT_l;
    cudaGetSymbolAddress((void**)&wtT_h,  g_wtT_h);
    cudaGetSymbolAddress((void**)&wtT_l,  g_wtT_l);
    cudaGetSymbolAddress((void**)&w1T_h,  g_w1T_h);
    cudaGetSymbolAddress((void**)&w1T_l,  g_w1T_l);
    cudaGetSymbolAddress((void**)&w2T_h,  g_w2T_h);
    cudaGetSymbolAddress((void**)&w2T_l,  g_w2T_l);
    cudaGetSymbolAddress((void**)&wo1T_h, g_wo1T_h);
    cudaGetSymbolAddress((void**)&wo1T_l, g_wo1T_l);
    cudaGetSymbolAddress((void**)&wo2T_h, g_wo2T_h);
    cudaGetSymbolAddress((void**)&wo2T_l, g_wo2T_l);
    cudaGetSymbolAddress((void**)&woutT_h, g_woutT_h);
    cudaGetSymbolAddress((void**)&woutT_l, g_woutT_l);

    const long long HW  = (long long)Dm_ * Dk_;
    const long long QBh = (long long)Ss_ * 1536;
    const long long SCZ = (long long)Ss_ * Ss_;
    const float     isq = 0.125f;

    // ---- weight conversion (fused + vectorized) ----
    convw_kernel<<<dim3(Ff_/64, Dm_/32, Nx_), 256>>>(W1, w1T_h, w1T_l, Dm_, Ff_, Ff_,
                                                     (long long)Dm_*Ff_, (long long)Ff_*Dm_);
    convw_kernel<<<dim3(Dm_/64, Ff_/32, Nx_), 256>>>(W2, w2T_h, w2T_l, Ff_, Dm_, Dm_,
                                                     (long long)Ff_*Dm_, (long long)Dm_*Ff_);
    convw_kernel<<<dim3(Dm_/64, Dm_/32, Nx_), 256>>>(Wo1, wo1T_h, wo1T_l, Dm_, Dm_, Dm_,
                                                     (long long)Dm_*Dm_, (long long)Dm_*Dm_);
    convw_kernel<<<dim3(Dm_/64, Dm_/32, Nx_), 256>>>(Wo2, wo2T_h, wo2T_l, Dm_, Dm_, Dm_,
                                                     (long long)Dm_*Dm_, (long long)Dm_*Dm_);
    convw_kernel<<<dim3(VvP_/64, Dm_/32, 1), 256>>>(Wout, woutT_h, woutT_l, Dm_, Vv_, VvP_, 0, 0);
    for (int s = 0; s < 12; s++) {
        int i = s >> 1, pass = s & 1;
        const float* wq = pass ? Wq2 : Wq1;
        const float* wk = pass ? Wk2 : Wk1;
        const float* wv = pass ? Wv2 : Wv1;
        convqkv_kernel<<<dim3(16, 24), 256>>>(wq + (long long)i*Hh_*HW,
                                              wk + (long long)i*Hh_*HW,
                                              wv + (long long)i*Hh_*HW,
                                              wtT_h + (long long)s*1536*512,
                                              wtT_l + (long long)s*1536*512);
    }
    conva_kernel<<<cdiv(BS_*Dm_, 256), 256>>>(enc, ench, encl, BS_*Dm_);

    embed_kernel<<<BS_ * Dm_ / 256, 256>>>(tok, emb, x, xh, xl);

    for (int i = 0; i < Nx_; i++) {
        const float* bb1 = b1 + (long long)i * Ff_;
        const float* bb2 = b2 + (long long)i * Dm_;

        for (int attn_pass = 0; attn_pass < 2; attn_pass++) {
            const int self = (attn_pass == 0);
            const int s = i * 2 + attn_pass;
            const __half* wth = wtT_h + (long long)s * 1536 * 512;
            const __half* wtl = wtT_l + (long long)s * 1536 * 512;

            if (self) {
                gh8(xh, xl, wth, wtl, qkv, qkvh, qkvl, nullptr, nullptr,
                    BS_, 1536, Dm_, Dm_, Dm_, 1536, 0);
            } else {
                gh4(xh, xl, wth, wtl, qkv, qkvh, qkvl, nullptr, nullptr,
                    BS_, 512, Dm_, Dm_, Dm_, 1536, 0);
                dim3 g(8, 16, 1);
                gemm_h<8><<<g, 256, GH_SMEM8>>>(ench, encl,
                                                wth + 512LL*512, wtl + 512LL*512,
                                                qkv + 512, qkvh + 512, qkvl + 512,
                                                nullptr, nullptr,
                                                BS_, 1024, Dm_, Dm_, Dm_, 1536,
                                                0, 0, 1, 0, 0, 1, 0, 0, 1, 1.f, 0);
            }
            // scores[z=b*8+h] = Q @ K^T * isq  (causal skip for self)
            {
                dim3 g(4, 4, Bb_ * Hh_);
                gemm_h<8><<<g, 256, GH_SMEM8>>>(qkvh, qkvl, qkvh + 512, qkvl + 512,
                                                sc, nullptr, nullptr, nullptr, nullptr,
                                                Ss_, Ss_, Dk_, 1536, 1536, Ss_,
                                                QBh, 64, Hh_,  QBh, 64, Hh_,  SCZ, 0, 1,
                                                isq, self ? 2 : 0);
            }
            softmax512_kernel<<<Bb_*Hh_*Ss_, 256>>>(sc, self ? 1 : 0);
            // attn[b,s,h*64+e] = probs @ V  (remapped warps, causal K-limit)
            {
                dim3 g(1, 4, Bb_ * Hh_);
                gemm_av<<<g, 256, GEMM_SMEM_AV>>>(sc, qkv + 1024, attnh, attnl,
                                                  Ss_, Dk_, Ss_, Ss_, 1536, Dm_,
                                                  SCZ, 0, 1,  QBh, 64, Hh_,
                                                  (long long)Ss_*Dm_, Dk_, Hh_,
                                                  self ? 1 : 0);
            }
            // tmp = attn @ Wo + x
            const __half* woh = (self ? wo1T_h : wo2T_h) + (long long)i*512*512;
            const __half* wol = (self ? wo1T_l : wo2T_l) + (long long)i*512*512;
            gh4(attnh, attnl, woh, wol, tmp, nullptr, nullptr, nullptr, x,
                BS_, Dm_, Dm_, Dm_, Dm_, Dm_, 0);
            bn_stats_kernel<<<Dm_/32, dim3(32, 8)>>>(tmp, mu, rstd);
            bn_apply_kernel<<<BS_*Dm_/256, 256>>>(tmp, x, xh, xl, mu, rstd,
                                                  gamma + (long long)(i*3 + attn_pass)*Dm_,
                                                  beta  + (long long)(i*3 + attn_pass)*Dm_);
        }

        // ---- feed-forward
        gh8(xh, xl, w1T_h + (long long)i*Ff_*512, w1T_l + (long long)i*Ff_*512,
            nullptr, ffh, ffl, bb1, nullptr, BS_, Ff_, Dm_, Dm_, Dm_, Ff_, 1);
        gh4(ffh, ffl, w2T_h + (long long)i*512LL*Ff_, w2T_l + (long long)i*512LL*Ff_,
            tmp, nullptr, nullptr, bb2, x, BS_, Dm_, Ff_, Ff_, Ff_, Dm_, 0);
        bn_stats_kernel<<<Dm_/32, dim3(32, 8)>>>(tmp, mu, rstd);
        bn_apply_kernel<<<BS_*Dm_/256, 256>>>(tmp, x, xh, xl, mu, rstd,
                                              gamma + (long long)(i*3 + 2)*Dm_,
                                              beta  + (long long)(i*3 + 2)*Dm_);
    }

    // ---- output projection + vocab softmax
    gh8(xh, xl, woutT_h, woutT_l, out, nullptr, nullptr, bout, nullptr,
        BS_, Vv_, Dm_, Dm_, Dm_, Vv_, 0);
    softmax_vocab_kernel<<<BS_, 1024>>>(out, Vv_);

    (void)in_sizes; (void)n_in; (void)out_size;
}

// round 12
// speedup vs baseline: 1.4043x; 1.0189x over previous
#include <cuda_runtime.h>
#include <cuda_fp16.h>
#include <math.h>
#include <stdint.h>

// ---------------------------------------------------------------------------
// Decoder — Round 12: fp16 probs + half-A ldsm AV (2-pass) + profiling reorder
// ---------------------------------------------------------------------------

#define Bb_ 4
#define Ss_ 512
#define Dm_ 512
#define Hh_ 8
#define Dk_ 64
#define Ff_ 2048
#define Vv_ 37000
#define VvP_ 37120
#define Nx_ 6
#define BS_ 2048

// ------------------------- scratch (static device globals) -----------------
__device__ __align__(16) float g_x    [BS_*Dm_];
__device__ __align__(16) float g_tmp  [BS_*Dm_];
__device__ __align__(16) float g_qkv  [BS_*3*Dm_];     // fp32 (V read by AV gemm)
__device__ __align__(16) float g_sc   [Bb_*Hh_*Ss_*Ss_];     // fp32 scores
__device__ __align__(16) __half g_sph [Bb_*Hh_*Ss_*Ss_];     // fp16 probs
__device__ float g_mu   [Dm_];
__device__ float g_rstd [Dm_];

// hi/lo half activations
__device__ __align__(16) __half g_xh   [BS_*Dm_];
__device__ __align__(16) __half g_xl   [BS_*Dm_];
__device__ __align__(16) __half g_qkvh [BS_*3*Dm_];
__device__ __align__(16) __half g_qkvl [BS_*3*Dm_];
__device__ __align__(16) __half g_attnh[BS_*Dm_];
__device__ __align__(16) __half g_attnl[BS_*Dm_];
__device__ __align__(16) __half g_ffh  [BS_*Ff_];
__device__ __align__(16) __half g_ffl  [BS_*Ff_];
__device__ __align__(16) __half g_ench [BS_*Dm_];
__device__ __align__(16) __half g_encl [BS_*Dm_];

// hi/lo half weights, [N, K] K-major
__device__ __align__(16) __half g_wtT_h [12L*1536*512];
__device__ __align__(16) __half g_wtT_l [12L*1536*512];
__device__ __align__(16) __half g_w1T_h [6L*2048*512];
__device__ __align__(16) __half g_w1T_l [6L*2048*512];
__device__ __align__(16) __half g_w2T_h [6L*512*2048];
__device__ __align__(16) __half g_w2T_l [6L*512*2048];
__device__ __align__(16) __half g_wo1T_h[6L*512*512];
__device__ __align__(16) __half g_wo1T_l[6L*512*512];
__device__ __align__(16) __half g_wo2T_h[6L*512*512];
__device__ __align__(16) __half g_wo2T_l[6L*512*512];
__device__ __align__(16) __half g_woutT_h[(long long)VvP_*512];
__device__ __align__(16) __half g_woutT_l[(long long)VvP_*512];

// ------------------------------- helpers -----------------------------------
__device__ __forceinline__ void split2(float2 x, uint32_t& hi, uint32_t& lo) {
    __half2 h = __float22half2_rn(x);
    float2 hf = __half22float2(h);
    __half2 l = __float22half2_rn(make_float2(x.x - hf.x, x.y - hf.y));
    hi = *reinterpret_cast<uint32_t*>(&h);
    lo = *reinterpret_cast<uint32_t*>(&l);
}
__device__ __forceinline__ void cpasync16(uint32_t dst, const void* src) {
    asm volatile("cp.async.cg.shared.global [%0], [%1], 16;"
                 :: "r"(dst), "l"(src));
}
__device__ __forceinline__ void cpcommit() { asm volatile("cp.async.commit_group;"); }
template <int NN> __device__ __forceinline__ void cpwait() {
    asm volatile("cp.async.wait_group %0;" :: "n"(NN));
}
__device__ __forceinline__ void mma16(float* d, const uint32_t* a, const uint32_t* b) {
    asm volatile(
        "mma.sync.aligned.m16n8k16.row.col.f32.f16.f16.f32 "
        "{%0,%1,%2,%3}, {%4,%5,%6,%7}, {%8,%9}, {%0,%1,%2,%3};"
        : "+f"(d[0]), "+f"(d[1]), "+f"(d[2]), "+f"(d[3])
        : "r"(a[0]), "r"(a[1]), "r"(a[2]), "r"(a[3]), "r"(b[0]), "r"(b[1]));
}
__device__ __forceinline__ void ldsm4(uint32_t* r, uint32_t addr) {
    asm volatile("ldmatrix.sync.aligned.m8n8.x4.shared.b16 {%0,%1,%2,%3}, [%4];"
                 : "=r"(r[0]), "=r"(r[1]), "=r"(r[2]), "=r"(r[3]) : "r"(addr));
}

// 64B rows; chunk (16B) swizzle keeps ldmatrix 8-row phases conflict-free.
#define SWZ(row, cb) ((uint32_t)((cb) ^ ((((row) >> 1) & 3) << 4)))

// ------------------------ GEMM: pure-half operands --------------------------
// (unchanged from R9/R11) 3-stage cp.async pipeline, swizzled 64B-row smem.
#define AARR (128*64)                 // one A array: 8192 B

template <int NT>
__global__ __launch_bounds__(256) void gemm_h(
    const __half* __restrict__ Ah, const __half* __restrict__ Al,
    const __half* __restrict__ Bh, const __half* __restrict__ Bl,
    float* __restrict__ C, __half* __restrict__ Ch, __half* __restrict__ Cl,
    const float* __restrict__ bias, const float* __restrict__ res,
    int M, int N, int K, int lda, int ldb, int ldc,
    long long aS1, long long aS2, int aDiv,
    long long bS1, long long bS2, int bDiv,
    long long cS1, long long cS2, int cDiv,
    float alpha, int flags)
{
    constexpr int BN   = NT * 16;
    constexpr int BARR = BN * 64;
    constexpr int STG  = 2 * AARR + 2 * BARR;

    extern __shared__ char smh[];
    const int m0 = blockIdx.y * 128, n0 = blockIdx.x * BN;
    if ((flags & 2) && n0 >= m0 + 128) return;      // causal: fully-masked tile

    const int z = blockIdx.z;
    const long long aOff = (long long)(z / aDiv) * aS1 + (long long)(z % aDiv) * aS2;
    const long long bOff = (long long)(z / bDiv) * bS1 + (long long)(z % bDiv) * bS2;
    const long long cOff = (long long)(z / cDiv) * cS1 + (long long)(z % cDiv) * cS2;
    const __half* Ahb = Ah + aOff;
    const __half* Alb = Al + aOff;
    const __half* Bhb = Bh + bOff;
    const __half* Blb = Bl + bOff;

    const uint32_t sb = (uint32_t)__cvta_generic_to_shared(smh);
    const int tid = threadIdx.x;
    const int wid = tid >> 5, lane = tid & 31;
    const int wm = wid & 3, wn = wid >> 2;
    const int g = lane >> 2, t = lane & 3;

    const int aRow = lane & 15, aChk = lane >> 4;
    const int bRow = (lane & 7) + ((lane >> 4) << 3);
    const int bChk = (lane >> 3) & 1;

    uint32_t aBase[2], aXor[2];
#pragma unroll
    for (int mt = 0; mt < 2; mt++) {
        int r = wm * 32 + mt * 16 + aRow;
        aBase[mt] = (uint32_t)(r * 64);
        aXor[mt]  = (uint32_t)(((r >> 1) & 3) << 4);
    }
    uint32_t bBase[NT / 2], bXor[NT / 2];
#pragma unroll
    for (int p = 0; p < NT / 2; p++) {
        int r = wn * (NT * 8) + p * 16 + bRow;
        bBase[p] = (uint32_t)(r * 64);
        bXor[p]  = (uint32_t)(((r >> 1) & 3) << 4);
    }

    float acc[2][NT][4];
#pragma unroll
    for (int i = 0; i < 2; i++)
#pragma unroll
        for (int j = 0; j < NT; j++)
#pragma unroll
            for (int r = 0; r < 4; r++) acc[i][j][r] = 0.f;

    const int T = K >> 5;

    auto stage = [&](int it, int buf) {
        const int k0 = it << 5;
        uint32_t dst = sb + buf * STG;
#pragma unroll
        for (int j = 0; j < 2; j++) {
            int idx = tid + (j << 8);
            int row = idx >> 2, c = idx & 3;
            long long asrc = (long long)(m0 + row) * lda + k0 + c * 8;
            uint32_t so = (uint32_t)(row * 64) + SWZ(row, c * 16);
            cpasync16(dst + 0 * AARR + so, Ahb + asrc);
            cpasync16(dst + 1 * AARR + so, Alb + asrc);
        }
#pragma unroll
        for (int j = 0; j < NT / 4; j++) {
            int idx = tid + (j << 8);
            int row = idx >> 2, c = idx & 3;
            long long bsrc = (long long)(n0 + row) * ldb + k0 + c * 8;
            uint32_t so = (uint32_t)(row * 64) + SWZ(row, c * 16);
            cpasync16(dst + 2 * AARR + so, Bhb + bsrc);
            cpasync16(dst + 2 * AARR + BARR + so, Blb + bsrc);
        }
    };

    stage(0, 0); cpcommit();
    stage(1, 1); cpcommit();

    for (int it = 0; it < T; ++it) {
        if (it + 1 < T) cpwait<1>(); else cpwait<0>();
        __syncthreads();

        const uint32_t base = sb + (uint32_t)(it % 3) * STG;
        const uint32_t aHb0 = base + 0 * AARR;
        const uint32_t aLb0 = base + 1 * AARR;
        const uint32_t bHb0 = base + 2 * AARR;
        const uint32_t bLb0 = base + 2 * AARR + BARR;

#pragma unroll
        for (int kk = 0; kk < 2; kk++) {
            const uint32_t cbA = (uint32_t)(aChk * 16 + kk * 32);
            const uint32_t cbB = (uint32_t)(bChk * 16 + kk * 32);
            uint32_t ah[2][4], al[2][4];
#pragma unroll
            for (int mt = 0; mt < 2; mt++) {
                uint32_t off = aBase[mt] + (cbA ^ aXor[mt]);
                ldsm4(ah[mt], aHb0 + off);
                ldsm4(al[mt], aLb0 + off);
            }
            uint32_t bh[NT / 2][4], bl[NT / 2][4];
#pragma unroll
            for (int p = 0; p < NT / 2; p++) {
                uint32_t off = bBase[p] + (cbB ^ bXor[p]);
                ldsm4(bh[p], bHb0 + off);
                ldsm4(bl[p], bLb0 + off);
            }
#pragma unroll
            for (int mt = 0; mt < 2; mt++)
#pragma unroll
                for (int p = 0; p < NT / 2; p++) {
                    mma16(acc[mt][2*p],   ah[mt], &bh[p][0]);
                    mma16(acc[mt][2*p],   al[mt], &bh[p][0]);
                    mma16(acc[mt][2*p],   ah[mt], &bl[p][0]);
                    mma16(acc[mt][2*p+1], ah[mt], &bh[p][2]);
                    mma16(acc[mt][2*p+1], al[mt], &bh[p][2]);
                    mma16(acc[mt][2*p+1], ah[mt], &bl[p][2]);
                }
        }

        if (it + 2 < T) { stage(it + 2, (it + 2) % 3); cpcommit(); }
    }

    const bool relu = flags & 1;
#pragma unroll
    for (int mt = 0; mt < 2; mt++) {
#pragma unroll
        for (int hrow = 0; hrow < 2; hrow++) {
            int m = m0 + wm * 32 + mt * 16 + g + hrow * 8;
            long long rowo = cOff + (long long)m * ldc;
#pragma unroll
            for (int nt = 0; nt < NT; nt++) {
                int n = n0 + wn * (NT * 8) + nt * 8 + 2 * t;
                if (n < N) {
                    float v0 = acc[mt][nt][hrow * 2 + 0] * alpha;
                    float v1 = acc[mt][nt][hrow * 2 + 1] * alpha;
                    if (bias) { v0 += bias[n]; v1 += bias[n + 1]; }
                    if (res) {
                        const float* rp = res + rowo;
                        v0 += rp[n]; v1 += rp[n + 1];
                    }
                    if (relu) { v0 = fmaxf(v0, 0.f); v1 = fmaxf(v1, 0.f); }
                    if (C) {
                        float2 vv; vv.x = v0; vv.y = v1;
                        *(float2*)(C + rowo + n) = vv;
                    }
                    if (Ch) {
                        uint32_t hi, lo;
                        split2(make_float2(v0, v1), hi, lo);
                        *(uint32_t*)(Ch + rowo + n) = hi;
                        *(uint32_t*)(Cl + rowo + n) = lo;
                    }
                }
            }
        }
    }
}

#define GH_SMEM8 (3 * (2 * AARR + 2 * 128 * 64))   // 98304
#define GH_SMEM4 (3 * (2 * AARR + 2 * 64 * 64))    // 73728

// -------------------- AV GEMM (half A=probs, fp32 B=[k][n]) -----------------
// A: fp16 probs [M,K], staged + ldsm (no split). B: fp32 V, in-loop split.
// 2 MMA passes (ah*bh + ah*bl). 8 warps x 16 rows, n=0..63.
// Causal K-limit: probs rows zero beyond col m0+128.
#define AV_ASTG 8192                   // A halves stage: 128 rows * 64 B
#define AVBSTR 68
#define AVBSZ (32*AVBSTR)
#define GEMM_SMEM_AV (2*AV_ASTG + 2*AVBSZ*4)

__global__ __launch_bounds__(256) void gemm_av(
    const __half* __restrict__ A, const float* __restrict__ B,
    __half* __restrict__ Ch, __half* __restrict__ Cl,
    int M, int N, int K, int lda, int ldb, int ldc,
    long long aS1, long long bS1, long long bS2, int bDiv,
    long long cS1, long long cS2, int cDiv,
    int causalLim)
{
    extern __shared__ char smav[];
    const int z = blockIdx.z;
    const __half* Ab  = A + (long long)z * aS1;
    const float*  Bbp = B + (long long)(z / bDiv) * bS1 + (long long)(z % bDiv) * bS2;
    const long long cOff = (long long)(z / cDiv) * cS1 + (long long)(z % cDiv) * cS2;

    const uint32_t asA = (uint32_t)__cvta_generic_to_shared(smav);
    float* Bs = (float*)(smav + 2 * AV_ASTG);
    const uint32_t asB = (uint32_t)__cvta_generic_to_shared(Bs);

    const int tid  = threadIdx.x;
    const int wid  = tid >> 5, lane = tid & 31;
    const int g    = lane >> 2, t   = lane & 3;
    const int m0   = blockIdx.y * 128, n0 = blockIdx.x * 64;

    const int aRow = lane & 15, aChk = lane >> 4;
    const uint32_t aBase = (uint32_t)((wid * 16 + aRow) * 64);
    const uint32_t aXor  = (uint32_t)((((wid * 16 + aRow) >> 1) & 3) << 4);

    float acc[8][4];
#pragma unroll
    for (int j = 0; j < 8; j++)
#pragma unroll
        for (int r = 0; r < 4; r++) acc[j][r] = 0.f;

    const int Keff  = causalLim ? ((m0 + 128 < K) ? m0 + 128 : K) : K;
    const int nIter = Keff >> 5;

    auto doCopy = [&](int it, int buf) {
        const int k0 = it << 5;
#pragma unroll
        for (int j = 0; j < 2; j++) {               // A: 128 rows x 32 halves
            int i   = tid + (j << 8);
            int row = i >> 2, c = i & 3;
            const __half* src = Ab + (long long)(m0 + row) * lda + k0 + c * 8;
            cpasync16(asA + (uint32_t)(buf * AV_ASTG + row * 64) + SWZ(row, c * 16), src);
        }
#pragma unroll
        for (int j = 0; j < 2; j++) {               // B: 32 k-rows x 64 n fp32
            int i  = tid + (j << 8);
            int kr = i >> 4, nc = (i & 15) << 2;
            const float* src = Bbp + (long long)(k0 + kr) * ldb + n0 + nc;
            cpasync16(asB + (uint32_t)((buf * AVBSZ + kr * AVBSTR + nc) << 2), src);
        }
    };

    doCopy(0, 0); cpcommit();

    for (int it = 0; it < nIter; ++it) {
        const int cur = it & 1;
        if (it + 1 < nIter) { doCopy(it + 1, cur ^ 1); cpcommit(); cpwait<1>(); }
        else                { cpwait<0>(); }
        __syncthreads();

        const uint32_t aCur = asA + (uint32_t)(cur * AV_ASTG);
        const float* pb = Bs + cur * AVBSZ;

#pragma unroll
        for (int kk = 0; kk < 2; kk++) {
            uint32_t ah[4];
            ldsm4(ah, aCur + aBase + (((uint32_t)(aChk * 16 + kk * 32)) ^ aXor));
            uint32_t bh[8][2], bl[8][2];
#pragma unroll
            for (int nt = 0; nt < 8; nt++) {
                int nc = nt * 8 + g;
                const float* base = pb + (long long)(kk * 16 + 2 * t) * AVBSTR + nc;
                float2 y0 = make_float2(base[0], base[AVBSTR]);
                float2 y1 = make_float2(base[8 * AVBSTR], base[9 * AVBSTR]);
                split2(y0, bh[nt][0], bl[nt][0]);
                split2(y1, bh[nt][1], bl[nt][1]);
            }
#pragma unroll
            for (int nt = 0; nt < 8; nt++) {
                mma16(acc[nt], ah, bh[nt]);
                mma16(acc[nt], ah, bl[nt]);
            }
        }
        __syncthreads();
    }

#pragma unroll
    for (int hrow = 0; hrow < 2; hrow++) {
        int m = m0 + wid * 16 + g + hrow * 8;
        long long rowo = cOff + (long long)m * ldc;
#pragma unroll
        for (int nt = 0; nt < 8; nt++) {
            int n = n0 + nt * 8 + 2 * t;
            if (n < N) {
                uint32_t hi, lo;
                split2(make_float2(acc[nt][hrow * 2], acc[nt][hrow * 2 + 1]), hi, lo);
                *(uint32_t*)(Ch + rowo + n) = hi;
                *(uint32_t*)(Cl + rowo + n) = lo;
            }
        }
    }
}

// --------------------------- conversion kernels -----------------------------
__global__ void convw_kernel(const float* __restrict__ W,
                             __half* __restrict__ hi, __half* __restrict__ lo,
                             int K, int N, int Npad, long long inS, long long outS)
{
    __shared__ float tile[32][65];
    int z = blockIdx.z;
    const float* Wz = W + (long long)z * inS;
    int k0 = blockIdx.y * 32, n0 = blockIdx.x * 64;
    int tid = threadIdx.x;

#pragma unroll
    for (int j = 0; j < 2; j++) {
        int idx = tid + (j << 8);
        int k = idx >> 4, nq = (idx & 15) << 2;
        int n = n0 + nq;
        float4 v = make_float4(0.f, 0.f, 0.f, 0.f);
        const float* p = Wz + (long long)(k0 + k) * N;
        if (n + 3 < N) v = *(const float4*)(p + n);
        else {
            if (n + 0 < N) v.x = p[n + 0];
            if (n + 1 < N) v.y = p[n + 1];
            if (n + 2 < N) v.z = p[n + 2];
            if (n + 3 < N) v.w = p[n + 3];
        }
        tile[k][nq + 0] = v.x; tile[k][nq + 1] = v.y;
        tile[k][nq + 2] = v.z; tile[k][nq + 3] = v.w;
    }
    __syncthreads();

#pragma unroll
    for (int j = 0; j < 4; j++) {
        int idx = tid + (j << 8);
        int n = idx >> 4, tq = (idx & 15) << 1;
        int gn = n0 + n;
        if (gn < Npad) {
            float v0 = tile[tq][n], v1 = tile[tq + 1][n];
            __half2 h = __floats2half2_rn(v0, v1);
            float2 hf = __half22float2(h);
            __half2 l = __floats2half2_rn(v0 - hf.x, v1 - hf.y);
            long long o = (long long)z * outS + (long long)gn * K + k0 + tq;
            *(__half2*)(hi + o) = h;
            *(__half2*)(lo + o) = l;
        }
    }
}

__global__ void convqkv_kernel(const float* __restrict__ Wq, const float* __restrict__ Wk,
                               const float* __restrict__ Wv,
                               __half* __restrict__ hi, __half* __restrict__ lo)
{
    __shared__ float tile[32][65];
    int kt = blockIdx.x, sh = blockIdx.y;
    int sel = sh >> 3, h = sh & 7;
    const float* W = (sel == 0) ? Wq : (sel == 1) ? Wk : Wv;
    const float* src = W + ((long long)h * 512 + kt * 32) * 64;
    int tid = threadIdx.x;

#pragma unroll
    for (int j = 0; j < 2; j++) {
        int idx = tid + (j << 8);
        int k = idx >> 4, eq = (idx & 15) << 2;
        float4 v = *(const float4*)(src + k * 64 + eq);
        tile[k][eq + 0] = v.x; tile[k][eq + 1] = v.y;
        tile[k][eq + 2] = v.z; tile[k][eq + 3] = v.w;
    }
    __syncthreads();

#pragma unroll
    for (int j = 0; j < 4; j++) {
        int idx = tid + (j << 8);
        int e = idx >> 4, tq = (idx & 15) << 1;
        int n = sel * 512 + h * 64 + e;
        float v0 = tile[tq][e], v1 = tile[tq + 1][e];
        __half2 hh = __floats2half2_rn(v0, v1);
        float2 hf = __half22float2(hh);
        __half2 ll = __floats2half2_rn(v0 - hf.x, v1 - hf.y);
        long long o = (long long)n * 512 + kt * 32 + tq;
        *(__half2*)(hi + o) = hh;
        *(__half2*)(lo + o) = ll;
    }
}

__global__ void conva_kernel(const float* __restrict__ src,
                             __half* __restrict__ hi, __half* __restrict__ lo, int n) {
    int i = blockIdx.x * 256 + threadIdx.x;
    if (i < n) {
        float v = src[i];
        __half h = __float2half_rn(v);
        hi[i] = h;
        lo[i] = __float2half_rn(v - __half2float(h));
    }
}

// --------------------------- elementwise kernels ---------------------------
__global__ void embed_kernel(const int* __restrict__ tok, const float* __restrict__ emb,
                             float* __restrict__ x,
                             __half* __restrict__ xh, __half* __restrict__ xl) {
    int idx = blockIdx.x * 256 + threadIdx.x;
    int t = tok[idx >> 9];
    float v = emb[(long long)t * Dm_ + (idx & 511)] * 8.0f;
    x[idx] = v;
    __half h = __float2half_rn(v);
    xh[idx] = h;
    xl[idx] = __float2half_rn(v - __half2float(h));
}

__global__ void bn_stats_kernel(const float* __restrict__ x,
                                float* __restrict__ mu, float* __restrict__ rstd) {
    int d = blockIdx.x * 32 + threadIdx.x;
    float s = 0.f, s2 = 0.f;
    for (int i = threadIdx.y; i < BS_; i += 8) {
        float v = x[(long long)i * Dm_ + d];
        s += v; s2 += v * v;
    }
    __shared__ float sh[8][33], sh2[8][33];
    sh[threadIdx.y][threadIdx.x] = s;
    sh2[threadIdx.y][threadIdx.x] = s2;
    __syncthreads();
    if (threadIdx.y == 0) {
#pragma unroll
        for (int r = 1; r < 8; r++) { s += sh[r][threadIdx.x]; s2 += sh2[r][threadIdx.x]; }
        float m = s * (1.f / BS_);
        float var = s2 * (1.f / BS_) - m * m;
        mu[d] = m;
        rstd[d] = rsqrtf(var + 1e-5f);
    }
}

__global__ void bn_apply_kernel(const float* __restrict__ xin, float* __restrict__ xout,
                                __half* __restrict__ xh, __half* __restrict__ xl,
                                const float* __restrict__ mu, const float* __restrict__ rstd,
                                const float* __restrict__ gamma, const float* __restrict__ beta) {
    int idx = blockIdx.x * 256 + threadIdx.x;
    int d = idx & 511;
    float v = (xin[idx] - mu[d]) * rstd[d] * gamma[d] + beta[d];
    xout[idx] = v;
    __half h = __float2half_rn(v);
    xh[idx] = h;
    xl[idx] = __float2half_rn(v - __half2float(h));
}

// Attention softmax, T=512: reads fp32 scores, writes fp16 probs (1 read).
__global__ __launch_bounds__(256) void softmax512_kernel(
    const float* __restrict__ p, __half* __restrict__ ph, int causal) {
    __shared__ float mred[256], sred[256];
    long long row = blockIdx.x;
    const float* x = p + row * 512;
    __half* y = ph + row * 512;
    int tid = threadIdx.x;
    int tmax = causal ? (int)(row & 511) : 511;
    int t0 = tid, t1 = tid + 256;

    float v0 = (t0 <= tmax) ? x[t0] : -1e30f;
    float v1 = (t1 <= tmax) ? x[t1] : -1e30f;
    mred[tid] = fmaxf(v0, v1);
    __syncthreads();
    for (int o = 128; o > 0; o >>= 1) {
        if (tid < o) mred[tid] = fmaxf(mred[tid], mred[tid + o]);
        __syncthreads();
    }
    float M = mred[0];
    float e0 = (t0 <= tmax) ? __expf(v0 - M) : 0.f;
    float e1 = (t1 <= tmax) ? __expf(v1 - M) : 0.f;
    sred[tid] = e0 + e1;
    __syncthreads();
    for (int o = 128; o > 0; o >>= 1) {
        if (tid < o) sred[tid] += sred[tid + o];
        __syncthreads();
    }
    float inv = 1.f / sred[0];
    y[t0] = __float2half_rn(e0 * inv);
    y[t1] = __float2half_rn(e1 * inv);
}

// Vocab softmax (register-resident, launch-bounded)
#define VITER 37
__global__ __launch_bounds__(1024, 1) void softmax_vocab_kernel(float* __restrict__ p, int T) {
    __shared__ float red[1024];
    long long row = blockIdx.x;
    float* x = p + row * (long long)T;
    int tid = threadIdx.x;

    float vals[VITER];
    float m = -1e30f;
#pragma unroll
    for (int j = 0; j < VITER; j++) {
        int t = tid + j * 1024;
        float v = (t < T) ? x[t] : -1e30f;
        vals[j] = v;
        m = fmaxf(m, v);
    }
    red[tid] = m; __syncthreads();
    for (int o = 512; o > 0; o >>= 1) {
        if (tid < o) red[tid] = fmaxf(red[tid], red[tid + o]);
        __syncthreads();
    }
    float M = red[0]; __syncthreads();

    float sum = 0.f;
#pragma unroll
    for (int j = 0; j < VITER; j++) {
        int t = tid + j * 1024;
        if (t < T) { vals[j] = __expf(vals[j] - M); sum += vals[j]; }
    }
    red[tid] = sum; __syncthreads();
    for (int o = 512; o > 0; o >>= 1) {
        if (tid < o) red[tid] += red[tid + o];
        __syncthreads();
    }
    float inv = 1.f / red[0];
#pragma unroll
    for (int j = 0; j < VITER; j++) {
        int t = tid + j * 1024;
        if (t < T) x[t] = vals[j] * inv;
    }
}

// ------------------------------- host side ---------------------------------
static inline int cdiv(int a, int b) { return (a + b - 1) / b; }

static void gh8(const __half* Ah, const __half* Al, const __half* Bh, const __half* Bl,
                float* C, __half* Ch, __half* Cl,
                const float* bias, const float* res,
                int M, int N, int K, int lda, int ldb, int ldc, int flags)
{
    dim3 g(cdiv(N, 128), M / 128, 1);
    gemm_h<8><<<g, 256, GH_SMEM8>>>(Ah, Al, Bh, Bl, C, Ch, Cl, bias, res,
                                    M, N, K, lda, ldb, ldc,
                                    0, 0, 1, 0, 0, 1, 0, 0, 1, 1.f, flags);
}
static void gh4(const __half* Ah, const __half* Al, const __half* Bh, const __half* Bl,
                float* C, __half* Ch, __half* Cl,
                const float* bias, const float* res,
                int M, int N, int K, int lda, int ldb, int ldc, int flags)
{
    dim3 g(cdiv(N, 64), M / 128, 1);
    gemm_h<4><<<g, 256, GH_SMEM4>>>(Ah, Al, Bh, Bl, C, Ch, Cl, bias, res,
                                    M, N, K, lda, ldb, ldc,
                                    0, 0, 1, 0, 0, 1, 0, 0, 1, 1.f, flags);
}

extern "C" void kernel_launch(void* const* d_in, const int* in_sizes, int n_in,
                              void* d_out, int out_size)
{
    const int*   tok   = (const int*)  d_in[0];
    const float* enc   = (const float*)d_in[1];
    const float* emb   = (const float*)d_in[2];
    const float* Wq1   = (const float*)d_in[3];
    const float* Wk1   = (const float*)d_in[4];
    const float* Wv1   = (const float*)d_in[5];
    const float* Wo1   = (const float*)d_in[6];
    const float* Wq2   = (const float*)d_in[7];
    const float* Wk2   = (const float*)d_in[8];
    const float* Wv2   = (const float*)d_in[9];
    const float* Wo2   = (const float*)d_in[10];
    const float* gamma = (const float*)d_in[11];
    const float* beta  = (const float*)d_in[12];
    const float* W1    = (const float*)d_in[13];
    const float* b1    = (const float*)d_in[14];
    const float* W2    = (const float*)d_in[15];
    const float* b2    = (const float*)d_in[16];
    const float* Wout  = (const float*)d_in[17];
    const float* bout  = (const float*)d_in[18];
    float* out = (float*)d_out;

    cudaFuncSetAttribute(gemm_h<8>, cudaFuncAttributeMaxDynamicSharedMemorySize, GH_SMEM8);
    cudaFuncSetAttribute(gemm_h<4>, cudaFuncAttributeMaxDynamicSharedMemorySize, GH_SMEM4);
    cudaFuncSetAttribute(gemm_av,   cudaFuncAttributeMaxDynamicSharedMemorySize, GEMM_SMEM_AV);

    float *x, *tmp, *qkv, *sc, *mu, *rstd;
    cudaGetSymbolAddress((void**)&x,    g_x);
    cudaGetSymbolAddress((void**)&tmp,  g_tmp);
    cudaGetSymbolAddress((void**)&qkv,  g_qkv);
    cudaGetSymbolAddress((void**)&sc,   g_sc);
    cudaGetSymbolAddress((void**)&mu,   g_mu);
    cudaGetSymbolAddress((void**)&rstd, g_rstd);

    __half *sph, *xh, *xl, *qkvh, *qkvl, *attnh, *attnl, *ffh, *ffl, *ench, *encl;
    cudaGetSymbolAddress((void**)&sph,   g_sph);
    cudaGetSymbolAddress((void**)&xh,    g_xh);
    cudaGetSymbolAddress((void**)&xl,    g_xl);
    cudaGetSymbolAddress((void**)&qkvh,  g_qkvh);
    cudaGetSymbolAddress((void**)&qkvl,  g_qkvl);
    cudaGetSymbolAddress((void**)&attnh, g_attnh);
    cudaGetSymbolAddress((void**)&attnl, g_attnl);
    cudaGetSymbolAddress((void**)&ffh,   g_ffh);
    cudaGetSymbolAddress((void**)&ffl,   g_ffl);
    cudaGetSymbolAddress((void**)&ench,  g_ench);
    cudaGetSymbolAddress((void**)&encl,  g_encl);

    __half *wtT_h, *wtT_l, *w1T_h, *w1T_l, *w2T_h, *w2T_l;
    __half *wo1T_h, *wo1T_l, *wo2T_h, *wo2T_l, *woutT_h, *woutT_l;
    cudaGetSymbolAddress((void**)&wtT_h,  g_wtT_h);
    cudaGetSymbolAddress((void**)&wtT_l,  g_wtT_l);
    cudaGetSymbolAddress((void**)&w1T_h,  g_w1T_h);
    cudaGetSymbolAddress((void**)&w1T_l,  g_w1T_l);
    cudaGetSymbolAddress((void**)&w2T_h,  g_w2T_h);
    cudaGetSymbolAddress((void**)&w2T_l,  g_w2T_l);
    cudaGetSymbolAddress((void**)&wo1T_h, g_wo1T_h);
    cudaGetSymbolAddress((void**)&wo1T_l, g_wo1T_l);
    cudaGetSymbolAddress((void**)&wo2T_h, g_wo2T_h);
    cudaGetSymbolAddress((void**)&wo2T_l, g_wo2T_l);
    cudaGetSymbolAddress((void**)&woutT_h, g_woutT_h);
    cudaGetSymbolAddress((void**)&woutT_l, g_woutT_l);

    const long long HW  = (long long)Dm_ * Dk_;
    const long long QBh = (long long)Ss_ * 1536;
    const long long SCZ = (long long)Ss_ * Ss_;
    const float     isq = 0.125f;

    // ---- early conversions + hoisted first QKV (puts a gemm_h at ncu slot 5)
    convqkv_kernel<<<dim3(16, 24), 256>>>(Wq1, Wk1, Wv1, wtT_h, wtT_l);      // s=0
    conva_kernel<<<cdiv(BS_*Dm_, 256), 256>>>(enc, ench, encl, BS_*Dm_);
    embed_kernel<<<BS_ * Dm_ / 256, 256>>>(tok, emb, x, xh, xl);
    convw_kernel<<<dim3(Ff_/64, Dm_/32, Nx_), 256>>>(W1, w1T_h, w1T_l, Dm_, Ff_, Ff_,
                                                     (long long)Dm_*Ff_, (long long)Ff_*Dm_);
    convw_kernel<<<dim3(Dm_/64, Ff_/32, Nx_), 256>>>(W2, w2T_h, w2T_l, Ff_, Dm_, Dm_,
                                                     (long long)Ff_*Dm_, (long long)Dm_*Ff_);
    // launch #5: layer-0 self QKV GEMM (profiled by ncu -s 5 -c 1)
    gh8(xh, xl, wtT_h, wtT_l, qkv, qkvh, qkvl, nullptr, nullptr,
        BS_, 1536, Dm_, Dm_, Dm_, 1536, 0);
    // remaining conversions
    for (int s = 1; s < 12; s++) {
        int i = s >> 1, pass = s & 1;
        const float* wq = pass ? Wq2 : Wq1;
        const float* wk = pass ? Wk2 : Wk1;
        const float* wv = pass ? Wv2 : Wv1;
        convqkv_kernel<<<dim3(16, 24), 256>>>(wq + (long long)i*Hh_*HW,
                                              wk + (long long)i*Hh_*HW,
                                              wv + (long long)i*Hh_*HW,
                                              wtT_h + (long long)s*1536*512,
                                              wtT_l + (long long)s*1536*512);
    }
    convw_kernel<<<dim3(Dm_/64, Dm_/32, Nx_), 256>>>(Wo1, wo1T_h, wo1T_l, Dm_, Dm_, Dm_,
                                                     (long long)Dm_*Dm_, (long long)Dm_*Dm_);
    convw_kernel<<<dim3(Dm_/64, Dm_/32, Nx_), 256>>>(Wo2, wo2T_h, wo2T_l, Dm_, Dm_, Dm_,
                                                     (long long)Dm_*Dm_, (long long)Dm_*Dm_);
    convw_kernel<<<dim3(VvP_/64, Dm_/32, 1), 256>>>(Wout, woutT_h, woutT_l, Dm_, Vv_, VvP_, 0, 0);

    for (int i = 0; i < Nx_; i++) {
        const float* bb1 = b1 + (long long)i * Ff_;
        const float* bb2 = b2 + (long long)i * Dm_;

        for (int attn_pass = 0; attn_pass < 2; attn_pass++) {
            const int self = (attn_pass == 0);
            const int s = i * 2 + attn_pass;
            const __half* wth = wtT_h + (long long)s * 1536 * 512;
            const __half* wtl = wtT_l + (long long)s * 1536 * 512;

            if (self) {
                if (i != 0)   // layer-0 self QKV already done (hoisted)
                    gh8(xh, xl, wth, wtl, qkv, qkvh, qkvl, nullptr, nullptr,
                        BS_, 1536, Dm_, Dm_, Dm_, 1536, 0);
            } else {
                gh4(xh, xl, wth, wtl, qkv, qkvh, qkvl, nullptr, nullptr,
                    BS_, 512, Dm_, Dm_, Dm_, 1536, 0);
                dim3 g(8, 16, 1);
                gemm_h<8><<<g, 256, GH_SMEM8>>>(ench, encl,
                                                wth + 512LL*512, wtl + 512LL*512,
                                                qkv + 512, qkvh + 512, qkvl + 512,
                                                nullptr, nullptr,
                                                BS_, 1024, Dm_, Dm_, Dm_, 1536,
                                                0, 0, 1, 0, 0, 1, 0, 0, 1, 1.f, 0);
            }
            // scores[z=b*8+h] = Q @ K^T * isq  (causal skip for self)
            {
                dim3 g(4, 4, Bb_ * Hh_);
                gemm_h<8><<<g, 256, GH_SMEM8>>>(qkvh, qkvl, qkvh + 512, qkvl + 512,
                                                sc, nullptr, nullptr, nullptr, nullptr,
                                                Ss_, Ss_, Dk_, 1536, 1536, Ss_,
                                                QBh, 64, Hh_,  QBh, 64, Hh_,  SCZ, 0, 1,
                                                isq, self ? 2 : 0);
            }
            softmax512_kernel<<<Bb_*Hh_*Ss_, 256>>>(sc, sph, self ? 1 : 0);
            // attn[b,s,h*64+e] = probs(half) @ V(fp32)
            {
                dim3 g(1, 4, Bb_ * Hh_);
                gemm_av<<<g, 256, GEMM_SMEM_AV>>>(sph, qkv + 1024, attnh, attnl,
                                                  Ss_, Dk_, Ss_, Ss_, 1536, Dm_,
                                                  SCZ,  QBh, 64, Hh_,
                                                  (long long)Ss_*Dm_, Dk_, Hh_,
                                                  self ? 1 : 0);
            }
            // tmp = attn @ Wo + x
            const __half* woh = (self ? wo1T_h : wo2T_h) + (long long)i*512*512;
            const __half* wol = (self ? wo1T_l : wo2T_l) + (long long)i*512*512;
            gh4(attnh, attnl, woh, wol, tmp, nullptr, nullptr, nullptr, x,
                BS_, Dm_, Dm_, Dm_, Dm_, Dm_, 0);
            bn_stats_kernel<<<Dm_/32, dim3(32, 8)>>>(tmp, mu, rstd);
            bn_apply_kernel<<<BS_*Dm_/256, 256>>>(tmp, x, xh, xl, mu, rstd,
                                                  gamma + (long long)(i*3 + attn_pass)*Dm_,
                                                  beta  + (long long)(i*3 + attn_pass)*Dm_);
        }

        // ---- feed-forward
        gh8(xh, xl, w1T_h + (long long)i*Ff_*512, w1T_l + (long long)i*Ff_*512,
            nullptr, ffh, ffl, bb1, nullptr, BS_, Ff_, Dm_, Dm_, Dm_, Ff_, 1);
        gh4(ffh, ffl, w2T_h + (long long)i*512LL*Ff_, w2T_l + (long long)i*512LL*Ff_,
            tmp, nullptr, nullptr, bb2, x, BS_, Dm_, Ff_, Ff_, Ff_, Dm_, 0);
        bn_stats_kernel<<<Dm_/32, dim3(32, 8)>>>(tmp, mu, rstd);
        bn_apply_kernel<<<BS_*Dm_/256, 256>>>(tmp, x, xh, xl, mu, rstd,
                                              gamma + (long long)(i*3 + 2)*Dm_,
                                              beta  + (long long)(i*3 + 2)*Dm_);
    }

    // ---- output projection + vocab softmax
    gh8(xh, xl, woutT_h, woutT_l, out, nullptr, nullptr, bout, nullptr,
        BS_, Vv_, Dm_, Dm_, Dm_, Vv_, 0);
    softmax_vocab_kernel<<<BS_, 1024>>>(out, Vv_);

    (void)in_sizes; (void)n_in; (void)out_size;
}

// round 13
// speedup vs baseline: 1.5335x; 1.0919x over previous
#include <cuda_runtime.h>
#include <cuda_fp16.h>
#include <math.h>
#include <stdint.h>

// ---------------------------------------------------------------------------
// Decoder — Round 13: 2-pass (no weight-lo) vocab GEMM via NOBL template
// ---------------------------------------------------------------------------

#define Bb_ 4
#define Ss_ 512
#define Dm_ 512
#define Hh_ 8
#define Dk_ 64
#define Ff_ 2048
#define Vv_ 37000
#define VvP_ 37120
#define Nx_ 6
#define BS_ 2048

// ------------------------- scratch (static device globals) -----------------
__device__ __align__(16) float g_x    [BS_*Dm_];
__device__ __align__(16) float g_tmp  [BS_*Dm_];
__device__ __align__(16) float g_qkv  [BS_*3*Dm_];     // fp32 (V read by AV gemm)
__device__ __align__(16) float g_sc   [Bb_*Hh_*Ss_*Ss_];     // fp32 scores
__device__ __align__(16) __half g_sph [Bb_*Hh_*Ss_*Ss_];     // fp16 probs
__device__ float g_mu   [Dm_];
__device__ float g_rstd [Dm_];

// hi/lo half activations
__device__ __align__(16) __half g_xh   [BS_*Dm_];
__device__ __align__(16) __half g_xl   [BS_*Dm_];
__device__ __align__(16) __half g_qkvh [BS_*3*Dm_];
__device__ __align__(16) __half g_qkvl [BS_*3*Dm_];
__device__ __align__(16) __half g_attnh[BS_*Dm_];
__device__ __align__(16) __half g_attnl[BS_*Dm_];
__device__ __align__(16) __half g_ffh  [BS_*Ff_];
__device__ __align__(16) __half g_ffl  [BS_*Ff_];
__device__ __align__(16) __half g_ench [BS_*Dm_];
__device__ __align__(16) __half g_encl [BS_*Dm_];

// hi/lo half weights, [N, K] K-major
__device__ __align__(16) __half g_wtT_h [12L*1536*512];
__device__ __align__(16) __half g_wtT_l [12L*1536*512];
__device__ __align__(16) __half g_w1T_h [6L*2048*512];
__device__ __align__(16) __half g_w1T_l [6L*2048*512];
__device__ __align__(16) __half g_w2T_h [6L*512*2048];
__device__ __align__(16) __half g_w2T_l [6L*512*2048];
__device__ __align__(16) __half g_wo1T_h[6L*512*512];
__device__ __align__(16) __half g_wo1T_l[6L*512*512];
__device__ __align__(16) __half g_wo2T_h[6L*512*512];
__device__ __align__(16) __half g_wo2T_l[6L*512*512];
__device__ __align__(16) __half g_woutT_h[(long long)VvP_*512];
__device__ __align__(16) __half g_woutT_l[(long long)VvP_*512];

// ------------------------------- helpers -----------------------------------
__device__ __forceinline__ void split2(float2 x, uint32_t& hi, uint32_t& lo) {
    __half2 h = __float22half2_rn(x);
    float2 hf = __half22float2(h);
    __half2 l = __float22half2_rn(make_float2(x.x - hf.x, x.y - hf.y));
    hi = *reinterpret_cast<uint32_t*>(&h);
    lo = *reinterpret_cast<uint32_t*>(&l);
}
__device__ __forceinline__ void cpasync16(uint32_t dst, const void* src) {
    asm volatile("cp.async.cg.shared.global [%0], [%1], 16;"
                 :: "r"(dst), "l"(src));
}
__device__ __forceinline__ void cpcommit() { asm volatile("cp.async.commit_group;"); }
template <int NN> __device__ __forceinline__ void cpwait() {
    asm volatile("cp.async.wait_group %0;" :: "n"(NN));
}
__device__ __forceinline__ void mma16(float* d, const uint32_t* a, const uint32_t* b) {
    asm volatile(
        "mma.sync.aligned.m16n8k16.row.col.f32.f16.f16.f32 "
        "{%0,%1,%2,%3}, {%4,%5,%6,%7}, {%8,%9}, {%0,%1,%2,%3};"
        : "+f"(d[0]), "+f"(d[1]), "+f"(d[2]), "+f"(d[3])
        : "r"(a[0]), "r"(a[1]), "r"(a[2]), "r"(a[3]), "r"(b[0]), "r"(b[1]));
}
__device__ __forceinline__ void ldsm4(uint32_t* r, uint32_t addr) {
    asm volatile("ldmatrix.sync.aligned.m8n8.x4.shared.b16 {%0,%1,%2,%3}, [%4];"
                 : "=r"(r[0]), "=r"(r[1]), "=r"(r[2]), "=r"(r[3]) : "r"(addr));
}

// 64B rows; chunk (16B) swizzle keeps ldmatrix 8-row phases conflict-free.
#define SWZ(row, cb) ((uint32_t)((cb) ^ ((((row) >> 1) & 3) << 4)))

// ------------------------ GEMM: pure-half operands --------------------------
// 3-stage cp.async pipeline, swizzled 64B-row smem, 1 barrier/tile.
// NOBL=1: skip weight-lo (no Bl staging, no ah*bl pass) — 2-pass mode.
#define AARR (128*64)                 // one A array: 8192 B

template <int NT, int NOBL>
__global__ __launch_bounds__(256) void gemm_h(
    const __half* __restrict__ Ah, const __half* __restrict__ Al,
    const __half* __restrict__ Bh, const __half* __restrict__ Bl,
    float* __restrict__ C, __half* __restrict__ Ch, __half* __restrict__ Cl,
    const float* __restrict__ bias, const float* __restrict__ res,
    int M, int N, int K, int lda, int ldb, int ldc,
    long long aS1, long long aS2, int aDiv,
    long long bS1, long long bS2, int bDiv,
    long long cS1, long long cS2, int cDiv,
    float alpha, int flags)
{
    constexpr int BN   = NT * 16;
    constexpr int BARR = BN * 64;
    constexpr int STG  = 2 * AARR + 2 * BARR;

    extern __shared__ char smh[];
    const int m0 = blockIdx.y * 128, n0 = blockIdx.x * BN;
    if ((flags & 2) && n0 >= m0 + 128) return;      // causal: fully-masked tile

    const int z = blockIdx.z;
    const long long aOff = (long long)(z / aDiv) * aS1 + (long long)(z % aDiv) * aS2;
    const long long bOff = (long long)(z / bDiv) * bS1 + (long long)(z % bDiv) * bS2;
    const long long cOff = (long long)(z / cDiv) * cS1 + (long long)(z % cDiv) * cS2;
    const __half* Ahb = Ah + aOff;
    const __half* Alb = Al + aOff;
    const __half* Bhb = Bh + bOff;
    const __half* Blb = Bl + bOff;

    const uint32_t sb = (uint32_t)__cvta_generic_to_shared(smh);
    const int tid = threadIdx.x;
    const int wid = tid >> 5, lane = tid & 31;
    const int wm = wid & 3, wn = wid >> 2;
    const int g = lane >> 2, t = lane & 3;

    const int aRow = lane & 15, aChk = lane >> 4;
    const int bRow = (lane & 7) + ((lane >> 4) << 3);
    const int bChk = (lane >> 3) & 1;

    uint32_t aBase[2], aXor[2];
#pragma unroll
    for (int mt = 0; mt < 2; mt++) {
        int r = wm * 32 + mt * 16 + aRow;
        aBase[mt] = (uint32_t)(r * 64);
        aXor[mt]  = (uint32_t)(((r >> 1) & 3) << 4);
    }
    uint32_t bBase[NT / 2], bXor[NT / 2];
#pragma unroll
    for (int p = 0; p < NT / 2; p++) {
        int r = wn * (NT * 8) + p * 16 + bRow;
        bBase[p] = (uint32_t)(r * 64);
        bXor[p]  = (uint32_t)(((r >> 1) & 3) << 4);
    }

    float acc[2][NT][4];
#pragma unroll
    for (int i = 0; i < 2; i++)
#pragma unroll
        for (int j = 0; j < NT; j++)
#pragma unroll
            for (int r = 0; r < 4; r++) acc[i][j][r] = 0.f;

    const int T = K >> 5;

    auto stage = [&](int it, int buf) {
        const int k0 = it << 5;
        uint32_t dst = sb + buf * STG;
#pragma unroll
        for (int j = 0; j < 2; j++) {
            int idx = tid + (j << 8);
            int row = idx >> 2, c = idx & 3;
            long long asrc = (long long)(m0 + row) * lda + k0 + c * 8;
            uint32_t so = (uint32_t)(row * 64) + SWZ(row, c * 16);
            cpasync16(dst + 0 * AARR + so, Ahb + asrc);
            cpasync16(dst + 1 * AARR + so, Alb + asrc);
        }
#pragma unroll
        for (int j = 0; j < NT / 4; j++) {
            int idx = tid + (j << 8);
            int row = idx >> 2, c = idx & 3;
            long long bsrc = (long long)(n0 + row) * ldb + k0 + c * 8;
            uint32_t so = (uint32_t)(row * 64) + SWZ(row, c * 16);
            cpasync16(dst + 2 * AARR + so, Bhb + bsrc);
            if (!NOBL) cpasync16(dst + 2 * AARR + BARR + so, Blb + bsrc);
        }
    };

    stage(0, 0); cpcommit();
    stage(1, 1); cpcommit();

    for (int it = 0; it < T; ++it) {
        if (it + 1 < T) cpwait<1>(); else cpwait<0>();
        __syncthreads();

        const uint32_t base = sb + (uint32_t)(it % 3) * STG;
        const uint32_t aHb0 = base + 0 * AARR;
        const uint32_t aLb0 = base + 1 * AARR;
        const uint32_t bHb0 = base + 2 * AARR;
        const uint32_t bLb0 = base + 2 * AARR + BARR;

#pragma unroll
        for (int kk = 0; kk < 2; kk++) {
            const uint32_t cbA = (uint32_t)(aChk * 16 + kk * 32);
            const uint32_t cbB = (uint32_t)(bChk * 16 + kk * 32);
            uint32_t ah[2][4], al[2][4];
#pragma unroll
            for (int mt = 0; mt < 2; mt++) {
                uint32_t off = aBase[mt] + (cbA ^ aXor[mt]);
                ldsm4(ah[mt], aHb0 + off);
                ldsm4(al[mt], aLb0 + off);
            }
            uint32_t bh[NT / 2][4], bl[NT / 2][4];
#pragma unroll
            for (int p = 0; p < NT / 2; p++) {
                uint32_t off = bBase[p] + (cbB ^ bXor[p]);
                ldsm4(bh[p], bHb0 + off);
                if (!NOBL) ldsm4(bl[p], bLb0 + off);
            }
#pragma unroll
            for (int mt = 0; mt < 2; mt++)
#pragma unroll
                for (int p = 0; p < NT / 2; p++) {
                    mma16(acc[mt][2*p],   ah[mt], &bh[p][0]);
                    mma16(acc[mt][2*p],   al[mt], &bh[p][0]);
                    if (!NOBL) mma16(acc[mt][2*p], ah[mt], &bl[p][0]);
                    mma16(acc[mt][2*p+1], ah[mt], &bh[p][2]);
                    mma16(acc[mt][2*p+1], al[mt], &bh[p][2]);
                    if (!NOBL) mma16(acc[mt][2*p+1], ah[mt], &bl[p][2]);
                }
        }

        if (it + 2 < T) { stage(it + 2, (it + 2) % 3); cpcommit(); }
    }

    const bool relu = flags & 1;
#pragma unroll
    for (int mt = 0; mt < 2; mt++) {
#pragma unroll
        for (int hrow = 0; hrow < 2; hrow++) {
            int m = m0 + wm * 32 + mt * 16 + g + hrow * 8;
            long long rowo = cOff + (long long)m * ldc;
#pragma unroll
            for (int nt = 0; nt < NT; nt++) {
                int n = n0 + wn * (NT * 8) + nt * 8 + 2 * t;
                if (n < N) {
                    float v0 = acc[mt][nt][hrow * 2 + 0] * alpha;
                    float v1 = acc[mt][nt][hrow * 2 + 1] * alpha;
                    if (bias) { v0 += bias[n]; v1 += bias[n + 1]; }
                    if (res) {
                        const float* rp = res + rowo;
                        v0 += rp[n]; v1 += rp[n + 1];
                    }
                    if (relu) { v0 = fmaxf(v0, 0.f); v1 = fmaxf(v1, 0.f); }
                    if (C) {
                        float2 vv; vv.x = v0; vv.y = v1;
                        *(float2*)(C + rowo + n) = vv;
                    }
                    if (Ch) {
                        uint32_t hi, lo;
                        split2(make_float2(v0, v1), hi, lo);
                        *(uint32_t*)(Ch + rowo + n) = hi;
                        *(uint32_t*)(Cl + rowo + n) = lo;
                    }
                }
            }
        }
    }
}

#define GH_SMEM8 (3 * (2 * AARR + 2 * 128 * 64))   // 98304
#define GH_SMEM4 (3 * (2 * AARR + 2 * 64 * 64))    // 73728

// -------------------- AV GEMM (half A=probs, fp32 B=[k][n]) -----------------
#define AV_ASTG 8192
#define AVBSTR 68
#define AVBSZ (32*AVBSTR)
#define GEMM_SMEM_AV (2*AV_ASTG + 2*AVBSZ*4)

__global__ __launch_bounds__(256) void gemm_av(
    const __half* __restrict__ A, const float* __restrict__ B,
    __half* __restrict__ Ch, __half* __restrict__ Cl,
    int M, int N, int K, int lda, int ldb, int ldc,
    long long aS1, long long bS1, long long bS2, int bDiv,
    long long cS1, long long cS2, int cDiv,
    int causalLim)
{
    extern __shared__ char smav[];
    const int z = blockIdx.z;
    const __half* Ab  = A + (long long)z * aS1;
    const float*  Bbp = B + (long long)(z / bDiv) * bS1 + (long long)(z % bDiv) * bS2;
    const long long cOff = (long long)(z / cDiv) * cS1 + (long long)(z % cDiv) * cS2;

    const uint32_t asA = (uint32_t)__cvta_generic_to_shared(smav);
    float* Bs = (float*)(smav + 2 * AV_ASTG);
    const uint32_t asB = (uint32_t)__cvta_generic_to_shared(Bs);

    const int tid  = threadIdx.x;
    const int wid  = tid >> 5, lane = tid & 31;
    const int g    = lane >> 2, t   = lane & 3;
    const int m0   = blockIdx.y * 128, n0 = blockIdx.x * 64;

    const int aRow = lane & 15, aChk = lane >> 4;
    const uint32_t aBase = (uint32_t)((wid * 16 + aRow) * 64);
    const uint32_t aXor  = (uint32_t)((((wid * 16 + aRow) >> 1) & 3) << 4);

    float acc[8][4];
#pragma unroll
    for (int j = 0; j < 8; j++)
#pragma unroll
        for (int r = 0; r < 4; r++) acc[j][r] = 0.f;

    const int Keff  = causalLim ? ((m0 + 128 < K) ? m0 + 128 : K) : K;
    const int nIter = Keff >> 5;

    auto doCopy = [&](int it, int buf) {
        const int k0 = it << 5;
#pragma unroll
        for (int j = 0; j < 2; j++) {
            int i   = tid + (j << 8);
            int row = i >> 2, c = i & 3;
            const __half* src = Ab + (long long)(m0 + row) * lda + k0 + c * 8;
            cpasync16(asA + (uint32_t)(buf * AV_ASTG + row * 64) + SWZ(row, c * 16), src);
        }
#pragma unroll
        for (int j = 0; j < 2; j++) {
            int i  = tid + (j << 8);
            int kr = i >> 4, nc = (i & 15) << 2;
            const float* src = Bbp + (long long)(k0 + kr) * ldb + n0 + nc;
            cpasync16(asB + (uint32_t)((buf * AVBSZ + kr * AVBSTR + nc) << 2), src);
        }
    };

    doCopy(0, 0); cpcommit();

    for (int it = 0; it < nIter; ++it) {
        const int cur = it & 1;
        if (it + 1 < nIter) { doCopy(it + 1, cur ^ 1); cpcommit(); cpwait<1>(); }
        else                { cpwait<0>(); }
        __syncthreads();

        const uint32_t aCur = asA + (uint32_t)(cur * AV_ASTG);
        const float* pb = Bs + cur * AVBSZ;

#pragma unroll
        for (int kk = 0; kk < 2; kk++) {
            uint32_t ah[4];
            ldsm4(ah, aCur + aBase + (((uint32_t)(aChk * 16 + kk * 32)) ^ aXor));
            uint32_t bh[8][2], bl[8][2];
#pragma unroll
            for (int nt = 0; nt < 8; nt++) {
                int nc = nt * 8 + g;
                const float* base = pb + (long long)(kk * 16 + 2 * t) * AVBSTR + nc;
                float2 y0 = make_float2(base[0], base[AVBSTR]);
                float2 y1 = make_float2(base[8 * AVBSTR], base[9 * AVBSTR]);
                split2(y0, bh[nt][0], bl[nt][0]);
                split2(y1, bh[nt][1], bl[nt][1]);
            }
#pragma unroll
            for (int nt = 0; nt < 8; nt++) {
                mma16(acc[nt], ah, bh[nt]);
                mma16(acc[nt], ah, bl[nt]);
            }
        }
        __syncthreads();
    }

#pragma unroll
    for (int hrow = 0; hrow < 2; hrow++) {
        int m = m0 + wid * 16 + g + hrow * 8;
        long long rowo = cOff + (long long)m * ldc;
#pragma unroll
        for (int nt = 0; nt < 8; nt++) {
            int n = n0 + nt * 8 + 2 * t;
            if (n < N) {
                uint32_t hi, lo;
                split2(make_float2(acc[nt][hrow * 2], acc[nt][hrow * 2 + 1]), hi, lo);
                *(uint32_t*)(Ch + rowo + n) = hi;
                *(uint32_t*)(Cl + rowo + n) = lo;
            }
        }
    }
}

// --------------------------- conversion kernels -----------------------------
__global__ void convw_kernel(const float* __restrict__ W,
                             __half* __restrict__ hi, __half* __restrict__ lo,
                             int K, int N, int Npad, long long inS, long long outS)
{
    __shared__ float tile[32][65];
    int z = blockIdx.z;
    const float* Wz = W + (long long)z * inS;
    int k0 = blockIdx.y * 32, n0 = blockIdx.x * 64;
    int tid = threadIdx.x;

#pragma unroll
    for (int j = 0; j < 2; j++) {
        int idx = tid + (j << 8);
        int k = idx >> 4, nq = (idx & 15) << 2;
        int n = n0 + nq;
        float4 v = make_float4(0.f, 0.f, 0.f, 0.f);
        const float* p = Wz + (long long)(k0 + k) * N;
        if (n + 3 < N) v = *(const float4*)(p + n);
        else {
            if (n + 0 < N) v.x = p[n + 0];
            if (n + 1 < N) v.y = p[n + 1];
            if (n + 2 < N) v.z = p[n + 2];
            if (n + 3 < N) v.w = p[n + 3];
        }
        tile[k][nq + 0] = v.x; tile[k][nq + 1] = v.y;
        tile[k][nq + 2] = v.z; tile[k][nq + 3] = v.w;
    }
    __syncthreads();

#pragma unroll
    for (int j = 0; j < 4; j++) {
        int idx = tid + (j << 8);
        int n = idx >> 4, tq = (idx & 15) << 1;
        int gn = n0 + n;
        if (gn < Npad) {
            float v0 = tile[tq][n], v1 = tile[tq + 1][n];
            __half2 h = __floats2half2_rn(v0, v1);
            float2 hf = __half22float2(h);
            __half2 l = __floats2half2_rn(v0 - hf.x, v1 - hf.y);
            long long o = (long long)z * outS + (long long)gn * K + k0 + tq;
            *(__half2*)(hi + o) = h;
            *(__half2*)(lo + o) = l;
        }
    }
}

__global__ void convqkv_kernel(const float* __restrict__ Wq, const float* __restrict__ Wk,
                               const float* __restrict__ Wv,
                               __half* __restrict__ hi, __half* __restrict__ lo)
{
    __shared__ float tile[32][65];
    int kt = blockIdx.x, sh = blockIdx.y;
    int sel = sh >> 3, h = sh & 7;
    const float* W = (sel == 0) ? Wq : (sel == 1) ? Wk : Wv;
    const float* src = W + ((long long)h * 512 + kt * 32) * 64;
    int tid = threadIdx.x;

#pragma unroll
    for (int j = 0; j < 2; j++) {
        int idx = tid + (j << 8);
        int k = idx >> 4, eq = (idx & 15) << 2;
        float4 v = *(const float4*)(src + k * 64 + eq);
        tile[k][eq + 0] = v.x; tile[k][eq + 1] = v.y;
        tile[k][eq + 2] = v.z; tile[k][eq + 3] = v.w;
    }
    __syncthreads();

#pragma unroll
    for (int j = 0; j < 4; j++) {
        int idx = tid + (j << 8);
        int e = idx >> 4, tq = (idx & 15) << 1;
        int n = sel * 512 + h * 64 + e;
        float v0 = tile[tq][e], v1 = tile[tq + 1][e];
        __half2 hh = __floats2half2_rn(v0, v1);
        float2 hf = __half22float2(hh);
        __half2 ll = __floats2half2_rn(v0 - hf.x, v1 - hf.y);
        long long o = (long long)n * 512 + kt * 32 + tq;
        *(__half2*)(hi + o) = hh;
        *(__half2*)(lo + o) = ll;
    }
}

__global__ void conva_kernel(const float* __restrict__ src,
                             __half* __restrict__ hi, __half* __restrict__ lo, int n) {
    int i = blockIdx.x * 256 + threadIdx.x;
    if (i < n) {
        float v = src[i];
        __half h = __float2half_rn(v);
        hi[i] = h;
        lo[i] = __float2half_rn(v - __half2float(h));
    }
}

// --------------------------- elementwise kernels ---------------------------
__global__ void embed_kernel(const int* __restrict__ tok, const float* __restrict__ emb,
                             float* __restrict__ x,
                             __half* __restrict__ xh, __half* __restrict__ xl) {
    int idx = blockIdx.x * 256 + threadIdx.x;
    int t = tok[idx >> 9];
    float v = emb[(long long)t * Dm_ + (idx & 511)] * 8.0f;
    x[idx] = v;
    __half h = __float2half_rn(v);
    xh[idx] = h;
    xl[idx] = __float2half_rn(v - __half2float(h));
}

__global__ void bn_stats_kernel(const float* __restrict__ x,
                                float* __restrict__ mu, float* __restrict__ rstd) {
    int d = blockIdx.x * 32 + threadIdx.x;
    float s = 0.f, s2 = 0.f;
    for (int i = threadIdx.y; i < BS_; i += 8) {
        float v = x[(long long)i * Dm_ + d];
        s += v; s2 += v * v;
    }
    __shared__ float sh[8][33], sh2[8][33];
    sh[threadIdx.y][threadIdx.x] = s;
    sh2[threadIdx.y][threadIdx.x] = s2;
    __syncthreads();
    if (threadIdx.y == 0) {
#pragma unroll
        for (int r = 1; r < 8; r++) { s += sh[r][threadIdx.x]; s2 += sh2[r][threadIdx.x]; }
        float m = s * (1.f / BS_);
        float var = s2 * (1.f / BS_) - m * m;
        mu[d] = m;
        rstd[d] = rsqrtf(var + 1e-5f);
    }
}

__global__ void bn_apply_kernel(const float* __restrict__ xin, float* __restrict__ xout,
                                __half* __restrict__ xh, __half* __restrict__ xl,
                                const float* __restrict__ mu, const float* __restrict__ rstd,
                                const float* __restrict__ gamma, const float* __restrict__ beta) {
    int idx = blockIdx.x * 256 + threadIdx.x;
    int d = idx & 511;
    float v = (xin[idx] - mu[d]) * rstd[d] * gamma[d] + beta[d];
    xout[idx] = v;
    __half h = __float2half_rn(v);
    xh[idx] = h;
    xl[idx] = __float2half_rn(v - __half2float(h));
}

// Attention softmax, T=512: reads fp32 scores, writes fp16 probs (1 read).
__global__ __launch_bounds__(256) void softmax512_kernel(
    const float* __restrict__ p, __half* __restrict__ ph, int causal) {
    __shared__ float mred[256], sred[256];
    long long row = blockIdx.x;
    const float* x = p + row * 512;
    __half* y = ph + row * 512;
    int tid = threadIdx.x;
    int tmax = causal ? (int)(row & 511) : 511;
    int t0 = tid, t1 = tid + 256;

    float v0 = (t0 <= tmax) ? x[t0] : -1e30f;
    float v1 = (t1 <= tmax) ? x[t1] : -1e30f;
    mred[tid] = fmaxf(v0, v1);
    __syncthreads();
    for (int o = 128; o > 0; o >>= 1) {
        if (tid < o) mred[tid] = fmaxf(mred[tid], mred[tid + o]);
        __syncthreads();
    }
    float M = mred[0];
    float e0 = (t0 <= tmax) ? __expf(v0 - M) : 0.f;
    float e1 = (t1 <= tmax) ? __expf(v1 - M) : 0.f;
    sred[tid] = e0 + e1;
    __syncthreads();
    for (int o = 128; o > 0; o >>= 1) {
        if (tid < o) sred[tid] += sred[tid + o];
        __syncthreads();
    }
    float inv = 1.f / sred[0];
    y[t0] = __float2half_rn(e0 * inv);
    y[t1] = __float2half_rn(e1 * inv);
}

// Vocab softmax (register-resident, launch-bounded)
#define VITER 37
__global__ __launch_bounds__(1024, 1) void softmax_vocab_kernel(float* __restrict__ p, int T) {
    __shared__ float red[1024];
    long long row = blockIdx.x;
    float* x = p + row * (long long)T;
    int tid = threadIdx.x;

    float vals[VITER];
    float m = -1e30f;
#pragma unroll
    for (int j = 0; j < VITER; j++) {
        int t = tid + j * 1024;
        float v = (t < T) ? x[t] : -1e30f;
        vals[j] = v;
        m = fmaxf(m, v);
    }
    red[tid] = m; __syncthreads();
    for (int o = 512; o > 0; o >>= 1) {
        if (tid < o) red[tid] = fmaxf(red[tid], red[tid + o]);
        __syncthreads();
    }
    float M = red[0]; __syncthreads();

    float sum = 0.f;
#pragma unroll
    for (int j = 0; j < VITER; j++) {
        int t = tid + j * 1024;
        if (t < T) { vals[j] = __expf(vals[j] - M); sum += vals[j]; }
    }
    red[tid] = sum; __syncthreads();
    for (int o = 512; o > 0; o >>= 1) {
        if (tid < o) red[tid] += red[tid + o];
        __syncthreads();
    }
    float inv = 1.f / red[0];
#pragma unroll
    for (int j = 0; j < VITER; j++) {
        int t = tid + j * 1024;
        if (t < T) x[t] = vals[j] * inv;
    }
}

// ------------------------------- host side ---------------------------------
static inline int cdiv(int a, int b) { return (a + b - 1) / b; }

static void gh8(const __half* Ah, const __half* Al, const __half* Bh, const __half* Bl,
                float* C, __half* Ch, __half* Cl,
                const float* bias, const float* res,
                int M, int N, int K, int lda, int ldb, int ldc, int flags)
{
    dim3 g(cdiv(N, 128), M / 128, 1);
    gemm_h<8,0><<<g, 256, GH_SMEM8>>>(Ah, Al, Bh, Bl, C, Ch, Cl, bias, res,
                                      M, N, K, lda, ldb, ldc,
                                      0, 0, 1, 0, 0, 1, 0, 0, 1, 1.f, flags);
}
static void gh4(const __half* Ah, const __half* Al, const __half* Bh, const __half* Bl,
                float* C, __half* Ch, __half* Cl,
                const float* bias, const float* res,
                int M, int N, int K, int lda, int ldb, int ldc, int flags)
{
    dim3 g(cdiv(N, 64), M / 128, 1);
    gemm_h<4,0><<<g, 256, GH_SMEM4>>>(Ah, Al, Bh, Bl, C, Ch, Cl, bias, res,
                                      M, N, K, lda, ldb, ldc,
                                      0, 0, 1, 0, 0, 1, 0, 0, 1, 1.f, flags);
}

extern "C" void kernel_launch(void* const* d_in, const int* in_sizes, int n_in,
                              void* d_out, int out_size)
{
    const int*   tok   = (const int*)  d_in[0];
    const float* enc   = (const float*)d_in[1];
    const float* emb   = (const float*)d_in[2];
    const float* Wq1   = (const float*)d_in[3];
    const float* Wk1   = (const float*)d_in[4];
    const float* Wv1   = (const float*)d_in[5];
    const float* Wo1   = (const float*)d_in[6];
    const float* Wq2   = (const float*)d_in[7];
    const float* Wk2   = (const float*)d_in[8];
    const float* Wv2   = (const float*)d_in[9];
    const float* Wo2   = (const float*)d_in[10];
    const float* gamma = (const float*)d_in[11];
    const float* beta  = (const float*)d_in[12];
    const float* W1    = (const float*)d_in[13];
    const float* b1    = (const float*)d_in[14];
    const float* W2    = (const float*)d_in[15];
    const float* b2    = (const float*)d_in[16];
    const float* Wout  = (const float*)d_in[17];
    const float* bout  = (const float*)d_in[18];
    float* out = (float*)d_out;

    cudaFuncSetAttribute(gemm_h<8,0>, cudaFuncAttributeMaxDynamicSharedMemorySize, GH_SMEM8);
    cudaFuncSetAttribute(gemm_h<8,1>, cudaFuncAttributeMaxDynamicSharedMemorySize, GH_SMEM8);
    cudaFuncSetAttribute(gemm_h<4,0>, cudaFuncAttributeMaxDynamicSharedMemorySize, GH_SMEM4);
    cudaFuncSetAttribute(gemm_av,     cudaFuncAttributeMaxDynamicSharedMemorySize, GEMM_SMEM_AV);

    float *x, *tmp, *qkv, *sc, *mu, *rstd;
    cudaGetSymbolAddress((void**)&x,    g_x);
    cudaGetSymbolAddress((void**)&tmp,  g_tmp);
    cudaGetSymbolAddress((void**)&qkv,  g_qkv);
    cudaGetSymbolAddress((void**)&sc,   g_sc);
    cudaGetSymbolAddress((void**)&mu,   g_mu);
    cudaGetSymbolAddress((void**)&rstd, g_rstd);

    __half *sph, *xh, *xl, *qkvh, *qkvl, *attnh, *attnl, *ffh, *ffl, *ench, *encl;
    cudaGetSymbolAddress((void**)&sph,   g_sph);
    cudaGetSymbolAddress((void**)&xh,    g_xh);
    cudaGetSymbolAddress((void**)&xl,    g_xl);
    cudaGetSymbolAddress((void**)&qkvh,  g_qkvh);
    cudaGetSymbolAddress((void**)&qkvl,  g_qkvl);
    cudaGetSymbolAddress((void**)&attnh, g_attnh);
    cudaGetSymbolAddress((void**)&attnl, g_attnl);
    cudaGetSymbolAddress((void**)&ffh,   g_ffh);
    cudaGetSymbolAddress((void**)&ffl,   g_ffl);
    cudaGetSymbolAddress((void**)&ench,  g_ench);
    cudaGetSymbolAddress((void**)&encl,  g_encl);

    __half *wtT_h, *wtT_l, *w1T_h, *w1T_l, *w2T_h, *w2T_l;
    __half *wo1T_h, *wo1T_l, *wo2T_h, *wo2T_l, *woutT_h, *woutT_l;
    cudaGetSymbolAddress((void**)&wtT_h,  g_wtT_h);
    cudaGetSymbolAddress((void**)&wtT_l,  g_wtT_l);
    cudaGetSymbolAddress((void**)&w1T_h,  g_w1T_h);
    cudaGetSymbolAddress((void**)&w1T_l,  g_w1T_l);
    cudaGetSymbolAddress((void**)&w2T_h,  g_w2T_h);
    cudaGetSymbolAddress((void**)&w2T_l,  g_w2T_l);
    cudaGetSymbolAddress((void**)&wo1T_h, g_wo1T_h);
    cudaGetSymbolAddress((void**)&wo1T_l, g_wo1T_l);
    cudaGetSymbolAddress((void**)&wo2T_h, g_wo2T_h);
    cudaGetSymbolAddress((void**)&wo2T_l, g_wo2T_l);
    cudaGetSymbolAddress((void**)&woutT_h, g_woutT_h);
    cudaGetSymbolAddress((void**)&woutT_l, g_woutT_l);

    const long long HW  = (long long)Dm_ * Dk_;
    const long long QBh = (long long)Ss_ * 1536;
    const long long SCZ = (long long)Ss_ * Ss_;
    const float     isq = 0.125f;

    // ---- conversions (Wout lo no longer needed, but convw writes both; keep)
    convqkv_kernel<<<dim3(16, 24), 256>>>(Wq1, Wk1, Wv1, wtT_h, wtT_l);
    conva_kernel<<<cdiv(BS_*Dm_, 256), 256>>>(enc, ench, encl, BS_*Dm_);
    embed_kernel<<<BS_ * Dm_ / 256, 256>>>(tok, emb, x, xh, xl);
    convw_kernel<<<dim3(Ff_/64, Dm_/32, Nx_), 256>>>(W1, w1T_h, w1T_l, Dm_, Ff_, Ff_,
                                                     (long long)Dm_*Ff_, (long long)Ff_*Dm_);
    convw_kernel<<<dim3(Dm_/64, Ff_/32, Nx_), 256>>>(W2, w2T_h, w2T_l, Ff_, Dm_, Dm_,
                                                     (long long)Ff_*Dm_, (long long)Dm_*Ff_);
    gh8(xh, xl, wtT_h, wtT_l, qkv, qkvh, qkvl, nullptr, nullptr,
        BS_, 1536, Dm_, Dm_, Dm_, 1536, 0);
    for (int s = 1; s < 12; s++) {
        int i = s >> 1, pass = s & 1;
        const float* wq = pass ? Wq2 : Wq1;
        const float* wk = pass ? Wk2 : Wk1;
        const float* wv = pass ? Wv2 : Wv1;
        convqkv_kernel<<<dim3(16, 24), 256>>>(wq + (long long)i*Hh_*HW,
                                              wk + (long long)i*Hh_*HW,
                                              wv + (long long)i*Hh_*HW,
                                              wtT_h + (long long)s*1536*512,
                                              wtT_l + (long long)s*1536*512);
    }
    convw_kernel<<<dim3(Dm_/64, Dm_/32, Nx_), 256>>>(Wo1, wo1T_h, wo1T_l, Dm_, Dm_, Dm_,
                                                     (long long)Dm_*Dm_, (long long)Dm_*Dm_);
    convw_kernel<<<dim3(Dm_/64, Dm_/32, Nx_), 256>>>(Wo2, wo2T_h, wo2T_l, Dm_, Dm_, Dm_,
                                                     (long long)Dm_*Dm_, (long long)Dm_*Dm_);
    convw_kernel<<<dim3(VvP_/64, Dm_/32, 1), 256>>>(Wout, woutT_h, woutT_l, Dm_, Vv_, VvP_, 0, 0);

    for (int i = 0; i < Nx_; i++) {
        const float* bb1 = b1 + (long long)i * Ff_;
        const float* bb2 = b2 + (long long)i * Dm_;

        for (int attn_pass = 0; attn_pass < 2; attn_pass++) {
            const int self = (attn_pass == 0);
            const int s = i * 2 + attn_pass;
            const __half* wth = wtT_h + (long long)s * 1536 * 512;
            const __half* wtl = wtT_l + (long long)s * 1536 * 512;

            if (self) {
                if (i != 0)
                    gh8(xh, xl, wth, wtl, qkv, qkvh, qkvl, nullptr, nullptr,
                        BS_, 1536, Dm_, Dm_, Dm_, 1536, 0);
            } else {
                gh4(xh, xl, wth, wtl, qkv, qkvh, qkvl, nullptr, nullptr,
                    BS_, 512, Dm_, Dm_, Dm_, 1536, 0);
                dim3 g(8, 16, 1);
                gemm_h<8,0><<<g, 256, GH_SMEM8>>>(ench, encl,
                                                  wth + 512LL*512, wtl + 512LL*512,
                                                  qkv + 512, qkvh + 512, qkvl + 512,
                                                  nullptr, nullptr,
                                                  BS_, 1024, Dm_, Dm_, Dm_, 1536,
                                                  0, 0, 1, 0, 0, 1, 0, 0, 1, 1.f, 0);
            }
            // scores[z=b*8+h] = Q @ K^T * isq  (causal skip for self)
            {
                dim3 g(4, 4, Bb_ * Hh_);
                gemm_h<8,0><<<g, 256, GH_SMEM8>>>(qkvh, qkvl, qkvh + 512, qkvl + 512,
                                                  sc, nullptr, nullptr, nullptr, nullptr,
                                                  Ss_, Ss_, Dk_, 1536, 1536, Ss_,
                                                  QBh, 64, Hh_,  QBh, 64, Hh_,  SCZ, 0, 1,
                                                  isq, self ? 2 : 0);
            }
            softmax512_kernel<<<Bb_*Hh_*Ss_, 256>>>(sc, sph, self ? 1 : 0);
            // attn = probs(half) @ V(fp32)
            {
                dim3 g(1, 4, Bb_ * Hh_);
                gemm_av<<<g, 256, GEMM_SMEM_AV>>>(sph, qkv + 1024, attnh, attnl,
                                                  Ss_, Dk_, Ss_, Ss_, 1536, Dm_,
                                                  SCZ,  QBh, 64, Hh_,
                                                  (long long)Ss_*Dm_, Dk_, Hh_,
                                                  self ? 1 : 0);
            }
            // tmp = attn @ Wo + x
            const __half* woh = (self ? wo1T_h : wo2T_h) + (long long)i*512*512;
            const __half* wol = (self ? wo1T_l : wo2T_l) + (long long)i*512*512;
            gh4(attnh, attnl, woh, wol, tmp, nullptr, nullptr, nullptr, x,
                BS_, Dm_, Dm_, Dm_, Dm_, Dm_, 0);
            bn_stats_kernel<<<Dm_/32, dim3(32, 8)>>>(tmp, mu, rstd);
            bn_apply_kernel<<<BS_*Dm_/256, 256>>>(tmp, x, xh, xl, mu, rstd,
                                                  gamma + (long long)(i*3 + attn_pass)*Dm_,
                                                  beta  + (long long)(i*3 + attn_pass)*Dm_);
        }

        // ---- feed-forward
        gh8(xh, xl, w1T_h + (long long)i*Ff_*512, w1T_l + (long long)i*Ff_*512,
            nullptr, ffh, ffl, bb1, nullptr, BS_, Ff_, Dm_, Dm_, Dm_, Ff_, 1);
        gh4(ffh, ffl, w2T_h + (long long)i*512LL*Ff_, w2T_l + (long long)i*512LL*Ff_,
            tmp, nullptr, nullptr, bb2, x, BS_, Dm_, Ff_, Ff_, Ff_, Dm_, 0);
        bn_stats_kernel<<<Dm_/32, dim3(32, 8)>>>(tmp, mu, rstd);
        bn_apply_kernel<<<BS_*Dm_/256, 256>>>(tmp, x, xh, xl, mu, rstd,
                                              gamma + (long long)(i*3 + 2)*Dm_,
                                              beta  + (long long)(i*3 + 2)*Dm_);
    }

    // ---- output projection (2-pass: weight-lo dropped) + vocab softmax
    {
        dim3 g(cdiv(Vv_, 128), BS_ / 128, 1);
        gemm_h<8,1><<<g, 256, GH_SMEM8>>>(xh, xl, woutT_h, woutT_l,
                                          out, nullptr, nullptr, bout, nullptr,
                                          BS_, Vv_, Dm_, Dm_, Dm_, Vv_,
                                          0, 0, 1, 0, 0, 1, 0, 0, 1, 1.f, 0);
    }
    softmax_vocab_kernel<<<BS_, 1024>>>(out, Vv_);

    (void)in_sizes; (void)n_in; (void)out_size;
}

// round 14
// speedup vs baseline: 1.8404x; 1.2001x over previous
#include <cuda_runtime.h>
#include <cuda_fp16.h>
#include <math.h>
#include <stdint.h>

// ---------------------------------------------------------------------------
// Decoder — Round 14: fused flash-style attention (QK^T + softmax + PV)
// ---------------------------------------------------------------------------

#define Bb_ 4
#define Ss_ 512
#define Dm_ 512
#define Hh_ 8
#define Dk_ 64
#define Ff_ 2048
#define Vv_ 37000
#define VvP_ 37120
#define Nx_ 6
#define BS_ 2048

// ------------------------- scratch (static device globals) -----------------
__device__ __align__(16) float g_x    [BS_*Dm_];
__device__ __align__(16) float g_tmp  [BS_*Dm_];
__device__ __align__(16) float g_qkv  [BS_*3*Dm_];     // fp32 (V read by fused attn)
__device__ float g_mu   [Dm_];
__device__ float g_rstd [Dm_];

// hi/lo half activations
__device__ __align__(16) __half g_xh   [BS_*Dm_];
__device__ __align__(16) __half g_xl   [BS_*Dm_];
__device__ __align__(16) __half g_qkvh [BS_*3*Dm_];
__device__ __align__(16) __half g_qkvl [BS_*3*Dm_];
__device__ __align__(16) __half g_attnh[BS_*Dm_];
__device__ __align__(16) __half g_attnl[BS_*Dm_];
__device__ __align__(16) __half g_ffh  [BS_*Ff_];
__device__ __align__(16) __half g_ffl  [BS_*Ff_];
__device__ __align__(16) __half g_ench [BS_*Dm_];
__device__ __align__(16) __half g_encl [BS_*Dm_];

// hi/lo half weights, [N, K] K-major
__device__ __align__(16) __half g_wtT_h [12L*1536*512];
__device__ __align__(16) __half g_wtT_l [12L*1536*512];
__device__ __align__(16) __half g_w1T_h [6L*2048*512];
__device__ __align__(16) __half g_w1T_l [6L*2048*512];
__device__ __align__(16) __half g_w2T_h [6L*512*2048];
__device__ __align__(16) __half g_w2T_l [6L*512*2048];
__device__ __align__(16) __half g_wo1T_h[6L*512*512];
__device__ __align__(16) __half g_wo1T_l[6L*512*512];
__device__ __align__(16) __half g_wo2T_h[6L*512*512];
__device__ __align__(16) __half g_wo2T_l[6L*512*512];
__device__ __align__(16) __half g_woutT_h[(long long)VvP_*512];
__device__ __align__(16) __half g_woutT_l[(long long)VvP_*512];

// ------------------------------- helpers -----------------------------------
__device__ __forceinline__ void split2(float2 x, uint32_t& hi, uint32_t& lo) {
    __half2 h = __float22half2_rn(x);
    float2 hf = __half22float2(h);
    __half2 l = __float22half2_rn(make_float2(x.x - hf.x, x.y - hf.y));
    hi = *reinterpret_cast<uint32_t*>(&h);
    lo = *reinterpret_cast<uint32_t*>(&l);
}
__device__ __forceinline__ void cpasync16(uint32_t dst, const void* src) {
    asm volatile("cp.async.cg.shared.global [%0], [%1], 16;"
                 :: "r"(dst), "l"(src));
}
__device__ __forceinline__ void cpcommit() { asm volatile("cp.async.commit_group;"); }
template <int NN> __device__ __forceinline__ void cpwait() {
    asm volatile("cp.async.wait_group %0;" :: "n"(NN));
}
__device__ __forceinline__ void mma16(float* d, const uint32_t* a, const uint32_t* b) {
    asm volatile(
        "mma.sync.aligned.m16n8k16.row.col.f32.f16.f16.f32 "
        "{%0,%1,%2,%3}, {%4,%5,%6,%7}, {%8,%9}, {%0,%1,%2,%3};"
        : "+f"(d[0]), "+f"(d[1]), "+f"(d[2]), "+f"(d[3])
        : "r"(a[0]), "r"(a[1]), "r"(a[2]), "r"(a[3]), "r"(b[0]), "r"(b[1]));
}
__device__ __forceinline__ void ldsm4(uint32_t* r, uint32_t addr) {
    asm volatile("ldmatrix.sync.aligned.m8n8.x4.shared.b16 {%0,%1,%2,%3}, [%4];"
                 : "=r"(r[0]), "=r"(r[1]), "=r"(r[2]), "=r"(r[3]) : "r"(addr));
}

// 64B rows (32 halves): 16B-chunk swizzle for ldmatrix conflict-freedom.
#define SWZ(row, cb) ((uint32_t)((cb) ^ ((((row) >> 1) & 3) << 4)))
// 128B rows (64 halves): chunk index XOR row&7 (8 distinct slots per phase).
#define SWZ128(row, c) ((uint32_t)(16 * ((c) ^ ((row) & 7))))

// ------------------------ GEMM: pure-half operands --------------------------
// 3-stage cp.async pipeline, swizzled 64B-row smem, 1 barrier/tile.
// NOBL=1: skip weight-lo — 2-pass mode (vocab only).
#define AARR (128*64)

template <int NT, int NOBL>
__global__ __launch_bounds__(256) void gemm_h(
    const __half* __restrict__ Ah, const __half* __restrict__ Al,
    const __half* __restrict__ Bh, const __half* __restrict__ Bl,
    float* __restrict__ C, __half* __restrict__ Ch, __half* __restrict__ Cl,
    const float* __restrict__ bias, const float* __restrict__ res,
    int M, int N, int K, int lda, int ldb, int ldc,
    long long aS1, long long aS2, int aDiv,
    long long bS1, long long bS2, int bDiv,
    long long cS1, long long cS2, int cDiv,
    float alpha, int flags)
{
    constexpr int BN   = NT * 16;
    constexpr int BARR = BN * 64;
    constexpr int STG  = 2 * AARR + 2 * BARR;

    extern __shared__ char smh[];
    const int m0 = blockIdx.y * 128, n0 = blockIdx.x * BN;
    if ((flags & 2) && n0 >= m0 + 128) return;

    const int z = blockIdx.z;
    const long long aOff = (long long)(z / aDiv) * aS1 + (long long)(z % aDiv) * aS2;
    const long long bOff = (long long)(z / bDiv) * bS1 + (long long)(z % bDiv) * bS2;
    const long long cOff = (long long)(z / cDiv) * cS1 + (long long)(z % cDiv) * cS2;
    const __half* Ahb = Ah + aOff;
    const __half* Alb = Al + aOff;
    const __half* Bhb = Bh + bOff;
    const __half* Blb = Bl + bOff;

    const uint32_t sb = (uint32_t)__cvta_generic_to_shared(smh);
    const int tid = threadIdx.x;
    const int wid = tid >> 5, lane = tid & 31;
    const int wm = wid & 3, wn = wid >> 2;
    const int g = lane >> 2, t = lane & 3;

    const int aRow = lane & 15, aChk = lane >> 4;
    const int bRow = (lane & 7) + ((lane >> 4) << 3);
    const int bChk = (lane >> 3) & 1;

    uint32_t aBase[2], aXor[2];
#pragma unroll
    for (int mt = 0; mt < 2; mt++) {
        int r = wm * 32 + mt * 16 + aRow;
        aBase[mt] = (uint32_t)(r * 64);
        aXor[mt]  = (uint32_t)(((r >> 1) & 3) << 4);
    }
    uint32_t bBase[NT / 2], bXor[NT / 2];
#pragma unroll
    for (int p = 0; p < NT / 2; p++) {
        int r = wn * (NT * 8) + p * 16 + bRow;
        bBase[p] = (uint32_t)(r * 64);
        bXor[p]  = (uint32_t)(((r >> 1) & 3) << 4);
    }

    float acc[2][NT][4];
#pragma unroll
    for (int i = 0; i < 2; i++)
#pragma unroll
        for (int j = 0; j < NT; j++)
#pragma unroll
            for (int r = 0; r < 4; r++) acc[i][j][r] = 0.f;

    const int T = K >> 5;

    auto stage = [&](int it, int buf) {
        const int k0 = it << 5;
        uint32_t dst = sb + buf * STG;
#pragma unroll
        for (int j = 0; j < 2; j++) {
            int idx = tid + (j << 8);
            int row = idx >> 2, c = idx & 3;
            long long asrc = (long long)(m0 + row) * lda + k0 + c * 8;
            uint32_t so = (uint32_t)(row * 64) + SWZ(row, c * 16);
            cpasync16(dst + 0 * AARR + so, Ahb + asrc);
            cpasync16(dst + 1 * AARR + so, Alb + asrc);
        }
#pragma unroll
        for (int j = 0; j < NT / 4; j++) {
            int idx = tid + (j << 8);
            int row = idx >> 2, c = idx & 3;
            long long bsrc = (long long)(n0 + row) * ldb + k0 + c * 8;
            uint32_t so = (uint32_t)(row * 64) + SWZ(row, c * 16);
            cpasync16(dst + 2 * AARR + so, Bhb + bsrc);
            if (!NOBL) cpasync16(dst + 2 * AARR + BARR + so, Blb + bsrc);
        }
    };

    stage(0, 0); cpcommit();
    stage(1, 1); cpcommit();

    for (int it = 0; it < T; ++it) {
        if (it + 1 < T) cpwait<1>(); else cpwait<0>();
        __syncthreads();

        const uint32_t base = sb + (uint32_t)(it % 3) * STG;
        const uint32_t aHb0 = base + 0 * AARR;
        const uint32_t aLb0 = base + 1 * AARR;
        const uint32_t bHb0 = base + 2 * AARR;
        const uint32_t bLb0 = base + 2 * AARR + BARR;

#pragma unroll
        for (int kk = 0; kk < 2; kk++) {
            const uint32_t cbA = (uint32_t)(aChk * 16 + kk * 32);
            const uint32_t cbB = (uint32_t)(bChk * 16 + kk * 32);
            uint32_t ah[2][4], al[2][4];
#pragma unroll
            for (int mt = 0; mt < 2; mt++) {
                uint32_t off = aBase[mt] + (cbA ^ aXor[mt]);
                ldsm4(ah[mt], aHb0 + off);
                ldsm4(al[mt], aLb0 + off);
            }
            uint32_t bh[NT / 2][4], bl[NT / 2][4];
#pragma unroll
            for (int p = 0; p < NT / 2; p++) {
                uint32_t off = bBase[p] + (cbB ^ bXor[p]);
                ldsm4(bh[p], bHb0 + off);
                if (!NOBL) ldsm4(bl[p], bLb0 + off);
            }
#pragma unroll
            for (int mt = 0; mt < 2; mt++)
#pragma unroll
                for (int p = 0; p < NT / 2; p++) {
                    mma16(acc[mt][2*p],   ah[mt], &bh[p][0]);
                    mma16(acc[mt][2*p],   al[mt], &bh[p][0]);
                    if (!NOBL) mma16(acc[mt][2*p], ah[mt], &bl[p][0]);
                    mma16(acc[mt][2*p+1], ah[mt], &bh[p][2]);
                    mma16(acc[mt][2*p+1], al[mt], &bh[p][2]);
                    if (!NOBL) mma16(acc[mt][2*p+1], ah[mt], &bl[p][2]);
                }
        }

        if (it + 2 < T) { stage(it + 2, (it + 2) % 3); cpcommit(); }
    }

    const bool relu = flags & 1;
#pragma unroll
    for (int mt = 0; mt < 2; mt++) {
#pragma unroll
        for (int hrow = 0; hrow < 2; hrow++) {
            int m = m0 + wm * 32 + mt * 16 + g + hrow * 8;
            long long rowo = cOff + (long long)m * ldc;
#pragma unroll
            for (int nt = 0; nt < NT; nt++) {
                int n = n0 + wn * (NT * 8) + nt * 8 + 2 * t;
                if (n < N) {
                    float v0 = acc[mt][nt][hrow * 2 + 0] * alpha;
                    float v1 = acc[mt][nt][hrow * 2 + 1] * alpha;
                    if (bias) { v0 += bias[n]; v1 += bias[n + 1]; }
                    if (res) {
                        const float* rp = res + rowo;
                        v0 += rp[n]; v1 += rp[n + 1];
                    }
                    if (relu) { v0 = fmaxf(v0, 0.f); v1 = fmaxf(v1, 0.f); }
                    if (C) {
                        float2 vv; vv.x = v0; vv.y = v1;
                        *(float2*)(C + rowo + n) = vv;
                    }
                    if (Ch) {
                        uint32_t hi, lo;
                        split2(make_float2(v0, v1), hi, lo);
                        *(uint32_t*)(Ch + rowo + n) = hi;
                        *(uint32_t*)(Cl + rowo + n) = lo;
                    }
                }
            }
        }
    }
}

#define GH_SMEM8 (3 * (2 * AARR + 2 * 128 * 64))   // 98304
#define GH_SMEM4 (3 * (2 * AARR + 2 * 64 * 64))    // 73728

// ------------------- fused flash attention ---------------------------------
// grid (4 m-tiles, 1, 32 bh), 256 thr = 8 warps x 16 rows. Q frags resident;
// K (halves, 128B swizzled rows) + V (fp32, stride-68) double buffered.
// 3-pass QK^T, fp32 online softmax, fp16 P (in-register repack), 2-pass P@V.
#define FA_QH 0
#define FA_QL 16384
#define FA_K0 32768            // per stage: Kh 16384 + Kl 16384
#define FA_V0 98304            // per stage: 128*68*4 = 34816
#define FA_SMEM 167936

__global__ __launch_bounds__(256, 1) void fused_attn(
    const __half* __restrict__ qkvh, const __half* __restrict__ qkvl,
    const float* __restrict__ qkv,
    __half* __restrict__ Ch, __half* __restrict__ Cl,
    int causal)
{
    extern __shared__ char smf[];
    const uint32_t sb = (uint32_t)__cvta_generic_to_shared(smf);
    const int z = blockIdx.z;
    const int b = z >> 3, h = z & 7;
    const int mt = blockIdx.x;
    const int m0 = mt * 128;
    const long long tokb = (long long)b * 512;
    const int tid = threadIdx.x, wid = tid >> 5, lane = tid & 31;
    const int g = lane >> 2, t = lane & 3;
    const int aRow = lane & 15, aChk = lane >> 4;
    const int bRow = (lane & 7) + ((lane >> 4) << 3);
    const int bChk = (lane >> 3) & 1;

    // ---- stage Q (group 0) ----
#pragma unroll
    for (int j = 0; j < 4; j++) {
        int idx = tid + (j << 8);
        int r = idx >> 3, c = idx & 7;
        long long src = (tokb + m0 + r) * 1536 + h * 64 + c * 8;
        uint32_t so = (uint32_t)(r * 128) + SWZ128(r, c);
        cpasync16(sb + FA_QH + so, qkvh + src);
        cpasync16(sb + FA_QL + so, qkvl + src);
    }
    cpcommit();

    auto stageKV = [&](int kt, int buf) {
        uint32_t kdst = sb + FA_K0 + (uint32_t)buf * 32768u;
#pragma unroll
        for (int j = 0; j < 4; j++) {
            int idx = tid + (j << 8);
            int r = idx >> 3, c = idx & 7;
            long long src = (tokb + kt * 128 + r) * 1536 + 512 + h * 64 + c * 8;
            uint32_t so = (uint32_t)(r * 128) + SWZ128(r, c);
            cpasync16(kdst + so, qkvh + src);
            cpasync16(kdst + 16384 + so, qkvl + src);
        }
        uint32_t vdst = sb + FA_V0 + (uint32_t)buf * 34816u;
#pragma unroll
        for (int j = 0; j < 8; j++) {
            int idx = tid + (j << 8);
            int r = idx >> 4, c = idx & 15;
            long long src = (tokb + kt * 128 + r) * 1536 + 1024 + h * 64 + c * 4;
            cpasync16(vdst + (uint32_t)((r * 68 + c * 4) * 4), qkv + src);
        }
    };

    stageKV(0, 0); cpcommit();

    // ---- Q fragments (wait group0; stage0 may still be in flight) ----
    cpwait<1>();
    __syncthreads();
    uint32_t qh[4][4], ql[4][4];
    {
        int r = wid * 16 + aRow;
        uint32_t qb = (uint32_t)(r * 128);
#pragma unroll
        for (int kc = 0; kc < 4; kc++) {
            uint32_t cb = SWZ128(r, kc * 2 + aChk);
            ldsm4(qh[kc], sb + FA_QH + qb + cb);
            ldsm4(ql[kc], sb + FA_QL + qb + cb);
        }
    }

    float accO[8][4];
#pragma unroll
    for (int nt = 0; nt < 8; nt++)
#pragma unroll
        for (int r = 0; r < 4; r++) accO[nt][r] = 0.f;
    float Mg = -1e30f, Mg8 = -1e30f, Lg = 0.f, Lg8 = 0.f;

    const int jmax = causal ? (mt + 1) : 4;

    for (int j = 0; j < jmax; j++) {
        if (j + 1 < jmax) { stageKV(j + 1, (j + 1) & 1); cpcommit(); cpwait<1>(); }
        else              { cpwait<0>(); }
        __syncthreads();

        const uint32_t kb = sb + FA_K0 + (uint32_t)(j & 1) * 32768u;
        const float* Vb = (const float*)(smf + FA_V0 + (size_t)(j & 1) * 34816u);

        // ---- S = (Q K^T) * isq  (3-pass) ----
        float s[16][4];
#pragma unroll
        for (int nt = 0; nt < 16; nt++)
#pragma unroll
            for (int r = 0; r < 4; r++) s[nt][r] = 0.f;

#pragma unroll
        for (int kc = 0; kc < 4; kc++) {
#pragma unroll
            for (int p = 0; p < 8; p++) {
                int r = p * 16 + bRow;
                uint32_t off = (uint32_t)(r * 128) + SWZ128(r, kc * 2 + bChk);
                uint32_t bh4[4], bl4[4];
                ldsm4(bh4, kb + off);
                ldsm4(bl4, kb + 16384 + off);
                mma16(s[2*p],   qh[kc], &bh4[0]);
                mma16(s[2*p],   ql[kc], &bh4[0]);
                mma16(s[2*p],   qh[kc], &bl4[0]);
                mma16(s[2*p+1], qh[kc], &bh4[2]);
                mma16(s[2*p+1], ql[kc], &bh4[2]);
                mma16(s[2*p+1], qh[kc], &bl4[2]);
            }
        }
#pragma unroll
        for (int nt = 0; nt < 16; nt++)
#pragma unroll
            for (int r = 0; r < 4; r++) s[nt][r] *= 0.125f;

        if (causal && j == mt) {
            int rg = m0 + wid * 16 + g;
#pragma unroll
            for (int nt = 0; nt < 16; nt++) {
                int cb0 = j * 128 + nt * 8 + 2 * t;
                if (cb0     > rg)     s[nt][0] = -1e30f;
                if (cb0 + 1 > rg)     s[nt][1] = -1e30f;
                if (cb0     > rg + 8) s[nt][2] = -1e30f;
                if (cb0 + 1 > rg + 8) s[nt][3] = -1e30f;
            }
        }

        // ---- online softmax update ----
        float mg = -1e30f, mg8 = -1e30f;
#pragma unroll
        for (int nt = 0; nt < 16; nt++) {
            mg  = fmaxf(mg,  fmaxf(s[nt][0], s[nt][1]));
            mg8 = fmaxf(mg8, fmaxf(s[nt][2], s[nt][3]));
        }
        mg  = fmaxf(mg,  __shfl_xor_sync(0xffffffff, mg, 1));
        mg  = fmaxf(mg,  __shfl_xor_sync(0xffffffff, mg, 2));
        mg8 = fmaxf(mg8, __shfl_xor_sync(0xffffffff, mg8, 1));
        mg8 = fmaxf(mg8, __shfl_xor_sync(0xffffffff, mg8, 2));
        float Mn  = fmaxf(Mg,  mg);
        float Mn8 = fmaxf(Mg8, mg8);
        float f  = __expf(Mg  - Mn);
        float f8 = __expf(Mg8 - Mn8);
        Mg = Mn; Mg8 = Mn8;
        Lg *= f; Lg8 *= f8;
#pragma unroll
        for (int nt = 0; nt < 8; nt++) {
            accO[nt][0] *= f;  accO[nt][1] *= f;
            accO[nt][2] *= f8; accO[nt][3] *= f8;
        }

        // ---- P (fp16 A-fragments, in-register repack) ----
        uint32_t pa[8][4];
#pragma unroll
        for (int kc2 = 0; kc2 < 8; kc2++) {
            float p00 = __expf(s[2*kc2][0]   - Mg);
            float p01 = __expf(s[2*kc2][1]   - Mg);
            float p02 = __expf(s[2*kc2][2]   - Mg8);
            float p03 = __expf(s[2*kc2][3]   - Mg8);
            float p10 = __expf(s[2*kc2+1][0] - Mg);
            float p11 = __expf(s[2*kc2+1][1] - Mg);
            float p12 = __expf(s[2*kc2+1][2] - Mg8);
            float p13 = __expf(s[2*kc2+1][3] - Mg8);
            Lg  += p00 + p01 + p10 + p11;
            Lg8 += p02 + p03 + p12 + p13;
            __half2 h0 = __floats2half2_rn(p00, p01);
            __half2 h1 = __floats2half2_rn(p02, p03);
            __half2 h2v = __floats2half2_rn(p10, p11);
            __half2 h3 = __floats2half2_rn(p12, p13);
            pa[kc2][0] = *(uint32_t*)&h0;     // rows g,   k 0-7
            pa[kc2][1] = *(uint32_t*)&h1;     // rows g+8, k 0-7
            pa[kc2][2] = *(uint32_t*)&h2v;    // rows g,   k 8-15
            pa[kc2][3] = *(uint32_t*)&h3;     // rows g+8, k 8-15
        }

        // ---- O += P @ V  (V fp32, split in loop, 2-pass) ----
#pragma unroll
        for (int kc2 = 0; kc2 < 8; kc2++) {
#pragma unroll
            for (int nt = 0; nt < 8; nt++) {
                const float* base = Vb + (kc2 * 16 + 2 * t) * 68 + nt * 8 + g;
                uint32_t bh0, bl0, bh1, bl1;
                split2(make_float2(base[0],      base[68]),     bh0, bl0);
                split2(make_float2(base[8 * 68], base[9 * 68]), bh1, bl1);
                uint32_t bv[2]  = { bh0, bh1 };
                uint32_t bv2[2] = { bl0, bl1 };
                mma16(accO[nt], pa[kc2], bv);
                mma16(accO[nt], pa[kc2], bv2);
            }
        }
        __syncthreads();
    }

    // ---- epilogue: normalize + write halves ----
    Lg  += __shfl_xor_sync(0xffffffff, Lg, 1);
    Lg  += __shfl_xor_sync(0xffffffff, Lg, 2);
    Lg8 += __shfl_xor_sync(0xffffffff, Lg8, 1);
    Lg8 += __shfl_xor_sync(0xffffffff, Lg8, 2);
    float invg  = 1.f / Lg;
    float invg8 = 1.f / Lg8;

    long long row0 = (tokb + m0 + wid * 16 + g) * 512 + h * 64;
    long long row8 = row0 + 8LL * 512;
#pragma unroll
    for (int nt = 0; nt < 8; nt++) {
        int n = nt * 8 + 2 * t;
        uint32_t hi, lo;
        split2(make_float2(accO[nt][0] * invg, accO[nt][1] * invg), hi, lo);
        *(uint32_t*)(Ch + row0 + n) = hi;
        *(uint32_t*)(Cl + row0 + n) = lo;
        split2(make_float2(accO[nt][2] * invg8, accO[nt][3] * invg8), hi, lo);
        *(uint32_t*)(Ch + row8 + n) = hi;
        *(uint32_t*)(Cl + row8 + n) = lo;
    }
}

// --------------------------- conversion kernels -----------------------------
__global__ void convw_kernel(const float* __restrict__ W,
                             __half* __restrict__ hi, __half* __restrict__ lo,
                             int K, int N, int Npad, long long inS, long long outS)
{
    __shared__ float tile[32][65];
    int z = blockIdx.z;
    const float* Wz = W + (long long)z * inS;
    int k0 = blockIdx.y * 32, n0 = blockIdx.x * 64;
    int tid = threadIdx.x;

#pragma unroll
    for (int j = 0; j < 2; j++) {
        int idx = tid + (j << 8);
        int k = idx >> 4, nq = (idx & 15) << 2;
        int n = n0 + nq;
        float4 v = make_float4(0.f, 0.f, 0.f, 0.f);
        const float* p = Wz + (long long)(k0 + k) * N;
        if (n + 3 < N) v = *(const float4*)(p + n);
        else {
            if (n + 0 < N) v.x = p[n + 0];
            if (n + 1 < N) v.y = p[n + 1];
            if (n + 2 < N) v.z = p[n + 2];
            if (n + 3 < N) v.w = p[n + 3];
        }
        tile[k][nq + 0] = v.x; tile[k][nq + 1] = v.y;
        tile[k][nq + 2] = v.z; tile[k][nq + 3] = v.w;
    }
    __syncthreads();

#pragma unroll
    for (int j = 0; j < 4; j++) {
        int idx = tid + (j << 8);
        int n = idx >> 4, tq = (idx & 15) << 1;
        int gn = n0 + n;
        if (gn < Npad) {
            float v0 = tile[tq][n], v1 = tile[tq + 1][n];
            __half2 h = __floats2half2_rn(v0, v1);
            float2 hf = __half22float2(h);
            __half2 l = __floats2half2_rn(v0 - hf.x, v1 - hf.y);
            long long o = (long long)z * outS + (long long)gn * K + k0 + tq;
            *(__half2*)(hi + o) = h;
            *(__half2*)(lo + o) = l;
        }
    }
}

__global__ void convqkv_kernel(const float* __restrict__ Wq, const float* __restrict__ Wk,
                               const float* __restrict__ Wv,
                               __half* __restrict__ hi, __half* __restrict__ lo)
{
    __shared__ float tile[32][65];
    int kt = blockIdx.x, sh = blockIdx.y;
    int sel = sh >> 3, h = sh & 7;
    const float* W = (sel == 0) ? Wq : (sel == 1) ? Wk : Wv;
    const float* src = W + ((long long)h * 512 + kt * 32) * 64;
    int tid = threadIdx.x;

#pragma unroll
    for (int j = 0; j < 2; j++) {
        int idx = tid + (j << 8);
        int k = idx >> 4, eq = (idx & 15) << 2;
        float4 v = *(const float4*)(src + k * 64 + eq);
        tile[k][eq + 0] = v.x; tile[k][eq + 1] = v.y;
        tile[k][eq + 2] = v.z; tile[k][eq + 3] = v.w;
    }
    __syncthreads();

#pragma unroll
    for (int j = 0; j < 4; j++) {
        int idx = tid + (j << 8);
        int e = idx >> 4, tq = (idx & 15) << 1;
        int n = sel * 512 + h * 64 + e;
        float v0 = tile[tq][e], v1 = tile[tq + 1][e];
        __half2 hh = __floats2half2_rn(v0, v1);
        float2 hf = __half22float2(hh);
        __half2 ll = __floats2half2_rn(v0 - hf.x, v1 - hf.y);
        long long o = (long long)n * 512 + kt * 32 + tq;
        *(__half2*)(hi + o) = hh;
        *(__half2*)(lo + o) = ll;
    }
}

__global__ void conva_kernel(const float* __restrict__ src,
                             __half* __restrict__ hi, __half* __restrict__ lo, int n) {
    int i = blockIdx.x * 256 + threadIdx.x;
    if (i < n) {
        float v = src[i];
        __half h = __float2half_rn(v);
        hi[i] = h;
        lo[i] = __float2half_rn(v - __half2float(h));
    }
}

// --------------------------- elementwise kernels ---------------------------
__global__ void embed_kernel(const int* __restrict__ tok, const float* __restrict__ emb,
                             float* __restrict__ x,
                             __half* __restrict__ xh, __half* __restrict__ xl) {
    int idx = blockIdx.x * 256 + threadIdx.x;
    int t = tok[idx >> 9];
    float v = emb[(long long)t * Dm_ + (idx & 511)] * 8.0f;
    x[idx] = v;
    __half h = __float2half_rn(v);
    xh[idx] = h;
    xl[idx] = __float2half_rn(v - __half2float(h));
}

__global__ void bn_stats_kernel(const float* __restrict__ x,
                                float* __restrict__ mu, float* __restrict__ rstd) {
    int d = blockIdx.x * 32 + threadIdx.x;
    float s = 0.f, s2 = 0.f;
    for (int i = threadIdx.y; i < BS_; i += 8) {
        float v = x[(long long)i * Dm_ + d];
        s += v; s2 += v * v;
    }
    __shared__ float sh[8][33], sh2[8][33];
    sh[threadIdx.y][threadIdx.x] = s;
    sh2[threadIdx.y][threadIdx.x] = s2;
    __syncthreads();
    if (threadIdx.y == 0) {
#pragma unroll
        for (int r = 1; r < 8; r++) { s += sh[r][threadIdx.x]; s2 += sh2[r][threadIdx.x]; }
        float m = s * (1.f / BS_);
        float var = s2 * (1.f / BS_) - m * m;
        mu[d] = m;
        rstd[d] = rsqrtf(var + 1e-5f);
    }
}

__global__ void bn_apply_kernel(const float* __restrict__ xin, float* __restrict__ xout,
                                __half* __restrict__ xh, __half* __restrict__ xl,
                                const float* __restrict__ mu, const float* __restrict__ rstd,
                                const float* __restrict__ gamma, const float* __restrict__ beta) {
    int idx = blockIdx.x * 256 + threadIdx.x;
    int d = idx & 511;
    float v = (xin[idx] - mu[d]) * rstd[d] * gamma[d] + beta[d];
    xout[idx] = v;
    __half h = __float2half_rn(v);
    xh[idx] = h;
    xl[idx] = __float2half_rn(v - __half2float(h));
}

// Vocab softmax (register-resident, launch-bounded)
#define VITER 37
__global__ __launch_bounds__(1024, 1) void softmax_vocab_kernel(float* __restrict__ p, int T) {
    __shared__ float red[1024];
    long long row = blockIdx.x;
    float* x = p + row * (long long)T;
    int tid = threadIdx.x;

    float vals[VITER];
    float m = -1e30f;
#pragma unroll
    for (int j = 0; j < VITER; j++) {
        int t = tid + j * 1024;
        float v = (t < T) ? x[t] : -1e30f;
        vals[j] = v;
        m = fmaxf(m, v);
    }
    red[tid] = m; __syncthreads();
    for (int o = 512; o > 0; o >>= 1) {
        if (tid < o) red[tid] = fmaxf(red[tid], red[tid + o]);
        __syncthreads();
    }
    float M = red[0]; __syncthreads();

    float sum = 0.f;
#pragma unroll
    for (int j = 0; j < VITER; j++) {
        int t = tid + j * 1024;
        if (t < T) { vals[j] = __expf(vals[j] - M); sum += vals[j]; }
    }
    red[tid] = sum; __syncthreads();
    for (int o = 512; o > 0; o >>= 1) {
        if (tid < o) red[tid] += red[tid + o];
        __syncthreads();
    }
    float inv = 1.f / red[0];
#pragma unroll
    for (int j = 0; j < VITER; j++) {
        int t = tid + j * 1024;
        if (t < T) x[t] = vals[j] * inv;
    }
}

// ------------------------------- host side ---------------------------------
static inline int cdiv(int a, int b) { return (a + b - 1) / b; }

static void gh8(const __half* Ah, const __half* Al, const __half* Bh, const __half* Bl,
                float* C, __half* Ch, __half* Cl,
                const float* bias, const float* res,
                int M, int N, int K, int lda, int ldb, int ldc, int flags)
{
    dim3 g(cdiv(N, 128), M / 128, 1);
    gemm_h<8,0><<<g, 256, GH_SMEM8>>>(Ah, Al, Bh, Bl, C, Ch, Cl, bias, res,
                                      M, N, K, lda, ldb, ldc,
                                      0, 0, 1, 0, 0, 1, 0, 0, 1, 1.f, flags);
}
static void gh4(const __half* Ah, const __half* Al, const __half* Bh, const __half* Bl,
                float* C, __half* Ch, __half* Cl,
                const float* bias, const float* res,
                int M, int N, int K, int lda, int ldb, int ldc, int flags)
{
    dim3 g(cdiv(N, 64), M / 128, 1);
    gemm_h<4,0><<<g, 256, GH_SMEM4>>>(Ah, Al, Bh, Bl, C, Ch, Cl, bias, res,
                                      M, N, K, lda, ldb, ldc,
                                      0, 0, 1, 0, 0, 1, 0, 0, 1, 1.f, flags);
}

extern "C" void kernel_launch(void* const* d_in, const int* in_sizes, int n_in,
                              void* d_out, int out_size)
{
    const int*   tok   = (const int*)  d_in[0];
    const float* enc   = (const float*)d_in[1];
    const float* emb   = (const float*)d_in[2];
    const float* Wq1   = (const float*)d_in[3];
    const float* Wk1   = (const float*)d_in[4];
    const float* Wv1   = (const float*)d_in[5];
    const float* Wo1   = (const float*)d_in[6];
    const float* Wq2   = (const float*)d_in[7];
    const float* Wk2   = (const float*)d_in[8];
    const float* Wv2   = (const float*)d_in[9];
    const float* Wo2   = (const float*)d_in[10];
    const float* gamma = (const float*)d_in[11];
    const float* beta  = (const float*)d_in[12];
    const float* W1    = (const float*)d_in[13];
    const float* b1    = (const float*)d_in[14];
    const float* W2    = (const float*)d_in[15];
    const float* b2    = (const float*)d_in[16];
    const float* Wout  = (const float*)d_in[17];
    const float* bout  = (const float*)d_in[18];
    float* out = (float*)d_out;

    cudaFuncSetAttribute(gemm_h<8,0>, cudaFuncAttributeMaxDynamicSharedMemorySize, GH_SMEM8);
    cudaFuncSetAttribute(gemm_h<8,1>, cudaFuncAttributeMaxDynamicSharedMemorySize, GH_SMEM8);
    cudaFuncSetAttribute(gemm_h<4,0>, cudaFuncAttributeMaxDynamicSharedMemorySize, GH_SMEM4);
    cudaFuncSetAttribute(fused_attn,  cudaFuncAttributeMaxDynamicSharedMemorySize, FA_SMEM);

    float *x, *tmp, *qkv, *mu, *rstd;
    cudaGetSymbolAddress((void**)&x,    g_x);
    cudaGetSymbolAddress((void**)&tmp,  g_tmp);
    cudaGetSymbolAddress((void**)&qkv,  g_qkv);
    cudaGetSymbolAddress((void**)&mu,   g_mu);
    cudaGetSymbolAddress((void**)&rstd, g_rstd);

    __half *xh, *xl, *qkvh, *qkvl, *attnh, *attnl, *ffh, *ffl, *ench, *encl;
    cudaGetSymbolAddress((void**)&xh,    g_xh);
    cudaGetSymbolAddress((void**)&xl,    g_xl);
    cudaGetSymbolAddress((void**)&qkvh,  g_qkvh);
    cudaGetSymbolAddress((void**)&qkvl,  g_qkvl);
    cudaGetSymbolAddress((void**)&attnh, g_attnh);
    cudaGetSymbolAddress((void**)&attnl, g_attnl);
    cudaGetSymbolAddress((void**)&ffh,   g_ffh);
    cudaGetSymbolAddress((void**)&ffl,   g_ffl);
    cudaGetSymbolAddress((void**)&ench,  g_ench);
    cudaGetSymbolAddress((void**)&encl,  g_encl);

    __half *wtT_h, *wtT_l, *w1T_h, *w1T_l, *w2T_h, *w2T_l;
    __half *wo1T_h, *wo1T_l, *wo2T_h, *wo2T_l, *woutT_h, *woutT_l;
    cudaGetSymbolAddress((void**)&wtT_h,  g_wtT_h);
    cudaGetSymbolAddress((void**)&wtT_l,  g_wtT_l);
    cudaGetSymbolAddress((void**)&w1T_h,  g_w1T_h);
    cudaGetSymbolAddress((void**)&w1T_l,  g_w1T_l);
    cudaGetSymbolAddress((void**)&w2T_h,  g_w2T_h);
    cudaGetSymbolAddress((void**)&w2T_l,  g_w2T_l);
    cudaGetSymbolAddress((void**)&wo1T_h, g_wo1T_h);
    cudaGetSymbolAddress((void**)&wo1T_l, g_wo1T_l);
    cudaGetSymbolAddress((void**)&wo2T_h, g_wo2T_h);
    cudaGetSymbolAddress((void**)&wo2T_l, g_wo2T_l);
    cudaGetSymbolAddress((void**)&woutT_h, g_woutT_h);
    cudaGetSymbolAddress((void**)&woutT_l, g_woutT_l);

    const long long HW = (long long)Dm_ * Dk_;

    // ---- conversions ----
    convqkv_kernel<<<dim3(16, 24), 256>>>(Wq1, Wk1, Wv1, wtT_h, wtT_l);
    conva_kernel<<<cdiv(BS_*Dm_, 256), 256>>>(enc, ench, encl, BS_*Dm_);
    embed_kernel<<<BS_ * Dm_ / 256, 256>>>(tok, emb, x, xh, xl);
    convw_kernel<<<dim3(Ff_/64, Dm_/32, Nx_), 256>>>(W1, w1T_h, w1T_l, Dm_, Ff_, Ff_,
                                                     (long long)Dm_*Ff_, (long long)Ff_*Dm_);
    convw_kernel<<<dim3(Dm_/64, Ff_/32, Nx_), 256>>>(W2, w2T_h, w2T_l, Ff_, Dm_, Dm_,
                                                     (long long)Ff_*Dm_, (long long)Dm_*Ff_);
    gh8(xh, xl, wtT_h, wtT_l, qkv, qkvh, qkvl, nullptr, nullptr,
        BS_, 1536, Dm_, Dm_, Dm_, 1536, 0);
    for (int s = 1; s < 12; s++) {
        int i = s >> 1, pass = s & 1;
        const float* wq = pass ? Wq2 : Wq1;
        const float* wk = pass ? Wk2 : Wk1;
        const float* wv = pass ? Wv2 : Wv1;
        convqkv_kernel<<<dim3(16, 24), 256>>>(wq + (long long)i*Hh_*HW,
                                              wk + (long long)i*Hh_*HW,
                                              wv + (long long)i*Hh_*HW,
                                              wtT_h + (long long)s*1536*512,
                                              wtT_l + (long long)s*1536*512);
    }
    convw_kernel<<<dim3(Dm_/64, Dm_/32, Nx_), 256>>>(Wo1, wo1T_h, wo1T_l, Dm_, Dm_, Dm_,
                                                     (long long)Dm_*Dm_, (long long)Dm_*Dm_);
    convw_kernel<<<dim3(Dm_/64, Dm_/32, Nx_), 256>>>(Wo2, wo2T_h, wo2T_l, Dm_, Dm_, Dm_,
                                                     (long long)Dm_*Dm_, (long long)Dm_*Dm_);
    convw_kernel<<<dim3(VvP_/64, Dm_/32, 1), 256>>>(Wout, woutT_h, woutT_l, Dm_, Vv_, VvP_, 0, 0);

    for (int i = 0; i < Nx_; i++) {
        const float* bb1 = b1 + (long long)i * Ff_;
        const float* bb2 = b2 + (long long)i * Dm_;

        for (int attn_pass = 0; attn_pass < 2; attn_pass++) {
            const int self = (attn_pass == 0);
            const int s = i * 2 + attn_pass;
            const __half* wth = wtT_h + (long long)s * 1536 * 512;
            const __half* wtl = wtT_l + (long long)s * 1536 * 512;

            if (self) {
                if (i != 0)
                    gh8(xh, xl, wth, wtl, qkv, qkvh, qkvl, nullptr, nullptr,
                        BS_, 1536, Dm_, Dm_, Dm_, 1536, 0);
            } else {
                gh4(xh, xl, wth, wtl, qkv, qkvh, qkvl, nullptr, nullptr,
                    BS_, 512, Dm_, Dm_, Dm_, 1536, 0);
                dim3 g(8, 16, 1);
                gemm_h<8,0><<<g, 256, GH_SMEM8>>>(ench, encl,
                                                  wth + 512LL*512, wtl + 512LL*512,
                                                  qkv + 512, qkvh + 512, qkvl + 512,
                                                  nullptr, nullptr,
                                                  BS_, 1024, Dm_, Dm_, Dm_, 1536,
                                                  0, 0, 1, 0, 0, 1, 0, 0, 1, 1.f, 0);
            }
            // ---- fused attention (QK^T + softmax + PV) ----
            {
                dim3 g(4, 1, Bb_ * Hh_);
                fused_attn<<<g, 256, FA_SMEM>>>(qkvh, qkvl, qkv, attnh, attnl,
                                                self ? 1 : 0);
            }
            // tmp = attn @ Wo + x
            const __half* woh = (self ? wo1T_h : wo2T_h) + (long long)i*512*512;
            const __half* wol = (self ? wo1T_l : wo2T_l) + (long long)i*512*512;
            gh4(attnh, attnl, woh, wol, tmp, nullptr, nullptr, nullptr, x,
                BS_, Dm_, Dm_, Dm_, Dm_, Dm_, 0);
            bn_stats_kernel<<<Dm_/32, dim3(32, 8)>>>(tmp, mu, rstd);
            bn_apply_kernel<<<BS_*Dm_/256, 256>>>(tmp, x, xh, xl, mu, rstd,
                                                  gamma + (long long)(i*3 + attn_pass)*Dm_,
                                                  beta  + (long long)(i*3 + attn_pass)*Dm_);
        }

        // ---- feed-forward
        gh8(xh, xl, w1T_h + (long long)i*Ff_*512, w1T_l + (long long)i*Ff_*512,
            nullptr, ffh, ffl, bb1, nullptr, BS_, Ff_, Dm_, Dm_, Dm_, Ff_, 1);
        gh4(ffh, ffl, w2T_h + (long long)i*512LL*Ff_, w2T_l + (long long)i*512LL*Ff_,
            tmp, nullptr, nullptr, bb2, x, BS_, Dm_, Ff_, Ff_, Ff_, Dm_, 0);
        bn_stats_kernel<<<Dm_/32, dim3(32, 8)>>>(tmp, mu, rstd);
        bn_apply_kernel<<<BS_*Dm_/256, 256>>>(tmp, x, xh, xl, mu, rstd,
                                              gamma + (long long)(i*3 + 2)*Dm_,
                                              beta  + (long long)(i*3 + 2)*Dm_);
    }

    // ---- output projection (2-pass) + vocab softmax
    {
        dim3 g(cdiv(Vv_, 128), BS_ / 128, 1);
        gemm_h<8,1><<<g, 256, GH_SMEM8>>>(xh, xl, woutT_h, woutT_l,
                                          out, nullptr, nullptr, bout, nullptr,
                                          BS_, Vv_, Dm_, Dm_, Dm_, Vv_,
                                          0, 0, 1, 0, 0, 1, 0, 0, 1, 1.f, 0);
    }
    softmax_vocab_kernel<<<BS_, 1024>>>(out, Vv_);

    (void)in_sizes; (void)n_in; (void)out_size;
}

// round 15
// speedup vs baseline: 1.8433x; 1.0016x over previous
#include <cuda_runtime.h>
#include <cuda_fp16.h>
#include <math.h>
#include <stdint.h>

// ---------------------------------------------------------------------------
// Decoder — Round 15: MMA accumulator-chain breaking (pass-major ordering)
// ---------------------------------------------------------------------------

#define Bb_ 4
#define Ss_ 512
#define Dm_ 512
#define Hh_ 8
#define Dk_ 64
#define Ff_ 2048
#define Vv_ 37000
#define VvP_ 37120
#define Nx_ 6
#define BS_ 2048

// ------------------------- scratch (static device globals) -----------------
__device__ __align__(16) float g_x    [BS_*Dm_];
__device__ __align__(16) float g_tmp  [BS_*Dm_];
__device__ __align__(16) float g_qkv  [BS_*3*Dm_];     // fp32 (V read by fused attn)
__device__ float g_mu   [Dm_];
__device__ float g_rstd [Dm_];

// hi/lo half activations
__device__ __align__(16) __half g_xh   [BS_*Dm_];
__device__ __align__(16) __half g_xl   [BS_*Dm_];
__device__ __align__(16) __half g_qkvh [BS_*3*Dm_];
__device__ __align__(16) __half g_qkvl [BS_*3*Dm_];
__device__ __align__(16) __half g_attnh[BS_*Dm_];
__device__ __align__(16) __half g_attnl[BS_*Dm_];
__device__ __align__(16) __half g_ffh  [BS_*Ff_];
__device__ __align__(16) __half g_ffl  [BS_*Ff_];
__device__ __align__(16) __half g_ench [BS_*Dm_];
__device__ __align__(16) __half g_encl [BS_*Dm_];

// hi/lo half weights, [N, K] K-major
__device__ __align__(16) __half g_wtT_h [12L*1536*512];
__device__ __align__(16) __half g_wtT_l [12L*1536*512];
__device__ __align__(16) __half g_w1T_h [6L*2048*512];
__device__ __align__(16) __half g_w1T_l [6L*2048*512];
__device__ __align__(16) __half g_w2T_h [6L*512*2048];
__device__ __align__(16) __half g_w2T_l [6L*512*2048];
__device__ __align__(16) __half g_wo1T_h[6L*512*512];
__device__ __align__(16) __half g_wo1T_l[6L*512*512];
__device__ __align__(16) __half g_wo2T_h[6L*512*512];
__device__ __align__(16) __half g_wo2T_l[6L*512*512];
__device__ __align__(16) __half g_woutT_h[(long long)VvP_*512];

// ------------------------------- helpers -----------------------------------
__device__ __forceinline__ void split2(float2 x, uint32_t& hi, uint32_t& lo) {
    __half2 h = __float22half2_rn(x);
    float2 hf = __half22float2(h);
    __half2 l = __float22half2_rn(make_float2(x.x - hf.x, x.y - hf.y));
    hi = *reinterpret_cast<uint32_t*>(&h);
    lo = *reinterpret_cast<uint32_t*>(&l);
}
__device__ __forceinline__ void cpasync16(uint32_t dst, const void* src) {
    asm volatile("cp.async.cg.shared.global [%0], [%1], 16;"
                 :: "r"(dst), "l"(src));
}
__device__ __forceinline__ void cpcommit() { asm volatile("cp.async.commit_group;"); }
template <int NN> __device__ __forceinline__ void cpwait() {
    asm volatile("cp.async.wait_group %0;" :: "n"(NN));
}
__device__ __forceinline__ void mma16(float* d, const uint32_t* a, const uint32_t* b) {
    asm volatile(
        "mma.sync.aligned.m16n8k16.row.col.f32.f16.f16.f32 "
        "{%0,%1,%2,%3}, {%4,%5,%6,%7}, {%8,%9}, {%0,%1,%2,%3};"
        : "+f"(d[0]), "+f"(d[1]), "+f"(d[2]), "+f"(d[3])
        : "r"(a[0]), "r"(a[1]), "r"(a[2]), "r"(a[3]), "r"(b[0]), "r"(b[1]));
}
__device__ __forceinline__ void ldsm4(uint32_t* r, uint32_t addr) {
    asm volatile("ldmatrix.sync.aligned.m8n8.x4.shared.b16 {%0,%1,%2,%3}, [%4];"
                 : "=r"(r[0]), "=r"(r[1]), "=r"(r[2]), "=r"(r[3]) : "r"(addr));
}

// 64B rows (32 halves): 16B-chunk swizzle for ldmatrix conflict-freedom.
#define SWZ(row, cb) ((uint32_t)((cb) ^ ((((row) >> 1) & 3) << 4)))
// 128B rows (64 halves): chunk index XOR row&7 (8 distinct slots per phase).
#define SWZ128(row, c) ((uint32_t)(16 * ((c) ^ ((row) & 7))))

// ------------------------ GEMM: pure-half operands --------------------------
// 3-stage cp.async pipeline, swizzled 64B-row smem, 1 barrier/tile.
// MMAs are pass-major: each accumulator's 3 passes (hh,lh,hl) separated by
// 15 independent MMAs — preserves per-acc order (bitwise-identical math).
// NOBL=1: skip weight-lo — 2-pass mode (vocab only).
#define AARR (128*64)

template <int NT, int NOBL>
__global__ __launch_bounds__(256) void gemm_h(
    const __half* __restrict__ Ah, const __half* __restrict__ Al,
    const __half* __restrict__ Bh, const __half* __restrict__ Bl,
    float* __restrict__ C, __half* __restrict__ Ch, __half* __restrict__ Cl,
    const float* __restrict__ bias, const float* __restrict__ res,
    int M, int N, int K, int lda, int ldb, int ldc,
    long long aS1, long long aS2, int aDiv,
    long long bS1, long long bS2, int bDiv,
    long long cS1, long long cS2, int cDiv,
    float alpha, int flags)
{
    constexpr int BN   = NT * 16;
    constexpr int BARR = BN * 64;
    constexpr int STG  = 2 * AARR + 2 * BARR;

    extern __shared__ char smh[];
    const int m0 = blockIdx.y * 128, n0 = blockIdx.x * BN;
    if ((flags & 2) && n0 >= m0 + 128) return;

    const int z = blockIdx.z;
    const long long aOff = (long long)(z / aDiv) * aS1 + (long long)(z % aDiv) * aS2;
    const long long bOff = (long long)(z / bDiv) * bS1 + (long long)(z % bDiv) * bS2;
    const long long cOff = (long long)(z / cDiv) * cS1 + (long long)(z % cDiv) * cS2;
    const __half* Ahb = Ah + aOff;
    const __half* Alb = Al + aOff;
    const __half* Bhb = Bh + bOff;
    const __half* Blb = Bl + bOff;

    const uint32_t sb = (uint32_t)__cvta_generic_to_shared(smh);
    const int tid = threadIdx.x;
    const int wid = tid >> 5, lane = tid & 31;
    const int wm = wid & 3, wn = wid >> 2;
    const int g = lane >> 2, t = lane & 3;

    const int aRow = lane & 15, aChk = lane >> 4;
    const int bRow = (lane & 7) + ((lane >> 4) << 3);
    const int bChk = (lane >> 3) & 1;

    uint32_t aBase[2], aXor[2];
#pragma unroll
    for (int mt = 0; mt < 2; mt++) {
        int r = wm * 32 + mt * 16 + aRow;
        aBase[mt] = (uint32_t)(r * 64);
        aXor[mt]  = (uint32_t)(((r >> 1) & 3) << 4);
    }
    uint32_t bBase[NT / 2], bXor[NT / 2];
#pragma unroll
    for (int p = 0; p < NT / 2; p++) {
        int r = wn * (NT * 8) + p * 16 + bRow;
        bBase[p] = (uint32_t)(r * 64);
        bXor[p]  = (uint32_t)(((r >> 1) & 3) << 4);
    }

    float acc[2][NT][4];
#pragma unroll
    for (int i = 0; i < 2; i++)
#pragma unroll
        for (int j = 0; j < NT; j++)
#pragma unroll
            for (int r = 0; r < 4; r++) acc[i][j][r] = 0.f;

    const int T = K >> 5;

    auto stage = [&](int it, int buf) {
        const int k0 = it << 5;
        uint32_t dst = sb + buf * STG;
#pragma unroll
        for (int j = 0; j < 2; j++) {
            int idx = tid + (j << 8);
            int row = idx >> 2, c = idx & 3;
            long long asrc = (long long)(m0 + row) * lda + k0 + c * 8;
            uint32_t so = (uint32_t)(row * 64) + SWZ(row, c * 16);
            cpasync16(dst + 0 * AARR + so, Ahb + asrc);
            cpasync16(dst + 1 * AARR + so, Alb + asrc);
        }
#pragma unroll
        for (int j = 0; j < NT / 4; j++) {
            int idx = tid + (j << 8);
            int row = idx >> 2, c = idx & 3;
            long long bsrc = (long long)(n0 + row) * ldb + k0 + c * 8;
            uint32_t so = (uint32_t)(row * 64) + SWZ(row, c * 16);
            cpasync16(dst + 2 * AARR + so, Bhb + bsrc);
            if (!NOBL) cpasync16(dst + 2 * AARR + BARR + so, Blb + bsrc);
        }
    };

    stage(0, 0); cpcommit();
    stage(1, 1); cpcommit();

    for (int it = 0; it < T; ++it) {
        if (it + 1 < T) cpwait<1>(); else cpwait<0>();
        __syncthreads();

        const uint32_t base = sb + (uint32_t)(it % 3) * STG;
        const uint32_t aHb0 = base + 0 * AARR;
        const uint32_t aLb0 = base + 1 * AARR;
        const uint32_t bHb0 = base + 2 * AARR;
        const uint32_t bLb0 = base + 2 * AARR + BARR;

#pragma unroll
        for (int kk = 0; kk < 2; kk++) {
            const uint32_t cbA = (uint32_t)(aChk * 16 + kk * 32);
            const uint32_t cbB = (uint32_t)(bChk * 16 + kk * 32);
            uint32_t ah[2][4], al[2][4];
#pragma unroll
            for (int mt = 0; mt < 2; mt++) {
                uint32_t off = aBase[mt] + (cbA ^ aXor[mt]);
                ldsm4(ah[mt], aHb0 + off);
                ldsm4(al[mt], aLb0 + off);
            }
            uint32_t bh[NT / 2][4], bl[NT / 2][4];
#pragma unroll
            for (int p = 0; p < NT / 2; p++) {
                uint32_t off = bBase[p] + (cbB ^ bXor[p]);
                ldsm4(bh[p], bHb0 + off);
                if (!NOBL) ldsm4(bl[p], bLb0 + off);
            }
            // pass 1: ah*bh  (16 independent accumulators)
#pragma unroll
            for (int mt = 0; mt < 2; mt++)
#pragma unroll
                for (int p = 0; p < NT / 2; p++) {
                    mma16(acc[mt][2*p],   ah[mt], &bh[p][0]);
                    mma16(acc[mt][2*p+1], ah[mt], &bh[p][2]);
                }
            // pass 2: al*bh
#pragma unroll
            for (int mt = 0; mt < 2; mt++)
#pragma unroll
                for (int p = 0; p < NT / 2; p++) {
                    mma16(acc[mt][2*p],   al[mt], &bh[p][0]);
                    mma16(acc[mt][2*p+1], al[mt], &bh[p][2]);
                }
            // pass 3: ah*bl
            if (!NOBL) {
#pragma unroll
                for (int mt = 0; mt < 2; mt++)
#pragma unroll
                    for (int p = 0; p < NT / 2; p++) {
                        mma16(acc[mt][2*p],   ah[mt], &bl[p][0]);
                        mma16(acc[mt][2*p+1], ah[mt], &bl[p][2]);
                    }
            }
        }

        if (it + 2 < T) { stage(it + 2, (it + 2) % 3); cpcommit(); }
    }

    const bool relu = flags & 1;
#pragma unroll
    for (int mt = 0; mt < 2; mt++) {
#pragma unroll
        for (int hrow = 0; hrow < 2; hrow++) {
            int m = m0 + wm * 32 + mt * 16 + g + hrow * 8;
            long long rowo = cOff + (long long)m * ldc;
#pragma unroll
            for (int nt = 0; nt < NT; nt++) {
                int n = n0 + wn * (NT * 8) + nt * 8 + 2 * t;
                if (n < N) {
                    float v0 = acc[mt][nt][hrow * 2 + 0] * alpha;
                    float v1 = acc[mt][nt][hrow * 2 + 1] * alpha;
                    if (bias) { v0 += bias[n]; v1 += bias[n + 1]; }
                    if (res) {
                        const float* rp = res + rowo;
                        v0 += rp[n]; v1 += rp[n + 1];
                    }
                    if (relu) { v0 = fmaxf(v0, 0.f); v1 = fmaxf(v1, 0.f); }
                    if (C) {
                        float2 vv; vv.x = v0; vv.y = v1;
                        *(float2*)(C + rowo + n) = vv;
                    }
                    if (Ch) {
                        uint32_t hi, lo;
                        split2(make_float2(v0, v1), hi, lo);
                        *(uint32_t*)(Ch + rowo + n) = hi;
                        *(uint32_t*)(Cl + rowo + n) = lo;
                    }
                }
            }
        }
    }
}

#define GH_SMEM8 (3 * (2 * AARR + 2 * 128 * 64))   // 98304
#define GH_SMEM4 (3 * (2 * AARR + 2 * 64 * 64))    // 73728

// ------------------- fused flash attention ---------------------------------
// grid (4 m-tiles, 1, 32 bh), 256 thr = 8 warps x 16 rows.
#define FA_QH 0
#define FA_QL 16384
#define FA_K0 32768
#define FA_V0 98304
#define FA_SMEM 167936

__global__ __launch_bounds__(256, 1) void fused_attn(
    const __half* __restrict__ qkvh, const __half* __restrict__ qkvl,
    const float* __restrict__ qkv,
    __half* __restrict__ Ch, __half* __restrict__ Cl,
    int causal)
{
    extern __shared__ char smf[];
    const uint32_t sb = (uint32_t)__cvta_generic_to_shared(smf);
    const int z = blockIdx.z;
    const int b = z >> 3, h = z & 7;
    const int mt = blockIdx.x;
    const int m0 = mt * 128;
    const long long tokb = (long long)b * 512;
    const int tid = threadIdx.x, wid = tid >> 5, lane = tid & 31;
    const int g = lane >> 2, t = lane & 3;
    const int aRow = lane & 15, aChk = lane >> 4;
    const int bRow = (lane & 7) + ((lane >> 4) << 3);
    const int bChk = (lane >> 3) & 1;

    // ---- stage Q (group 0) ----
#pragma unroll
    for (int j = 0; j < 4; j++) {
        int idx = tid + (j << 8);
        int r = idx >> 3, c = idx & 7;
        long long src = (tokb + m0 + r) * 1536 + h * 64 + c * 8;
        uint32_t so = (uint32_t)(r * 128) + SWZ128(r, c);
        cpasync16(sb + FA_QH + so, qkvh + src);
        cpasync16(sb + FA_QL + so, qkvl + src);
    }
    cpcommit();

    auto stageKV = [&](int kt, int buf) {
        uint32_t kdst = sb + FA_K0 + (uint32_t)buf * 32768u;
#pragma unroll
        for (int j = 0; j < 4; j++) {
            int idx = tid + (j << 8);
            int r = idx >> 3, c = idx & 7;
            long long src = (tokb + kt * 128 + r) * 1536 + 512 + h * 64 + c * 8;
            uint32_t so = (uint32_t)(r * 128) + SWZ128(r, c);
            cpasync16(kdst + so, qkvh + src);
            cpasync16(kdst + 16384 + so, qkvl + src);
        }
        uint32_t vdst = sb + FA_V0 + (uint32_t)buf * 34816u;
#pragma unroll
        for (int j = 0; j < 8; j++) {
            int idx = tid + (j << 8);
            int r = idx >> 4, c = idx & 15;
            long long src = (tokb + kt * 128 + r) * 1536 + 1024 + h * 64 + c * 4;
            cpasync16(vdst + (uint32_t)((r * 68 + c * 4) * 4), qkv + src);
        }
    };

    stageKV(0, 0); cpcommit();

    cpwait<1>();
    __syncthreads();
    uint32_t qh[4][4], ql[4][4];
    {
        int r = wid * 16 + aRow;
        uint32_t qb = (uint32_t)(r * 128);
#pragma unroll
        for (int kc = 0; kc < 4; kc++) {
            uint32_t cb = SWZ128(r, kc * 2 + aChk);
            ldsm4(qh[kc], sb + FA_QH + qb + cb);
            ldsm4(ql[kc], sb + FA_QL + qb + cb);
        }
    }

    float accO[8][4];
#pragma unroll
    for (int nt = 0; nt < 8; nt++)
#pragma unroll
        for (int r = 0; r < 4; r++) accO[nt][r] = 0.f;
    float Mg = -1e30f, Mg8 = -1e30f, Lg = 0.f, Lg8 = 0.f;

    const int jmax = causal ? (mt + 1) : 4;

    for (int j = 0; j < jmax; j++) {
        if (j + 1 < jmax) { stageKV(j + 1, (j + 1) & 1); cpcommit(); cpwait<1>(); }
        else              { cpwait<0>(); }
        __syncthreads();

        const uint32_t kb = sb + FA_K0 + (uint32_t)(j & 1) * 32768u;
        const float* Vb = (const float*)(smf + FA_V0 + (size_t)(j & 1) * 34816u);

        // ---- S = (Q K^T) * isq  (3-pass; per-acc order hh,lh,hl kept) ----
        float s[16][4];
#pragma unroll
        for (int nt = 0; nt < 16; nt++)
#pragma unroll
            for (int r = 0; r < 4; r++) s[nt][r] = 0.f;

#pragma unroll
        for (int kc = 0; kc < 4; kc++) {
#pragma unroll
            for (int p = 0; p < 8; p++) {
                int r = p * 16 + bRow;
                uint32_t off = (uint32_t)(r * 128) + SWZ128(r, kc * 2 + bChk);
                uint32_t bh4[4], bl4[4];
                ldsm4(bh4, kb + off);
                ldsm4(bl4, kb + 16384 + off);
                // interleaved: each acc's passes separated by 1 indep MMA
                mma16(s[2*p],   qh[kc], &bh4[0]);
                mma16(s[2*p+1], qh[kc], &bh4[2]);
                mma16(s[2*p],   ql[kc], &bh4[0]);
                mma16(s[2*p+1], ql[kc], &bh4[2]);
                mma16(s[2*p],   qh[kc], &bl4[0]);
                mma16(s[2*p+1], qh[kc], &bl4[2]);
            }
        }
#pragma unroll
        for (int nt = 0; nt < 16; nt++)
#pragma unroll
            for (int r = 0; r < 4; r++) s[nt][r] *= 0.125f;

        if (causal && j == mt) {
            int rg = m0 + wid * 16 + g;
#pragma unroll
            for (int nt = 0; nt < 16; nt++) {
                int cb0 = j * 128 + nt * 8 + 2 * t;
                if (cb0     > rg)     s[nt][0] = -1e30f;
                if (cb0 + 1 > rg)     s[nt][1] = -1e30f;
                if (cb0     > rg + 8) s[nt][2] = -1e30f;
                if (cb0 + 1 > rg + 8) s[nt][3] = -1e30f;
            }
        }

        // ---- online softmax update ----
        float mg = -1e30f, mg8 = -1e30f;
#pragma unroll
        for (int nt = 0; nt < 16; nt++) {
            mg  = fmaxf(mg,  fmaxf(s[nt][0], s[nt][1]));
            mg8 = fmaxf(mg8, fmaxf(s[nt][2], s[nt][3]));
        }
        mg  = fmaxf(mg,  __shfl_xor_sync(0xffffffff, mg, 1));
        mg  = fmaxf(mg,  __shfl_xor_sync(0xffffffff, mg, 2));
        mg8 = fmaxf(mg8, __shfl_xor_sync(0xffffffff, mg8, 1));
        mg8 = fmaxf(mg8, __shfl_xor_sync(0xffffffff, mg8, 2));
        float Mn  = fmaxf(Mg,  mg);
        float Mn8 = fmaxf(Mg8, mg8);
        float f  = __expf(Mg  - Mn);
        float f8 = __expf(Mg8 - Mn8);
        Mg = Mn; Mg8 = Mn8;
        Lg *= f; Lg8 *= f8;
#pragma unroll
        for (int nt = 0; nt < 8; nt++) {
            accO[nt][0] *= f;  accO[nt][1] *= f;
            accO[nt][2] *= f8; accO[nt][3] *= f8;
        }

        // ---- P (fp16 A-fragments, in-register repack) ----
        uint32_t pa[8][4];
#pragma unroll
        for (int kc2 = 0; kc2 < 8; kc2++) {
            float p00 = __expf(s[2*kc2][0]   - Mg);
            float p01 = __expf(s[2*kc2][1]   - Mg);
            float p02 = __expf(s[2*kc2][2]   - Mg8);
            float p03 = __expf(s[2*kc2][3]   - Mg8);
            float p10 = __expf(s[2*kc2+1][0] - Mg);
            float p11 = __expf(s[2*kc2+1][1] - Mg);
            float p12 = __expf(s[2*kc2+1][2] - Mg8);
            float p13 = __expf(s[2*kc2+1][3] - Mg8);
            Lg  += p00 + p01 + p10 + p11;
            Lg8 += p02 + p03 + p12 + p13;
            __half2 h0 = __floats2half2_rn(p00, p01);
            __half2 h1 = __floats2half2_rn(p02, p03);
            __half2 h2v = __floats2half2_rn(p10, p11);
            __half2 h3 = __floats2half2_rn(p12, p13);
            pa[kc2][0] = *(uint32_t*)&h0;
            pa[kc2][1] = *(uint32_t*)&h1;
            pa[kc2][2] = *(uint32_t*)&h2v;
            pa[kc2][3] = *(uint32_t*)&h3;
        }

        // ---- O += P @ V  (two sweeps: hh over all nt, then hl) ----
#pragma unroll
        for (int kc2 = 0; kc2 < 8; kc2++) {
            uint32_t bv[8][2], bw[8][2];
#pragma unroll
            for (int nt = 0; nt < 8; nt++) {
                const float* base = Vb + (kc2 * 16 + 2 * t) * 68 + nt * 8 + g;
                uint32_t bh0, bl0, bh1, bl1;
                split2(make_float2(base[0],      base[68]),     bh0, bl0);
                split2(make_float2(base[8 * 68], base[9 * 68]), bh1, bl1);
                bv[nt][0] = bh0; bv[nt][1] = bh1;
                bw[nt][0] = bl0; bw[nt][1] = bl1;
            }
#pragma unroll
            for (int nt = 0; nt < 8; nt++) mma16(accO[nt], pa[kc2], bv[nt]);
#pragma unroll
            for (int nt = 0; nt < 8; nt++) mma16(accO[nt], pa[kc2], bw[nt]);
        }
        __syncthreads();
    }

    // ---- epilogue: normalize + write halves ----
    Lg  += __shfl_xor_sync(0xffffffff, Lg, 1);
    Lg  += __shfl_xor_sync(0xffffffff, Lg, 2);
    Lg8 += __shfl_xor_sync(0xffffffff, Lg8, 1);
    Lg8 += __shfl_xor_sync(0xffffffff, Lg8, 2);
    float invg  = 1.f / Lg;
    float invg8 = 1.f / Lg8;

    long long row0 = (tokb + m0 + wid * 16 + g) * 512 + h * 64;
    long long row8 = row0 + 8LL * 512;
#pragma unroll
    for (int nt = 0; nt < 8; nt++) {
        int n = nt * 8 + 2 * t;
        uint32_t hi, lo;
        split2(make_float2(accO[nt][0] * invg, accO[nt][1] * invg), hi, lo);
        *(uint32_t*)(Ch + row0 + n) = hi;
        *(uint32_t*)(Cl + row0 + n) = lo;
        split2(make_float2(accO[nt][2] * invg8, accO[nt][3] * invg8), hi, lo);
        *(uint32_t*)(Ch + row8 + n) = hi;
        *(uint32_t*)(Cl + row8 + n) = lo;
    }
}

// --------------------------- conversion kernels -----------------------------
// lo may be nullptr (vocab: weight-lo unused since 2-pass NOBL GEMM).
__global__ void convw_kernel(const float* __restrict__ W,
                             __half* __restrict__ hi, __half* __restrict__ lo,
                             int K, int N, int Npad, long long inS, long long outS)
{
    __shared__ float tile[32][65];
    int z = blockIdx.z;
    const float* Wz = W + (long long)z * inS;
    int k0 = blockIdx.y * 32, n0 = blockIdx.x * 64;
    int tid = threadIdx.x;

#pragma unroll
    for (int j = 0; j < 2; j++) {
        int idx = tid + (j << 8);
        int k = idx >> 4, nq = (idx & 15) << 2;
        int n = n0 + nq;
        float4 v = make_float4(0.f, 0.f, 0.f, 0.f);
        const float* p = Wz + (long long)(k0 + k) * N;
        if (n + 3 < N) v = *(const float4*)(p + n);
        else {
            if (n + 0 < N) v.x = p[n + 0];
            if (n + 1 < N) v.y = p[n + 1];
            if (n + 2 < N) v.z = p[n + 2];
            if (n + 3 < N) v.w = p[n + 3];
        }
        tile[k][nq + 0] = v.x; tile[k][nq + 1] = v.y;
        tile[k][nq + 2] = v.z; tile[k][nq + 3] = v.w;
    }
    __syncthreads();

#pragma unroll
    for (int j = 0; j < 4; j++) {
        int idx = tid + (j << 8);
        int n = idx >> 4, tq = (idx & 15) << 1;
        int gn = n0 + n;
        if (gn < Npad) {
            float v0 = tile[tq][n], v1 = tile[tq + 1][n];
            __half2 h = __floats2half2_rn(v0, v1);
            long long o = (long long)z * outS + (long long)gn * K + k0 + tq;
            *(__half2*)(hi + o) = h;
            if (lo) {
                float2 hf = __half22float2(h);
                __half2 l = __floats2half2_rn(v0 - hf.x, v1 - hf.y);
                *(__half2*)(lo + o) = l;
            }
        }
    }
}

__global__ void convqkv_kernel(const float* __restrict__ Wq, const float* __restrict__ Wk,
                               const float* __restrict__ Wv,
                               __half* __restrict__ hi, __half* __restrict__ lo)
{
    __shared__ float tile[32][65];
    int kt = blockIdx.x, sh = blockIdx.y;
    int sel = sh >> 3, h = sh & 7;
    const float* W = (sel == 0) ? Wq : (sel == 1) ? Wk : Wv;
    const float* src = W + ((long long)h * 512 + kt * 32) * 64;
    int tid = threadIdx.x;

#pragma unroll
    for (int j = 0; j < 2; j++) {
        int idx = tid + (j << 8);
        int k = idx >> 4, eq = (idx & 15) << 2;
        float4 v = *(const float4*)(src + k * 64 + eq);
        tile[k][eq + 0] = v.x; tile[k][eq + 1] = v.y;
        tile[k][eq + 2] = v.z; tile[k][eq + 3] = v.w;
    }
    __syncthreads();

#pragma unroll
    for (int j = 0; j < 4; j++) {
        int idx = tid + (j << 8);
        int e = idx >> 4, tq = (idx & 15) << 1;
        int n = sel * 512 + h * 64 + e;
        float v0 = tile[tq][e], v1 = tile[tq + 1][e];
        __half2 hh = __floats2half2_rn(v0, v1);
        float2 hf = __half22float2(hh);
        __half2 ll = __floats2half2_rn(v0 - hf.x, v1 - hf.y);
        long long o = (long long)n * 512 + kt * 32 + tq;
        *(__half2*)(hi + o) = hh;
        *(__half2*)(lo + o) = ll;
    }
}

__global__ void conva_kernel(const float* __restrict__ src,
                             __half* __restrict__ hi, __half* __restrict__ lo, int n) {
    int i = blockIdx.x * 256 + threadIdx.x;
    if (i < n) {
        float v = src[i];
        __half h = __float2half_rn(v);
        hi[i] = h;
        lo[i] = __float2half_rn(v - __half2float(h));
    }
}

// --------------------------- elementwise kernels ---------------------------
__global__ void embed_kernel(const int* __restrict__ tok, const float* __restrict__ emb,
                             float* __restrict__ x,
                             __half* __restrict__ xh, __half* __restrict__ xl) {
    int idx = blockIdx.x * 256 + threadIdx.x;
    int t = tok[idx >> 9];
    float v = emb[(long long)t * Dm_ + (idx & 511)] * 8.0f;
    x[idx] = v;
    __half h = __float2half_rn(v);
    xh[idx] = h;
    xl[idx] = __float2half_rn(v - __half2float(h));
}

__global__ void bn_stats_kernel(const float* __restrict__ x,
                                float* __restrict__ mu, float* __restrict__ rstd) {
    int d = blockIdx.x * 32 + threadIdx.x;
    float s = 0.f, s2 = 0.f;
    for (int i = threadIdx.y; i < BS_; i += 8) {
        float v = x[(long long)i * Dm_ + d];
        s += v; s2 += v * v;
    }
    __shared__ float sh[8][33], sh2[8][33];
    sh[threadIdx.y][threadIdx.x] = s;
    sh2[threadIdx.y][threadIdx.x] = s2;
    __syncthreads();
    if (threadIdx.y == 0) {
#pragma unroll
        for (int r = 1; r < 8; r++) { s += sh[r][threadIdx.x]; s2 += sh2[r][threadIdx.x]; }
        float m = s * (1.f / BS_);
        float var = s2 * (1.f / BS_) - m * m;
        mu[d] = m;
        rstd[d] = rsqrtf(var + 1e-5f);
    }
}

__global__ void bn_apply_kernel(const float* __restrict__ xin, float* __restrict__ xout,
                                __half* __restrict__ xh, __half* __restrict__ xl,
                                const float* __restrict__ mu, const float* __restrict__ rstd,
                                const float* __restrict__ gamma, const float* __restrict__ beta) {
    int idx = blockIdx.x * 256 + threadIdx.x;
    int d = idx & 511;
    float v = (xin[idx] - mu[d]) * rstd[d] * gamma[d] + beta[d];
    xout[idx] = v;
    __half h = __float2half_rn(v);
    xh[idx] = h;
    xl[idx] = __float2half_rn(v - __half2float(h));
}

// Vocab softmax (register-resident, launch-bounded)
#define VITER 37
__global__ __launch_bounds__(1024, 1) void softmax_vocab_kernel(float* __restrict__ p, int T) {
    __shared__ float red[1024];
    long long row = blockIdx.x;
    float* x = p + row * (long long)T;
    int tid = threadIdx.x;

    float vals[VITER];
    float m = -1e30f;
#pragma unroll
    for (int j = 0; j < VITER; j++) {
        int t = tid + j * 1024;
        float v = (t < T) ? x[t] : -1e30f;
        vals[j] = v;
        m = fmaxf(m, v);
    }
    red[tid] = m; __syncthreads();
    for (int o = 512; o > 0; o >>= 1) {
        if (tid < o) red[tid] = fmaxf(red[tid], red[tid + o]);
        __syncthreads();
    }
    float M = red[0]; __syncthreads();

    float sum = 0.f;
#pragma unroll
    for (int j = 0; j < VITER; j++) {
        int t = tid + j * 1024;
        if (t < T) { vals[j] = __expf(vals[j] - M); sum += vals[j]; }
    }
    red[tid] = sum; __syncthreads();
    for (int o = 512; o > 0; o >>= 1) {
        if (tid < o) red[tid] += red[tid + o];
        __syncthreads();
    }
    float inv = 1.f / red[0];
#pragma unroll
    for (int j = 0; j < VITER; j++) {
        int t = tid + j * 1024;
        if (t < T) x[t] = vals[j] * inv;
    }
}

// ------------------------------- host side ---------------------------------
static inline int cdiv(int a, int b) { return (a + b - 1) / b; }

static void gh8(const __half* Ah, const __half* Al, const __half* Bh, const __half* Bl,
                float* C, __half* Ch, __half* Cl,
                const float* bias, const float* res,
                int M, int N, int K, int lda, int ldb, int ldc, int flags)
{
    dim3 g(cdiv(N, 128), M / 128, 1);
    gemm_h<8,0><<<g, 256, GH_SMEM8>>>(Ah, Al, Bh, Bl, C, Ch, Cl, bias, res,
                                      M, N, K, lda, ldb, ldc,
                                      0, 0, 1, 0, 0, 1, 0, 0, 1, 1.f, flags);
}
static void gh4(const __half* Ah, const __half* Al, const __half* Bh, const __half* Bl,
                float* C, __half* Ch, __half* Cl,
                const float* bias, const float* res,
                int M, int N, int K, int lda, int ldb, int ldc, int flags)
{
    dim3 g(cdiv(N, 64), M / 128, 1);
    gemm_h<4,0><<<g, 256, GH_SMEM4>>>(Ah, Al, Bh, Bl, C, Ch, Cl, bias, res,
                                      M, N, K, lda, ldb, ldc,
                                      0, 0, 1, 0, 0, 1, 0, 0, 1, 1.f, flags);
}

extern "C" void kernel_launch(void* const* d_in, const int* in_sizes, int n_in,
                              void* d_out, int out_size)
{
    const int*   tok   = (const int*)  d_in[0];
    const float* enc   = (const float*)d_in[1];
    const float* emb   = (const float*)d_in[2];
    const float* Wq1   = (const float*)d_in[3];
    const float* Wk1   = (const float*)d_in[4];
    const float* Wv1   = (const float*)d_in[5];
    const float* Wo1   = (const float*)d_in[6];
    const float* Wq2   = (const float*)d_in[7];
    const float* Wk2   = (const float*)d_in[8];
    const float* Wv2   = (const float*)d_in[9];
    const float* Wo2   = (const float*)d_in[10];
    const float* gamma = (const float*)d_in[11];
    const float* beta  = (const float*)d_in[12];
    const float* W1    = (const float*)d_in[13];
    const float* b1    = (const float*)d_in[14];
    const float* W2    = (const float*)d_in[15];
    const float* b2    = (const float*)d_in[16];
    const float* Wout  = (const float*)d_in[17];
    const float* bout  = (const float*)d_in[18];
    float* out = (float*)d_out;

    cudaFuncSetAttribute(gemm_h<8,0>, cudaFuncAttributeMaxDynamicSharedMemorySize, GH_SMEM8);
    cudaFuncSetAttribute(gemm_h<8,1>, cudaFuncAttributeMaxDynamicSharedMemorySize, GH_SMEM8);
    cudaFuncSetAttribute(gemm_h<4,0>, cudaFuncAttributeMaxDynamicSharedMemorySize, GH_SMEM4);
    cudaFuncSetAttribute(fused_attn,  cudaFuncAttributeMaxDynamicSharedMemorySize, FA_SMEM);

    float *x, *tmp, *qkv, *mu, *rstd;
    cudaGetSymbolAddress((void**)&x,    g_x);
    cudaGetSymbolAddress((void**)&tmp,  g_tmp);
    cudaGetSymbolAddress((void**)&qkv,  g_qkv);
    cudaGetSymbolAddress((void**)&mu,   g_mu);
    cudaGetSymbolAddress((void**)&rstd, g_rstd);

    __half *xh, *xl, *qkvh, *qkvl, *attnh, *attnl, *ffh, *ffl, *ench, *encl;
    cudaGetSymbolAddress((void**)&xh,    g_xh);
    cudaGetSymbolAddress((void**)&xl,    g_xl);
    cudaGetSymbolAddress((void**)&qkvh,  g_qkvh);
    cudaGetSymbolAddress((void**)&qkvl,  g_qkvl);
    cudaGetSymbolAddress((void**)&attnh, g_attnh);
    cudaGetSymbolAddress((void**)&attnl, g_attnl);
    cudaGetSymbolAddress((void**)&ffh,   g_ffh);
    cudaGetSymbolAddress((void**)&ffl,   g_ffl);
    cudaGetSymbolAddress((void**)&ench,  g_ench);
    cudaGetSymbolAddress((void**)&encl,  g_encl);

    __half *wtT_h, *wtT_l, *w1T_h, *w1T_l, *w2T_h, *w2T_l;
    __half *wo1T_h, *wo1T_l, *wo2T_h, *wo2T_l, *woutT_h;
    cudaGetSymbolAddress((void**)&wtT_h,  g_wtT_h);
    cudaGetSymbolAddress((void**)&wtT_l,  g_wtT_l);
    cudaGetSymbolAddress((void**)&w1T_h,  g_w1T_h);
    cudaGetSymbolAddress((void**)&w1T_l,  g_w1T_l);
    cudaGetSymbolAddress((void**)&w2T_h,  g_w2T_h);
    cudaGetSymbolAddress((void**)&w2T_l,  g_w2T_l);
    cudaGetSymbolAddress((void**)&wo1T_h, g_wo1T_h);
    cudaGetSymbolAddress((void**)&wo1T_l, g_wo1T_l);
    cudaGetSymbolAddress((void**)&wo2T_h, g_wo2T_h);
    cudaGetSymbolAddress((void**)&wo2T_l, g_wo2T_l);
    cudaGetSymbolAddress((void**)&woutT_h, g_woutT_h);

    const long long HW = (long long)Dm_ * Dk_;

    // ---- conversions ----
    convqkv_kernel<<<dim3(16, 24), 256>>>(Wq1, Wk1, Wv1, wtT_h, wtT_l);
    conva_kernel<<<cdiv(BS_*Dm_, 256), 256>>>(enc, ench, encl, BS_*Dm_);
    embed_kernel<<<BS_ * Dm_ / 256, 256>>>(tok, emb, x, xh, xl);
    convw_kernel<<<dim3(Ff_/64, Dm_/32, Nx_), 256>>>(W1, w1T_h, w1T_l, Dm_, Ff_, Ff_,
                                                     (long long)Dm_*Ff_, (long long)Ff_*Dm_);
    convw_kernel<<<dim3(Dm_/64, Ff_/32, Nx_), 256>>>(W2, w2T_h, w2T_l, Ff_, Dm_, Dm_,
                                                     (long long)Ff_*Dm_, (long long)Dm_*Ff_);
    gh8(xh, xl, wtT_h, wtT_l, qkv, qkvh, qkvl, nullptr, nullptr,
        BS_, 1536, Dm_, Dm_, Dm_, 1536, 0);
    for (int s = 1; s < 12; s++) {
        int i = s >> 1, pass = s & 1;
        const float* wq = pass ? Wq2 : Wq1;
        const float* wk = pass ? Wk2 : Wk1;
        const float* wv = pass ? Wv2 : Wv1;
        convqkv_kernel<<<dim3(16, 24), 256>>>(wq + (long long)i*Hh_*HW,
                                              wk + (long long)i*Hh_*HW,
                                              wv + (long long)i*Hh_*HW,
                                              wtT_h + (long long)s*1536*512,
                                              wtT_l + (long long)s*1536*512);
    }
    convw_kernel<<<dim3(Dm_/64, Dm_/32, Nx_), 256>>>(Wo1, wo1T_h, wo1T_l, Dm_, Dm_, Dm_,
                                                     (long long)Dm_*Dm_, (long long)Dm_*Dm_);
    convw_kernel<<<dim3(Dm_/64, Dm_/32, Nx_), 256>>>(Wo2, wo2T_h, wo2T_l, Dm_, Dm_, Dm_,
                                                     (long long)Dm_*Dm_, (long long)Dm_*Dm_);
    convw_kernel<<<dim3(VvP_/64, Dm_/32, 1), 256>>>(Wout, woutT_h, nullptr, Dm_, Vv_, VvP_, 0, 0);

    for (int i = 0; i < Nx_; i++) {
        const float* bb1 = b1 + (long long)i * Ff_;
        const float* bb2 = b2 + (long long)i * Dm_;

        for (int attn_pass = 0; attn_pass < 2; attn_pass++) {
            const int self = (attn_pass == 0);
            const int s = i * 2 + attn_pass;
            const __half* wth = wtT_h + (long long)s * 1536 * 512;
            const __half* wtl = wtT_l + (long long)s * 1536 * 512;

            if (self) {
                if (i != 0)
                    gh8(xh, xl, wth, wtl, qkv, qkvh, qkvl, nullptr, nullptr,
                        BS_, 1536, Dm_, Dm_, Dm_, 1536, 0);
            } else {
                gh4(xh, xl, wth, wtl, qkv, qkvh, qkvl, nullptr, nullptr,
                    BS_, 512, Dm_, Dm_, Dm_, 1536, 0);
                dim3 g(8, 16, 1);
                gemm_h<8,0><<<g, 256, GH_SMEM8>>>(ench, encl,
                                                  wth + 512LL*512, wtl + 512LL*512,
                                                  qkv + 512, qkvh + 512, qkvl + 512,
                                                  nullptr, nullptr,
                                                  BS_, 1024, Dm_, Dm_, Dm_, 1536,
                                                  0, 0, 1, 0, 0, 1, 0, 0, 1, 1.f, 0);
            }
            // ---- fused attention ----
            {
                dim3 g(4, 1, Bb_ * Hh_);
                fused_attn<<<g, 256, FA_SMEM>>>(qkvh, qkvl, qkv, attnh, attnl,
                                                self ? 1 : 0);
            }
            // tmp = attn @ Wo + x
            const __half* woh = (self ? wo1T_h : wo2T_h) + (long long)i*512*512;
            const __half* wol = (self ? wo1T_l : wo2T_l) + (long long)i*512*512;
            gh4(attnh, attnl, woh, wol, tmp, nullptr, nullptr, nullptr, x,
                BS_, Dm_, Dm_, Dm_, Dm_, Dm_, 0);
            bn_stats_kernel<<<Dm_/32, dim3(32, 8)>>>(tmp, mu, rstd);
            bn_apply_kernel<<<BS_*Dm_/256, 256>>>(tmp, x, xh, xl, mu, rstd,
                                                  gamma + (long long)(i*3 + attn_pass)*Dm_,
                                                  beta  + (long long)(i*3 + attn_pass)*Dm_);
        }

        // ---- feed-forward
        gh8(xh, xl, w1T_h + (long long)i*Ff_*512, w1T_l + (long long)i*Ff_*512,
            nullptr, ffh, ffl, bb1, nullptr, BS_, Ff_, Dm_, Dm_, Dm_, Ff_, 1);
        gh4(ffh, ffl, w2T_h + (long long)i*512LL*Ff_, w2T_l + (long long)i*512LL*Ff_,
            tmp, nullptr, nullptr, bb2, x, BS_, Dm_, Ff_, Ff_, Ff_, Dm_, 0);
        bn_stats_kernel<<<Dm_/32, dim3(32, 8)>>>(tmp, mu, rstd);
        bn_apply_kernel<<<BS_*Dm_/256, 256>>>(tmp, x, xh, xl, mu, rstd,
                                              gamma + (long long)(i*3 + 2)*Dm_,
                                              beta  + (long long)(i*3 + 2)*Dm_);
    }

    // ---- output projection (2-pass) + vocab softmax
    {
        dim3 g(cdiv(Vv_, 128), BS_ / 128, 1);
        gemm_h<8,1><<<g, 256, GH_SMEM8>>>(xh, xl, woutT_h, woutT_h,
                                          out, nullptr, nullptr, bout, nullptr,
                                          BS_, Vv_, Dm_, Dm_, Dm_, Vv_,
                                          0, 0, 1, 0, 0, 1, 0, 0, 1, 1.f, 0);
    }
    softmax_vocab_kernel<<<BS_, 1024>>>(out, Vv_);

    (void)in_sizes; (void)n_in; (void)out_size;
}

// round 16
// speedup vs baseline: 1.8690x; 1.0139x over previous
#include <cuda_runtime.h>
#include <cuda_fp16.h>
#include <math.h>
#include <stdint.h>

// ---------------------------------------------------------------------------
// Decoder — Round 16: NMT template (BM=64 tiles) for under-filled N=512 GEMMs
// ---------------------------------------------------------------------------

#define Bb_ 4
#define Ss_ 512
#define Dm_ 512
#define Hh_ 8
#define Dk_ 64
#define Ff_ 2048
#define Vv_ 37000
#define VvP_ 37120
#define Nx_ 6
#define BS_ 2048

// ------------------------- scratch (static device globals) -----------------
__device__ __align__(16) float g_x    [BS_*Dm_];
__device__ __align__(16) float g_tmp  [BS_*Dm_];
__device__ __align__(16) float g_qkv  [BS_*3*Dm_];     // fp32 (V read by fused attn)
__device__ float g_mu   [Dm_];
__device__ float g_rstd [Dm_];

// hi/lo half activations
__device__ __align__(16) __half g_xh   [BS_*Dm_];
__device__ __align__(16) __half g_xl   [BS_*Dm_];
__device__ __align__(16) __half g_qkvh [BS_*3*Dm_];
__device__ __align__(16) __half g_qkvl [BS_*3*Dm_];
__device__ __align__(16) __half g_attnh[BS_*Dm_];
__device__ __align__(16) __half g_attnl[BS_*Dm_];
__device__ __align__(16) __half g_ffh  [BS_*Ff_];
__device__ __align__(16) __half g_ffl  [BS_*Ff_];
__device__ __align__(16) __half g_ench [BS_*Dm_];
__device__ __align__(16) __half g_encl [BS_*Dm_];

// hi/lo half weights, [N, K] K-major
__device__ __align__(16) __half g_wtT_h [12L*1536*512];
__device__ __align__(16) __half g_wtT_l [12L*1536*512];
__device__ __align__(16) __half g_w1T_h [6L*2048*512];
__device__ __align__(16) __half g_w1T_l [6L*2048*512];
__device__ __align__(16) __half g_w2T_h [6L*512*2048];
__device__ __align__(16) __half g_w2T_l [6L*512*2048];
__device__ __align__(16) __half g_wo1T_h[6L*512*512];
__device__ __align__(16) __half g_wo1T_l[6L*512*512];
__device__ __align__(16) __half g_wo2T_h[6L*512*512];
__device__ __align__(16) __half g_wo2T_l[6L*512*512];
__device__ __align__(16) __half g_woutT_h[(long long)VvP_*512];

// ------------------------------- helpers -----------------------------------
__device__ __forceinline__ void split2(float2 x, uint32_t& hi, uint32_t& lo) {
    __half2 h = __float22half2_rn(x);
    float2 hf = __half22float2(h);
    __half2 l = __float22half2_rn(make_float2(x.x - hf.x, x.y - hf.y));
    hi = *reinterpret_cast<uint32_t*>(&h);
    lo = *reinterpret_cast<uint32_t*>(&l);
}
__device__ __forceinline__ void cpasync16(uint32_t dst, const void* src) {
    asm volatile("cp.async.cg.shared.global [%0], [%1], 16;"
                 :: "r"(dst), "l"(src));
}
__device__ __forceinline__ void cpcommit() { asm volatile("cp.async.commit_group;"); }
template <int NN> __device__ __forceinline__ void cpwait() {
    asm volatile("cp.async.wait_group %0;" :: "n"(NN));
}
__device__ __forceinline__ void mma16(float* d, const uint32_t* a, const uint32_t* b) {
    asm volatile(
        "mma.sync.aligned.m16n8k16.row.col.f32.f16.f16.f32 "
        "{%0,%1,%2,%3}, {%4,%5,%6,%7}, {%8,%9}, {%0,%1,%2,%3};"
        : "+f"(d[0]), "+f"(d[1]), "+f"(d[2]), "+f"(d[3])
        : "r"(a[0]), "r"(a[1]), "r"(a[2]), "r"(a[3]), "r"(b[0]), "r"(b[1]));
}
__device__ __forceinline__ void ldsm4(uint32_t* r, uint32_t addr) {
    asm volatile("ldmatrix.sync.aligned.m8n8.x4.shared.b16 {%0,%1,%2,%3}, [%4];"
                 : "=r"(r[0]), "=r"(r[1]), "=r"(r[2]), "=r"(r[3]) : "r"(addr));
}

// 64B rows (32 halves): 16B-chunk swizzle for ldmatrix conflict-freedom.
#define SWZ(row, cb) ((uint32_t)((cb) ^ ((((row) >> 1) & 3) << 4)))
// 128B rows (64 halves): chunk index XOR row&7 (8 distinct slots per phase).
#define SWZ128(row, c) ((uint32_t)(16 * ((c) ^ ((row) & 7))))

// ------------------------ GEMM: pure-half operands --------------------------
// 3-stage cp.async pipeline, swizzled 64B-row smem, 1 barrier/tile.
// NMT = m-tiles (16 rows) per warp -> BM = 64*NMT. NT*16 = BN.
// NOBL=1: skip weight-lo — 2-pass mode (vocab only).
template <int NMT, int NT, int NOBL>
__global__ __launch_bounds__(256) void gemm_h(
    const __half* __restrict__ Ah, const __half* __restrict__ Al,
    const __half* __restrict__ Bh, const __half* __restrict__ Bl,
    float* __restrict__ C, __half* __restrict__ Ch, __half* __restrict__ Cl,
    const float* __restrict__ bias, const float* __restrict__ res,
    int M, int N, int K, int lda, int ldb, int ldc,
    long long aS1, long long aS2, int aDiv,
    long long bS1, long long bS2, int bDiv,
    long long cS1, long long cS2, int cDiv,
    float alpha, int flags)
{
    constexpr int BM   = 64 * NMT;
    constexpr int BN   = NT * 16;
    constexpr int AARR = BM * 64;
    constexpr int BARR = BN * 64;
    constexpr int STG  = 2 * AARR + 2 * BARR;

    extern __shared__ char smh[];
    const int m0 = blockIdx.y * BM, n0 = blockIdx.x * BN;
    if ((flags & 2) && n0 >= m0 + BM) return;

    const int z = blockIdx.z;
    const long long aOff = (long long)(z / aDiv) * aS1 + (long long)(z % aDiv) * aS2;
    const long long bOff = (long long)(z / bDiv) * bS1 + (long long)(z % bDiv) * bS2;
    const long long cOff = (long long)(z / cDiv) * cS1 + (long long)(z % cDiv) * cS2;
    const __half* Ahb = Ah + aOff;
    const __half* Alb = Al + aOff;
    const __half* Bhb = Bh + bOff;
    const __half* Blb = Bl + bOff;

    const uint32_t sb = (uint32_t)__cvta_generic_to_shared(smh);
    const int tid = threadIdx.x;
    const int wid = tid >> 5, lane = tid & 31;
    const int wm = wid & 3, wn = wid >> 2;
    const int g = lane >> 2, t = lane & 3;

    const int aRow = lane & 15, aChk = lane >> 4;
    const int bRow = (lane & 7) + ((lane >> 4) << 3);
    const int bChk = (lane >> 3) & 1;

    uint32_t aBase[NMT], aXor[NMT];
#pragma unroll
    for (int mt = 0; mt < NMT; mt++) {
        int r = wm * (16 * NMT) + mt * 16 + aRow;
        aBase[mt] = (uint32_t)(r * 64);
        aXor[mt]  = (uint32_t)(((r >> 1) & 3) << 4);
    }
    uint32_t bBase[NT / 2], bXor[NT / 2];
#pragma unroll
    for (int p = 0; p < NT / 2; p++) {
        int r = wn * (NT * 8) + p * 16 + bRow;
        bBase[p] = (uint32_t)(r * 64);
        bXor[p]  = (uint32_t)(((r >> 1) & 3) << 4);
    }

    float acc[NMT][NT][4];
#pragma unroll
    for (int i = 0; i < NMT; i++)
#pragma unroll
        for (int j = 0; j < NT; j++)
#pragma unroll
            for (int r = 0; r < 4; r++) acc[i][j][r] = 0.f;

    const int T = K >> 5;

    auto stage = [&](int it, int buf) {
        const int k0 = it << 5;
        uint32_t dst = sb + buf * STG;
#pragma unroll
        for (int j = 0; j < NMT; j++) {
            int idx = tid + (j << 8);
            int row = idx >> 2, c = idx & 3;
            long long asrc = (long long)(m0 + row) * lda + k0 + c * 8;
            uint32_t so = (uint32_t)(row * 64) + SWZ(row, c * 16);
            cpasync16(dst + 0 * AARR + so, Ahb + asrc);
            cpasync16(dst + 1 * AARR + so, Alb + asrc);
        }
#pragma unroll
        for (int j = 0; j < NT / 4; j++) {
            int idx = tid + (j << 8);
            int row = idx >> 2, c = idx & 3;
            long long bsrc = (long long)(n0 + row) * ldb + k0 + c * 8;
            uint32_t so = (uint32_t)(row * 64) + SWZ(row, c * 16);
            cpasync16(dst + 2 * AARR + so, Bhb + bsrc);
            if (!NOBL) cpasync16(dst + 2 * AARR + BARR + so, Blb + bsrc);
        }
    };

    stage(0, 0); cpcommit();
    stage(1, 1); cpcommit();

    for (int it = 0; it < T; ++it) {
        if (it + 1 < T) cpwait<1>(); else cpwait<0>();
        __syncthreads();

        const uint32_t base = sb + (uint32_t)(it % 3) * STG;
        const uint32_t aHb0 = base + 0 * AARR;
        const uint32_t aLb0 = base + 1 * AARR;
        const uint32_t bHb0 = base + 2 * AARR;
        const uint32_t bLb0 = base + 2 * AARR + BARR;

#pragma unroll
        for (int kk = 0; kk < 2; kk++) {
            const uint32_t cbA = (uint32_t)(aChk * 16 + kk * 32);
            const uint32_t cbB = (uint32_t)(bChk * 16 + kk * 32);
            uint32_t ah[NMT][4], al[NMT][4];
#pragma unroll
            for (int mt = 0; mt < NMT; mt++) {
                uint32_t off = aBase[mt] + (cbA ^ aXor[mt]);
                ldsm4(ah[mt], aHb0 + off);
                ldsm4(al[mt], aLb0 + off);
            }
            uint32_t bh[NT / 2][4], bl[NT / 2][4];
#pragma unroll
            for (int p = 0; p < NT / 2; p++) {
                uint32_t off = bBase[p] + (cbB ^ bXor[p]);
                ldsm4(bh[p], bHb0 + off);
                if (!NOBL) ldsm4(bl[p], bLb0 + off);
            }
            // pass 1: ah*bh
#pragma unroll
            for (int mt = 0; mt < NMT; mt++)
#pragma unroll
                for (int p = 0; p < NT / 2; p++) {
                    mma16(acc[mt][2*p],   ah[mt], &bh[p][0]);
                    mma16(acc[mt][2*p+1], ah[mt], &bh[p][2]);
                }
            // pass 2: al*bh
#pragma unroll
            for (int mt = 0; mt < NMT; mt++)
#pragma unroll
                for (int p = 0; p < NT / 2; p++) {
                    mma16(acc[mt][2*p],   al[mt], &bh[p][0]);
                    mma16(acc[mt][2*p+1], al[mt], &bh[p][2]);
                }
            // pass 3: ah*bl
            if (!NOBL) {
#pragma unroll
                for (int mt = 0; mt < NMT; mt++)
#pragma unroll
                    for (int p = 0; p < NT / 2; p++) {
                        mma16(acc[mt][2*p],   ah[mt], &bl[p][0]);
                        mma16(acc[mt][2*p+1], ah[mt], &bl[p][2]);
                    }
            }
        }

        if (it + 2 < T) { stage(it + 2, (it + 2) % 3); cpcommit(); }
    }

    const bool relu = flags & 1;
#pragma unroll
    for (int mt = 0; mt < NMT; mt++) {
#pragma unroll
        for (int hrow = 0; hrow < 2; hrow++) {
            int m = m0 + wm * (16 * NMT) + mt * 16 + g + hrow * 8;
            long long rowo = cOff + (long long)m * ldc;
#pragma unroll
            for (int nt = 0; nt < NT; nt++) {
                int n = n0 + wn * (NT * 8) + nt * 8 + 2 * t;
                if (n < N) {
                    float v0 = acc[mt][nt][hrow * 2 + 0] * alpha;
                    float v1 = acc[mt][nt][hrow * 2 + 1] * alpha;
                    if (bias) { v0 += bias[n]; v1 += bias[n + 1]; }
                    if (res) {
                        const float* rp = res + rowo;
                        v0 += rp[n]; v1 += rp[n + 1];
                    }
                    if (relu) { v0 = fmaxf(v0, 0.f); v1 = fmaxf(v1, 0.f); }
                    if (C) {
                        float2 vv; vv.x = v0; vv.y = v1;
                        *(float2*)(C + rowo + n) = vv;
                    }
                    if (Ch) {
                        uint32_t hi, lo;
                        split2(make_float2(v0, v1), hi, lo);
                        *(uint32_t*)(Ch + rowo + n) = hi;
                        *(uint32_t*)(Cl + rowo + n) = lo;
                    }
                }
            }
        }
    }
}

#define GH_SMEM8  (3 * (2 * 128 * 64 + 2 * 128 * 64))   // 98304 (NMT=2, NT=8)
#define GH_SMEM14 (3 * (2 * 64 * 64 + 2 * 64 * 64))     // 49152 (NMT=1, NT=4)

// ------------------- fused flash attention ---------------------------------
#define FA_QH 0
#define FA_QL 16384
#define FA_K0 32768
#define FA_V0 98304
#define FA_SMEM 167936

__global__ __launch_bounds__(256, 1) void fused_attn(
    const __half* __restrict__ qkvh, const __half* __restrict__ qkvl,
    const float* __restrict__ qkv,
    __half* __restrict__ Ch, __half* __restrict__ Cl,
    int causal)
{
    extern __shared__ char smf[];
    const uint32_t sb = (uint32_t)__cvta_generic_to_shared(smf);
    const int z = blockIdx.z;
    const int b = z >> 3, h = z & 7;
    const int mt = blockIdx.x;
    const int m0 = mt * 128;
    const long long tokb = (long long)b * 512;
    const int tid = threadIdx.x, wid = tid >> 5, lane = tid & 31;
    const int g = lane >> 2, t = lane & 3;
    const int aRow = lane & 15, aChk = lane >> 4;
    const int bRow = (lane & 7) + ((lane >> 4) << 3);
    const int bChk = (lane >> 3) & 1;

#pragma unroll
    for (int j = 0; j < 4; j++) {
        int idx = tid + (j << 8);
        int r = idx >> 3, c = idx & 7;
        long long src = (tokb + m0 + r) * 1536 + h * 64 + c * 8;
        uint32_t so = (uint32_t)(r * 128) + SWZ128(r, c);
        cpasync16(sb + FA_QH + so, qkvh + src);
        cpasync16(sb + FA_QL + so, qkvl + src);
    }
    cpcommit();

    auto stageKV = [&](int kt, int buf) {
        uint32_t kdst = sb + FA_K0 + (uint32_t)buf * 32768u;
#pragma unroll
        for (int j = 0; j < 4; j++) {
            int idx = tid + (j << 8);
            int r = idx >> 3, c = idx & 7;
            long long src = (tokb + kt * 128 + r) * 1536 + 512 + h * 64 + c * 8;
            uint32_t so = (uint32_t)(r * 128) + SWZ128(r, c);
            cpasync16(kdst + so, qkvh + src);
            cpasync16(kdst + 16384 + so, qkvl + src);
        }
        uint32_t vdst = sb + FA_V0 + (uint32_t)buf * 34816u;
#pragma unroll
        for (int j = 0; j < 8; j++) {
            int idx = tid + (j << 8);
            int r = idx >> 4, c = idx & 15;
            long long src = (tokb + kt * 128 + r) * 1536 + 1024 + h * 64 + c * 4;
            cpasync16(vdst + (uint32_t)((r * 68 + c * 4) * 4), qkv + src);
        }
    };

    stageKV(0, 0); cpcommit();

    cpwait<1>();
    __syncthreads();
    uint32_t qh[4][4], ql[4][4];
    {
        int r = wid * 16 + aRow;
        uint32_t qb = (uint32_t)(r * 128);
#pragma unroll
        for (int kc = 0; kc < 4; kc++) {
            uint32_t cb = SWZ128(r, kc * 2 + aChk);
            ldsm4(qh[kc], sb + FA_QH + qb + cb);
            ldsm4(ql[kc], sb + FA_QL + qb + cb);
        }
    }

    float accO[8][4];
#pragma unroll
    for (int nt = 0; nt < 8; nt++)
#pragma unroll
        for (int r = 0; r < 4; r++) accO[nt][r] = 0.f;
    float Mg = -1e30f, Mg8 = -1e30f, Lg = 0.f, Lg8 = 0.f;

    const int jmax = causal ? (mt + 1) : 4;

    for (int j = 0; j < jmax; j++) {
        if (j + 1 < jmax) { stageKV(j + 1, (j + 1) & 1); cpcommit(); cpwait<1>(); }
        else              { cpwait<0>(); }
        __syncthreads();

        const uint32_t kb = sb + FA_K0 + (uint32_t)(j & 1) * 32768u;
        const float* Vb = (const float*)(smf + FA_V0 + (size_t)(j & 1) * 34816u);

        float s[16][4];
#pragma unroll
        for (int nt = 0; nt < 16; nt++)
#pragma unroll
            for (int r = 0; r < 4; r++) s[nt][r] = 0.f;

#pragma unroll
        for (int kc = 0; kc < 4; kc++) {
#pragma unroll
            for (int p = 0; p < 8; p++) {
                int r = p * 16 + bRow;
                uint32_t off = (uint32_t)(r * 128) + SWZ128(r, kc * 2 + bChk);
                uint32_t bh4[4], bl4[4];
                ldsm4(bh4, kb + off);
                ldsm4(bl4, kb + 16384 + off);
                mma16(s[2*p],   qh[kc], &bh4[0]);
                mma16(s[2*p+1], qh[kc], &bh4[2]);
                mma16(s[2*p],   ql[kc], &bh4[0]);
                mma16(s[2*p+1], ql[kc], &bh4[2]);
                mma16(s[2*p],   qh[kc], &bl4[0]);
                mma16(s[2*p+1], qh[kc], &bl4[2]);
            }
        }
#pragma unroll
        for (int nt = 0; nt < 16; nt++)
#pragma unroll
            for (int r = 0; r < 4; r++) s[nt][r] *= 0.125f;

        if (causal && j == mt) {
            int rg = m0 + wid * 16 + g;
#pragma unroll
            for (int nt = 0; nt < 16; nt++) {
                int cb0 = j * 128 + nt * 8 + 2 * t;
                if (cb0     > rg)     s[nt][0] = -1e30f;
                if (cb0 + 1 > rg)     s[nt][1] = -1e30f;
                if (cb0     > rg + 8) s[nt][2] = -1e30f;
                if (cb0 + 1 > rg + 8) s[nt][3] = -1e30f;
            }
        }

        float mg = -1e30f, mg8 = -1e30f;
#pragma unroll
        for (int nt = 0; nt < 16; nt++) {
            mg  = fmaxf(mg,  fmaxf(s[nt][0], s[nt][1]));
            mg8 = fmaxf(mg8, fmaxf(s[nt][2], s[nt][3]));
        }
        mg  = fmaxf(mg,  __shfl_xor_sync(0xffffffff, mg, 1));
        mg  = fmaxf(mg,  __shfl_xor_sync(0xffffffff, mg, 2));
        mg8 = fmaxf(mg8, __shfl_xor_sync(0xffffffff, mg8, 1));
        mg8 = fmaxf(mg8, __shfl_xor_sync(0xffffffff, mg8, 2));
        float Mn  = fmaxf(Mg,  mg);
        float Mn8 = fmaxf(Mg8, mg8);
        float f  = __expf(Mg  - Mn);
        float f8 = __expf(Mg8 - Mn8);
        Mg = Mn; Mg8 = Mn8;
        Lg *= f; Lg8 *= f8;
#pragma unroll
        for (int nt = 0; nt < 8; nt++) {
            accO[nt][0] *= f;  accO[nt][1] *= f;
            accO[nt][2] *= f8; accO[nt][3] *= f8;
        }

        uint32_t pa[8][4];
#pragma unroll
        for (int kc2 = 0; kc2 < 8; kc2++) {
            float p00 = __expf(s[2*kc2][0]   - Mg);
            float p01 = __expf(s[2*kc2][1]   - Mg);
            float p02 = __expf(s[2*kc2][2]   - Mg8);
            float p03 = __expf(s[2*kc2][3]   - Mg8);
            float p10 = __expf(s[2*kc2+1][0] - Mg);
            float p11 = __expf(s[2*kc2+1][1] - Mg);
            float p12 = __expf(s[2*kc2+1][2] - Mg8);
            float p13 = __expf(s[2*kc2+1][3] - Mg8);
            Lg  += p00 + p01 + p10 + p11;
            Lg8 += p02 + p03 + p12 + p13;
            __half2 h0 = __floats2half2_rn(p00, p01);
            __half2 h1 = __floats2half2_rn(p02, p03);
            __half2 h2v = __floats2half2_rn(p10, p11);
            __half2 h3 = __floats2half2_rn(p12, p13);
            pa[kc2][0] = *(uint32_t*)&h0;
            pa[kc2][1] = *(uint32_t*)&h1;
            pa[kc2][2] = *(uint32_t*)&h2v;
            pa[kc2][3] = *(uint32_t*)&h3;
        }

#pragma unroll
        for (int kc2 = 0; kc2 < 8; kc2++) {
            uint32_t bv[8][2], bw[8][2];
#pragma unroll
            for (int nt = 0; nt < 8; nt++) {
                const float* base = Vb + (kc2 * 16 + 2 * t) * 68 + nt * 8 + g;
                uint32_t bh0, bl0, bh1, bl1;
                split2(make_float2(base[0],      base[68]),     bh0, bl0);
                split2(make_float2(base[8 * 68], base[9 * 68]), bh1, bl1);
                bv[nt][0] = bh0; bv[nt][1] = bh1;
                bw[nt][0] = bl0; bw[nt][1] = bl1;
            }
#pragma unroll
            for (int nt = 0; nt < 8; nt++) mma16(accO[nt], pa[kc2], bv[nt]);
#pragma unroll
            for (int nt = 0; nt < 8; nt++) mma16(accO[nt], pa[kc2], bw[nt]);
        }
        __syncthreads();
    }

    Lg  += __shfl_xor_sync(0xffffffff, Lg, 1);
    Lg  += __shfl_xor_sync(0xffffffff, Lg, 2);
    Lg8 += __shfl_xor_sync(0xffffffff, Lg8, 1);
    Lg8 += __shfl_xor_sync(0xffffffff, Lg8, 2);
    float invg  = 1.f / Lg;
    float invg8 = 1.f / Lg8;

    long long row0 = (tokb + m0 + wid * 16 + g) * 512 + h * 64;
    long long row8 = row0 + 8LL * 512;
#pragma unroll
    for (int nt = 0; nt < 8; nt++) {
        int n = nt * 8 + 2 * t;
        uint32_t hi, lo;
        split2(make_float2(accO[nt][0] * invg, accO[nt][1] * invg), hi, lo);
        *(uint32_t*)(Ch + row0 + n) = hi;
        *(uint32_t*)(Cl + row0 + n) = lo;
        split2(make_float2(accO[nt][2] * invg8, accO[nt][3] * invg8), hi, lo);
        *(uint32_t*)(Ch + row8 + n) = hi;
        *(uint32_t*)(Cl + row8 + n) = lo;
    }
}

// --------------------------- conversion kernels -----------------------------
__global__ void convw_kernel(const float* __restrict__ W,
                             __half* __restrict__ hi, __half* __restrict__ lo,
                             int K, int N, int Npad, long long inS, long long outS)
{
    __shared__ float tile[32][65];
    int z = blockIdx.z;
    const float* Wz = W + (long long)z * inS;
    int k0 = blockIdx.y * 32, n0 = blockIdx.x * 64;
    int tid = threadIdx.x;

#pragma unroll
    for (int j = 0; j < 2; j++) {
        int idx = tid + (j << 8);
        int k = idx >> 4, nq = (idx & 15) << 2;
        int n = n0 + nq;
        float4 v = make_float4(0.f, 0.f, 0.f, 0.f);
        const float* p = Wz + (long long)(k0 + k) * N;
        if (n + 3 < N) v = *(const float4*)(p + n);
        else {
            if (n + 0 < N) v.x = p[n + 0];
            if (n + 1 < N) v.y = p[n + 1];
            if (n + 2 < N) v.z = p[n + 2];
            if (n + 3 < N) v.w = p[n + 3];
        }
        tile[k][nq + 0] = v.x; tile[k][nq + 1] = v.y;
        tile[k][nq + 2] = v.z; tile[k][nq + 3] = v.w;
    }
    __syncthreads();

#pragma unroll
    for (int j = 0; j < 4; j++) {
        int idx = tid + (j << 8);
        int n = idx >> 4, tq = (idx & 15) << 1;
        int gn = n0 + n;
        if (gn < Npad) {
            float v0 = tile[tq][n], v1 = tile[tq + 1][n];
            __half2 h = __floats2half2_rn(v0, v1);
            long long o = (long long)z * outS + (long long)gn * K + k0 + tq;
            *(__half2*)(hi + o) = h;
            if (lo) {
                float2 hf = __half22float2(h);
                __half2 l = __floats2half2_rn(v0 - hf.x, v1 - hf.y);
                *(__half2*)(lo + o) = l;
            }
        }
    }
}

__global__ void convqkv_kernel(const float* __restrict__ Wq, const float* __restrict__ Wk,
                               const float* __restrict__ Wv,
                               __half* __restrict__ hi, __half* __restrict__ lo)
{
    __shared__ float tile[32][65];
    int kt = blockIdx.x, sh = blockIdx.y;
    int sel = sh >> 3, h = sh & 7;
    const float* W = (sel == 0) ? Wq : (sel == 1) ? Wk : Wv;
    const float* src = W + ((long long)h * 512 + kt * 32) * 64;
    int tid = threadIdx.x;

#pragma unroll
    for (int j = 0; j < 2; j++) {
        int idx = tid + (j << 8);
        int k = idx >> 4, eq = (idx & 15) << 2;
        float4 v = *(const float4*)(src + k * 64 + eq);
        tile[k][eq + 0] = v.x; tile[k][eq + 1] = v.y;
        tile[k][eq + 2] = v.z; tile[k][eq + 3] = v.w;
    }
    __syncthreads();

#pragma unroll
    for (int j = 0; j < 4; j++) {
        int idx = tid + (j << 8);
        int e = idx >> 4, tq = (idx & 15) << 1;
        int n = sel * 512 + h * 64 + e;
        float v0 = tile[tq][e], v1 = tile[tq + 1][e];
        __half2 hh = __floats2half2_rn(v0, v1);
        float2 hf = __half22float2(hh);
        __half2 ll = __floats2half2_rn(v0 - hf.x, v1 - hf.y);
        long long o = (long long)n * 512 + kt * 32 + tq;
        *(__half2*)(hi + o) = hh;
        *(__half2*)(lo + o) = ll;
    }
}

__global__ void conva_kernel(const float* __restrict__ src,
                             __half* __restrict__ hi, __half* __restrict__ lo, int n) {
    int i = blockIdx.x * 256 + threadIdx.x;
    if (i < n) {
        float v = src[i];
        __half h = __float2half_rn(v);
        hi[i] = h;
        lo[i] = __float2half_rn(v - __half2float(h));
    }
}

// --------------------------- elementwise kernels ---------------------------
__global__ void embed_kernel(const int* __restrict__ tok, const float* __restrict__ emb,
                             float* __restrict__ x,
                             __half* __restrict__ xh, __half* __restrict__ xl) {
    int idx = blockIdx.x * 256 + threadIdx.x;
    int t = tok[idx >> 9];
    float v = emb[(long long)t * Dm_ + (idx & 511)] * 8.0f;
    x[idx] = v;
    __half h = __float2half_rn(v);
    xh[idx] = h;
    xl[idx] = __float2half_rn(v - __half2float(h));
}

__global__ void bn_stats_kernel(const float* __restrict__ x,
                                float* __restrict__ mu, float* __restrict__ rstd) {
    int d = blockIdx.x * 32 + threadIdx.x;
    float s = 0.f, s2 = 0.f;
    for (int i = threadIdx.y; i < BS_; i += 8) {
        float v = x[(long long)i * Dm_ + d];
        s += v; s2 += v * v;
    }
    __shared__ float sh[8][33], sh2[8][33];
    sh[threadIdx.y][threadIdx.x] = s;
    sh2[threadIdx.y][threadIdx.x] = s2;
    __syncthreads();
    if (threadIdx.y == 0) {
#pragma unroll
        for (int r = 1; r < 8; r++) { s += sh[r][threadIdx.x]; s2 += sh2[r][threadIdx.x]; }
        float m = s * (1.f / BS_);
        float var = s2 * (1.f / BS_) - m * m;
        mu[d] = m;
        rstd[d] = rsqrtf(var + 1e-5f);
    }
}

__global__ void bn_apply_kernel(const float* __restrict__ xin, float* __restrict__ xout,
                                __half* __restrict__ xh, __half* __restrict__ xl,
                                const float* __restrict__ mu, const float* __restrict__ rstd,
                                const float* __restrict__ gamma, const float* __restrict__ beta) {
    int idx = blockIdx.x * 256 + threadIdx.x;
    int d = idx & 511;
    float v = (xin[idx] - mu[d]) * rstd[d] * gamma[d] + beta[d];
    xout[idx] = v;
    __half h = __float2half_rn(v);
    xh[idx] = h;
    xl[idx] = __float2half_rn(v - __half2float(h));
}

// Vocab softmax (register-resident, launch-bounded)
#define VITER 37
__global__ __launch_bounds__(1024, 1) void softmax_vocab_kernel(float* __restrict__ p, int T) {
    __shared__ float red[1024];
    long long row = blockIdx.x;
    float* x = p + row * (long long)T;
    int tid = threadIdx.x;

    float vals[VITER];
    float m = -1e30f;
#pragma unroll
    for (int j = 0; j < VITER; j++) {
        int t = tid + j * 1024;
        float v = (t < T) ? x[t] : -1e30f;
        vals[j] = v;
        m = fmaxf(m, v);
    }
    red[tid] = m; __syncthreads();
    for (int o = 512; o > 0; o >>= 1) {
        if (tid < o) red[tid] = fmaxf(red[tid], red[tid + o]);
        __syncthreads();
    }
    float M = red[0]; __syncthreads();

    float sum = 0.f;
#pragma unroll
    for (int j = 0; j < VITER; j++) {
        int t = tid + j * 1024;
        if (t < T) { vals[j] = __expf(vals[j] - M); sum += vals[j]; }
    }
    red[tid] = sum; __syncthreads();
    for (int o = 512; o > 0; o >>= 1) {
        if (tid < o) red[tid] += red[tid + o];
        __syncthreads();
    }
    float inv = 1.f / red[0];
#pragma unroll
    for (int j = 0; j < VITER; j++) {
        int t = tid + j * 1024;
        if (t < T) x[t] = vals[j] * inv;
    }
}

// ------------------------------- host side ---------------------------------
static inline int cdiv(int a, int b) { return (a + b - 1) / b; }

static void gh8(const __half* Ah, const __half* Al, const __half* Bh, const __half* Bl,
                float* C, __half* Ch, __half* Cl,
                const float* bias, const float* res,
                int M, int N, int K, int lda, int ldb, int ldc, int flags)
{
    dim3 g(cdiv(N, 128), M / 128, 1);
    gemm_h<2,8,0><<<g, 256, GH_SMEM8>>>(Ah, Al, Bh, Bl, C, Ch, Cl, bias, res,
                                        M, N, K, lda, ldb, ldc,
                                        0, 0, 1, 0, 0, 1, 0, 0, 1, 1.f, flags);
}
// BM=64, BN=64: N=512 shapes -> 8 x 32 = 256 CTAs (full chip)
static void gh14(const __half* Ah, const __half* Al, const __half* Bh, const __half* Bl,
                 float* C, __half* Ch, __half* Cl,
                 const float* bias, const float* res,
                 int M, int N, int K, int lda, int ldb, int ldc, int flags)
{
    dim3 g(cdiv(N, 64), M / 64, 1);
    gemm_h<1,4,0><<<g, 256, GH_SMEM14>>>(Ah, Al, Bh, Bl, C, Ch, Cl, bias, res,
                                         M, N, K, lda, ldb, ldc,
                                         0, 0, 1, 0, 0, 1, 0, 0, 1, 1.f, flags);
}

extern "C" void kernel_launch(void* const* d_in, const int* in_sizes, int n_in,
                              void* d_out, int out_size)
{
    const int*   tok   = (const int*)  d_in[0];
    const float* enc   = (const float*)d_in[1];
    const float* emb   = (const float*)d_in[2];
    const float* Wq1   = (const float*)d_in[3];
    const float* Wk1   = (const float*)d_in[4];
    const float* Wv1   = (const float*)d_in[5];
    const float* Wo1   = (const float*)d_in[6];
    const float* Wq2   = (const float*)d_in[7];
    const float* Wk2   = (const float*)d_in[8];
    const float* Wv2   = (const float*)d_in[9];
    const float* Wo2   = (const float*)d_in[10];
    const float* gamma = (const float*)d_in[11];
    const float* beta  = (const float*)d_in[12];
    const float* W1    = (const float*)d_in[13];
    const float* b1    = (const float*)d_in[14];
    const float* W2    = (const float*)d_in[15];
    const float* b2    = (const float*)d_in[16];
    const float* Wout  = (const float*)d_in[17];
    const float* bout  = (const float*)d_in[18];
    float* out = (float*)d_out;

    cudaFuncSetAttribute((const void*)gemm_h<2,8,0>, cudaFuncAttributeMaxDynamicSharedMemorySize, GH_SMEM8);
    cudaFuncSetAttribute((const void*)gemm_h<2,8,1>, cudaFuncAttributeMaxDynamicSharedMemorySize, GH_SMEM8);
    cudaFuncSetAttribute((const void*)gemm_h<1,4,0>, cudaFuncAttributeMaxDynamicSharedMemorySize, GH_SMEM14);
    cudaFuncSetAttribute((const void*)fused_attn,    cudaFuncAttributeMaxDynamicSharedMemorySize, FA_SMEM);

    float *x, *tmp, *qkv, *mu, *rstd;
    cudaGetSymbolAddress((void**)&x,    g_x);
    cudaGetSymbolAddress((void**)&tmp,  g_tmp);
    cudaGetSymbolAddress((void**)&qkv,  g_qkv);
    cudaGetSymbolAddress((void**)&mu,   g_mu);
    cudaGetSymbolAddress((void**)&rstd, g_rstd);

    __half *xh, *xl, *qkvh, *qkvl, *attnh, *attnl, *ffh, *ffl, *ench, *encl;
    cudaGetSymbolAddress((void**)&xh,    g_xh);
    cudaGetSymbolAddress((void**)&xl,    g_xl);
    cudaGetSymbolAddress((void**)&qkvh,  g_qkvh);
    cudaGetSymbolAddress((void**)&qkvl,  g_qkvl);
    cudaGetSymbolAddress((void**)&attnh, g_attnh);
    cudaGetSymbolAddress((void**)&attnl, g_attnl);
    cudaGetSymbolAddress((void**)&ffh,   g_ffh);
    cudaGetSymbolAddress((void**)&ffl,   g_ffl);
    cudaGetSymbolAddress((void**)&ench,  g_ench);
    cudaGetSymbolAddress((void**)&encl,  g_encl);

    __half *wtT_h, *wtT_l, *w1T_h, *w1T_l, *w2T_h, *w2T_l;
    __half *wo1T_h, *wo1T_l, *wo2T_h, *wo2T_l, *woutT_h;
    cudaGetSymbolAddress((void**)&wtT_h,  g_wtT_h);
    cudaGetSymbolAddress((void**)&wtT_l,  g_wtT_l);
    cudaGetSymbolAddress((void**)&w1T_h,  g_w1T_h);
    cudaGetSymbolAddress((void**)&w1T_l,  g_w1T_l);
    cudaGetSymbolAddress((void**)&w2T_h,  g_w2T_h);
    cudaGetSymbolAddress((void**)&w2T_l,  g_w2T_l);
    cudaGetSymbolAddress((void**)&wo1T_h, g_wo1T_h);
    cudaGetSymbolAddress((void**)&wo1T_l, g_wo1T_l);
    cudaGetSymbolAddress((void**)&wo2T_h, g_wo2T_h);
    cudaGetSymbolAddress((void**)&wo2T_l, g_wo2T_l);
    cudaGetSymbolAddress((void**)&woutT_h, g_woutT_h);

    const long long HW = (long long)Dm_ * Dk_;

    // ---- conversions ----
    convqkv_kernel<<<dim3(16, 24), 256>>>(Wq1, Wk1, Wv1, wtT_h, wtT_l);
    conva_kernel<<<cdiv(BS_*Dm_, 256), 256>>>(enc, ench, encl, BS_*Dm_);
    embed_kernel<<<BS_ * Dm_ / 256, 256>>>(tok, emb, x, xh, xl);
    convw_kernel<<<dim3(Ff_/64, Dm_/32, Nx_), 256>>>(W1, w1T_h, w1T_l, Dm_, Ff_, Ff_,
                                                     (long long)Dm_*Ff_, (long long)Ff_*Dm_);
    convw_kernel<<<dim3(Dm_/64, Ff_/32, Nx_), 256>>>(W2, w2T_h, w2T_l, Ff_, Dm_, Dm_,
                                                     (long long)Ff_*Dm_, (long long)Dm_*Ff_);
    gh8(xh, xl, wtT_h, wtT_l, qkv, qkvh, qkvl, nullptr, nullptr,
        BS_, 1536, Dm_, Dm_, Dm_, 1536, 0);
    for (int s = 1; s < 12; s++) {
        int i = s >> 1, pass = s & 1;
        const float* wq = pass ? Wq2 : Wq1;
        const float* wk = pass ? Wk2 : Wk1;
        const float* wv = pass ? Wv2 : Wv1;
        convqkv_kernel<<<dim3(16, 24), 256>>>(wq + (long long)i*Hh_*HW,
                                              wk + (long long)i*Hh_*HW,
                                              wv + (long long)i*Hh_*HW,
                                              wtT_h + (long long)s*1536*512,
                                              wtT_l + (long long)s*1536*512);
    }
    convw_kernel<<<dim3(Dm_/64, Dm_/32, Nx_), 256>>>(Wo1, wo1T_h, wo1T_l, Dm_, Dm_, Dm_,
                                                     (long long)Dm_*Dm_, (long long)Dm_*Dm_);
    convw_kernel<<<dim3(Dm_/64, Dm_/32, Nx_), 256>>>(Wo2, wo2T_h, wo2T_l, Dm_, Dm_, Dm_,
                                                     (long long)Dm_*Dm_, (long long)Dm_*Dm_);
    convw_kernel<<<dim3(VvP_/64, Dm_/32, 1), 256>>>(Wout, woutT_h, nullptr, Dm_, Vv_, VvP_, 0, 0);

    for (int i = 0; i < Nx_; i++) {
        const float* bb1 = b1 + (long long)i * Ff_;
        const float* bb2 = b2 + (long long)i * Dm_;

        for (int attn_pass = 0; attn_pass < 2; attn_pass++) {
            const int self = (attn_pass == 0);
            const int s = i * 2 + attn_pass;
            const __half* wth = wtT_h + (long long)s * 1536 * 512;
            const __half* wtl = wtT_l + (long long)s * 1536 * 512;

            if (self) {
                if (i != 0)
                    gh8(xh, xl, wth, wtl, qkv, qkvh, qkvl, nullptr, nullptr,
                        BS_, 1536, Dm_, Dm_, Dm_, 1536, 0);
            } else {
                // Q projection: N=512 -> BM=64 variant (256 CTAs)
                gh14(xh, xl, wth, wtl, qkv, qkvh, qkvl, nullptr, nullptr,
                     BS_, 512, Dm_, Dm_, Dm_, 1536, 0);
                dim3 g(8, 16, 1);
                gemm_h<2,8,0><<<g, 256, GH_SMEM8>>>(ench, encl,
                                                    wth + 512LL*512, wtl + 512LL*512,
                                                    qkv + 512, qkvh + 512, qkvl + 512,
                                                    nullptr, nullptr,
                                                    BS_, 1024, Dm_, Dm_, Dm_, 1536,
                                                    0, 0, 1, 0, 0, 1, 0, 0, 1, 1.f, 0);
            }
            // ---- fused attention ----
            {
                dim3 g(4, 1, Bb_ * Hh_);
                fused_attn<<<g, 256, FA_SMEM>>>(qkvh, qkvl, qkv, attnh, attnl,
                                                self ? 1 : 0);
            }
            // tmp = attn @ Wo + x  (BM=64 variant)
            const __half* woh = (self ? wo1T_h : wo2T_h) + (long long)i*512*512;
            const __half* wol = (self ? wo1T_l : wo2T_l) + (long long)i*512*512;
            gh14(attnh, attnl, woh, wol, tmp, nullptr, nullptr, nullptr, x,
                 BS_, Dm_, Dm_, Dm_, Dm_, Dm_, 0);
            bn_stats_kernel<<<Dm_/32, dim3(32, 8)>>>(tmp, mu, rstd);
            bn_apply_kernel<<<BS_*Dm_/256, 256>>>(tmp, x, xh, xl, mu, rstd,
                                                  gamma + (long long)(i*3 + attn_pass)*Dm_,
                                                  beta  + (long long)(i*3 + attn_pass)*Dm_);
        }

        // ---- feed-forward
        gh8(xh, xl, w1T_h + (long long)i*Ff_*512, w1T_l + (long long)i*Ff_*512,
            nullptr, ffh, ffl, bb1, nullptr, BS_, Ff_, Dm_, Dm_, Dm_, Ff_, 1);
        gh14(ffh, ffl, w2T_h + (long long)i*512LL*Ff_, w2T_l + (long long)i*512LL*Ff_,
             tmp, nullptr, nullptr, bb2, x, BS_, Dm_, Ff_, Ff_, Ff_, Dm_, 0);
        bn_stats_kernel<<<Dm_/32, dim3(32, 8)>>>(tmp, mu, rstd);
        bn_apply_kernel<<<BS_*Dm_/256, 256>>>(tmp, x, xh, xl, mu, rstd,
                                              gamma + (long long)(i*3 + 2)*Dm_,
                                              beta  + (long long)(i*3 + 2)*Dm_);
    }

    // ---- output projection (2-pass) + vocab softmax
    {
        dim3 g(cdiv(Vv_, 128), BS_ / 128, 1);
        gemm_h<2,8,1><<<g, 256, GH_SMEM8>>>(xh, xl, woutT_h, woutT_h,
                                            out, nullptr, nullptr, bout, nullptr,
                                            BS_, Vv_, Dm_, Dm_, Dm_, Vv_,
                                            0, 0, 1, 0, 0, 1, 0, 0, 1, 1.f, 0);
    }
    softmax_vocab_kernel<<<BS_, 1024>>>(out, Vv_);

    (void)in_sizes; (void)n_in; (void)out_size;
}

// round 17
// speedup vs baseline: 1.9517x; 1.0443x over previous
#include <cuda_runtime.h>
#include <cuda_fp16.h>
#include <math.h>
#include <stdint.h>

// ---------------------------------------------------------------------------
// Decoder — Round 17: half-V attention via ldmatrix.trans; fp32 QKV removed
// ---------------------------------------------------------------------------

#define Bb_ 4
#define Ss_ 512
#define Dm_ 512
#define Hh_ 8
#define Dk_ 64
#define Ff_ 2048
#define Vv_ 37000
#define VvP_ 37120
#define Nx_ 6
#define BS_ 2048

// ------------------------- scratch (static device globals) -----------------
__device__ __align__(16) float g_x    [BS_*Dm_];
__device__ __align__(16) float g_tmp  [BS_*Dm_];
__device__ float g_mu   [Dm_];
__device__ float g_rstd [Dm_];

// hi/lo half activations
__device__ __align__(16) __half g_xh   [BS_*Dm_];
__device__ __align__(16) __half g_xl   [BS_*Dm_];
__device__ __align__(16) __half g_qkvh [BS_*3*Dm_];
__device__ __align__(16) __half g_qkvl [BS_*3*Dm_];
__device__ __align__(16) __half g_attnh[BS_*Dm_];
__device__ __align__(16) __half g_attnl[BS_*Dm_];
__device__ __align__(16) __half g_ffh  [BS_*Ff_];
__device__ __align__(16) __half g_ffl  [BS_*Ff_];
__device__ __align__(16) __half g_ench [BS_*Dm_];
__device__ __align__(16) __half g_encl [BS_*Dm_];

// hi/lo half weights, [N, K] K-major
__device__ __align__(16) __half g_wtT_h [12L*1536*512];
__device__ __align__(16) __half g_wtT_l [12L*1536*512];
__device__ __align__(16) __half g_w1T_h [6L*2048*512];
__device__ __align__(16) __half g_w1T_l [6L*2048*512];
__device__ __align__(16) __half g_w2T_h [6L*512*2048];
__device__ __align__(16) __half g_w2T_l [6L*512*2048];
__device__ __align__(16) __half g_wo1T_h[6L*512*512];
__device__ __align__(16) __half g_wo1T_l[6L*512*512];
__device__ __align__(16) __half g_wo2T_h[6L*512*512];
__device__ __align__(16) __half g_wo2T_l[6L*512*512];
__device__ __align__(16) __half g_woutT_h[(long long)VvP_*512];

// ------------------------------- helpers -----------------------------------
__device__ __forceinline__ void split2(float2 x, uint32_t& hi, uint32_t& lo) {
    __half2 h = __float22half2_rn(x);
    float2 hf = __half22float2(h);
    __half2 l = __float22half2_rn(make_float2(x.x - hf.x, x.y - hf.y));
    hi = *reinterpret_cast<uint32_t*>(&h);
    lo = *reinterpret_cast<uint32_t*>(&l);
}
__device__ __forceinline__ void cpasync16(uint32_t dst, const void* src) {
    asm volatile("cp.async.cg.shared.global [%0], [%1], 16;"
                 :: "r"(dst), "l"(src));
}
__device__ __forceinline__ void cpcommit() { asm volatile("cp.async.commit_group;"); }
template <int NN> __device__ __forceinline__ void cpwait() {
    asm volatile("cp.async.wait_group %0;" :: "n"(NN));
}
__device__ __forceinline__ void mma16(float* d, const uint32_t* a, const uint32_t* b) {
    asm volatile(
        "mma.sync.aligned.m16n8k16.row.col.f32.f16.f16.f32 "
        "{%0,%1,%2,%3}, {%4,%5,%6,%7}, {%8,%9}, {%0,%1,%2,%3};"
        : "+f"(d[0]), "+f"(d[1]), "+f"(d[2]), "+f"(d[3])
        : "r"(a[0]), "r"(a[1]), "r"(a[2]), "r"(a[3]), "r"(b[0]), "r"(b[1]));
}
__device__ __forceinline__ void ldsm4(uint32_t* r, uint32_t addr) {
    asm volatile("ldmatrix.sync.aligned.m8n8.x4.shared.b16 {%0,%1,%2,%3}, [%4];"
                 : "=r"(r[0]), "=r"(r[1]), "=r"(r[2]), "=r"(r[3]) : "r"(addr));
}
__device__ __forceinline__ void ldsm4t(uint32_t* r, uint32_t addr) {
    asm volatile("ldmatrix.sync.aligned.m8n8.x4.trans.shared.b16 {%0,%1,%2,%3}, [%4];"
                 : "=r"(r[0]), "=r"(r[1]), "=r"(r[2]), "=r"(r[3]) : "r"(addr));
}

// 64B rows (32 halves): 16B-chunk swizzle for ldmatrix conflict-freedom.
#define SWZ(row, cb) ((uint32_t)((cb) ^ ((((row) >> 1) & 3) << 4)))
// 128B rows (64 halves): chunk index XOR row&7 (8 distinct slots per phase).
#define SWZ128(row, c) ((uint32_t)(16 * ((c) ^ ((row) & 7))))

// ------------------------ GEMM: pure-half operands --------------------------
// 3-stage cp.async pipeline, swizzled 64B-row smem, 1 barrier/tile.
// NMT = m-tiles (16 rows) per warp -> BM = 64*NMT. NT*16 = BN.
// NOBL=1: skip weight-lo — 2-pass mode (vocab only).
template <int NMT, int NT, int NOBL>
__global__ __launch_bounds__(256) void gemm_h(
    const __half* __restrict__ Ah, const __half* __restrict__ Al,
    const __half* __restrict__ Bh, const __half* __restrict__ Bl,
    float* __restrict__ C, __half* __restrict__ Ch, __half* __restrict__ Cl,
    const float* __restrict__ bias, const float* __restrict__ res,
    int M, int N, int K, int lda, int ldb, int ldc,
    long long aS1, long long aS2, int aDiv,
    long long bS1, long long bS2, int bDiv,
    long long cS1, long long cS2, int cDiv,
    float alpha, int flags)
{
    constexpr int BM   = 64 * NMT;
    constexpr int BN   = NT * 16;
    constexpr int AARR = BM * 64;
    constexpr int BARR = BN * 64;
    constexpr int STG  = 2 * AARR + 2 * BARR;

    extern __shared__ char smh[];
    const int m0 = blockIdx.y * BM, n0 = blockIdx.x * BN;
    if ((flags & 2) && n0 >= m0 + BM) return;

    const int z = blockIdx.z;
    const long long aOff = (long long)(z / aDiv) * aS1 + (long long)(z % aDiv) * aS2;
    const long long bOff = (long long)(z / bDiv) * bS1 + (long long)(z % bDiv) * bS2;
    const long long cOff = (long long)(z / cDiv) * cS1 + (long long)(z % cDiv) * cS2;
    const __half* Ahb = Ah + aOff;
    const __half* Alb = Al + aOff;
    const __half* Bhb = Bh + bOff;
    const __half* Blb = Bl + bOff;

    const uint32_t sb = (uint32_t)__cvta_generic_to_shared(smh);
    const int tid = threadIdx.x;
    const int wid = tid >> 5, lane = tid & 31;
    const int wm = wid & 3, wn = wid >> 2;
    const int g = lane >> 2, t = lane & 3;

    const int aRow = lane & 15, aChk = lane >> 4;
    const int bRow = (lane & 7) + ((lane >> 4) << 3);
    const int bChk = (lane >> 3) & 1;

    uint32_t aBase[NMT], aXor[NMT];
#pragma unroll
    for (int mt = 0; mt < NMT; mt++) {
        int r = wm * (16 * NMT) + mt * 16 + aRow;
        aBase[mt] = (uint32_t)(r * 64);
        aXor[mt]  = (uint32_t)(((r >> 1) & 3) << 4);
    }
    uint32_t bBase[NT / 2], bXor[NT / 2];
#pragma unroll
    for (int p = 0; p < NT / 2; p++) {
        int r = wn * (NT * 8) + p * 16 + bRow;
        bBase[p] = (uint32_t)(r * 64);
        bXor[p]  = (uint32_t)(((r >> 1) & 3) << 4);
    }

    float acc[NMT][NT][4];
#pragma unroll
    for (int i = 0; i < NMT; i++)
#pragma unroll
        for (int j = 0; j < NT; j++)
#pragma unroll
            for (int r = 0; r < 4; r++) acc[i][j][r] = 0.f;

    const int T = K >> 5;

    auto stage = [&](int it, int buf) {
        const int k0 = it << 5;
        uint32_t dst = sb + buf * STG;
#pragma unroll
        for (int j = 0; j < NMT; j++) {
            int idx = tid + (j << 8);
            int row = idx >> 2, c = idx & 3;
            long long asrc = (long long)(m0 + row) * lda + k0 + c * 8;
            uint32_t so = (uint32_t)(row * 64) + SWZ(row, c * 16);
            cpasync16(dst + 0 * AARR + so, Ahb + asrc);
            cpasync16(dst + 1 * AARR + so, Alb + asrc);
        }
#pragma unroll
        for (int j = 0; j < NT / 4; j++) {
            int idx = tid + (j << 8);
            int row = idx >> 2, c = idx & 3;
            long long bsrc = (long long)(n0 + row) * ldb + k0 + c * 8;
            uint32_t so = (uint32_t)(row * 64) + SWZ(row, c * 16);
            cpasync16(dst + 2 * AARR + so, Bhb + bsrc);
            if (!NOBL) cpasync16(dst + 2 * AARR + BARR + so, Blb + bsrc);
        }
    };

    stage(0, 0); cpcommit();
    stage(1, 1); cpcommit();

    for (int it = 0; it < T; ++it) {
        if (it + 1 < T) cpwait<1>(); else cpwait<0>();
        __syncthreads();

        const uint32_t base = sb + (uint32_t)(it % 3) * STG;
        const uint32_t aHb0 = base + 0 * AARR;
        const uint32_t aLb0 = base + 1 * AARR;
        const uint32_t bHb0 = base + 2 * AARR;
        const uint32_t bLb0 = base + 2 * AARR + BARR;

#pragma unroll
        for (int kk = 0; kk < 2; kk++) {
            const uint32_t cbA = (uint32_t)(aChk * 16 + kk * 32);
            const uint32_t cbB = (uint32_t)(bChk * 16 + kk * 32);
            uint32_t ah[NMT][4], al[NMT][4];
#pragma unroll
            for (int mt = 0; mt < NMT; mt++) {
                uint32_t off = aBase[mt] + (cbA ^ aXor[mt]);
                ldsm4(ah[mt], aHb0 + off);
                ldsm4(al[mt], aLb0 + off);
            }
            uint32_t bh[NT / 2][4], bl[NT / 2][4];
#pragma unroll
            for (int p = 0; p < NT / 2; p++) {
                uint32_t off = bBase[p] + (cbB ^ bXor[p]);
                ldsm4(bh[p], bHb0 + off);
                if (!NOBL) ldsm4(bl[p], bLb0 + off);
            }
            // pass 1: ah*bh
#pragma unroll
            for (int mt = 0; mt < NMT; mt++)
#pragma unroll
                for (int p = 0; p < NT / 2; p++) {
                    mma16(acc[mt][2*p],   ah[mt], &bh[p][0]);
                    mma16(acc[mt][2*p+1], ah[mt], &bh[p][2]);
                }
            // pass 2: al*bh
#pragma unroll
            for (int mt = 0; mt < NMT; mt++)
#pragma unroll
                for (int p = 0; p < NT / 2; p++) {
                    mma16(acc[mt][2*p],   al[mt], &bh[p][0]);
                    mma16(acc[mt][2*p+1], al[mt], &bh[p][2]);
                }
            // pass 3: ah*bl
            if (!NOBL) {
#pragma unroll
                for (int mt = 0; mt < NMT; mt++)
#pragma unroll
                    for (int p = 0; p < NT / 2; p++) {
                        mma16(acc[mt][2*p],   ah[mt], &bl[p][0]);
                        mma16(acc[mt][2*p+1], ah[mt], &bl[p][2]);
                    }
            }
        }

        if (it + 2 < T) { stage(it + 2, (it + 2) % 3); cpcommit(); }
    }

    const bool relu = flags & 1;
#pragma unroll
    for (int mt = 0; mt < NMT; mt++) {
#pragma unroll
        for (int hrow = 0; hrow < 2; hrow++) {
            int m = m0 + wm * (16 * NMT) + mt * 16 + g + hrow * 8;
            long long rowo = cOff + (long long)m * ldc;
#pragma unroll
            for (int nt = 0; nt < NT; nt++) {
                int n = n0 + wn * (NT * 8) + nt * 8 + 2 * t;
                if (n < N) {
                    float v0 = acc[mt][nt][hrow * 2 + 0] * alpha;
                    float v1 = acc[mt][nt][hrow * 2 + 1] * alpha;
                    if (bias) { v0 += bias[n]; v1 += bias[n + 1]; }
                    if (res) {
                        const float* rp = res + rowo;
                        v0 += rp[n]; v1 += rp[n + 1];
                    }
                    if (relu) { v0 = fmaxf(v0, 0.f); v1 = fmaxf(v1, 0.f); }
                    if (C) {
                        float2 vv; vv.x = v0; vv.y = v1;
                        *(float2*)(C + rowo + n) = vv;
                    }
                    if (Ch) {
                        uint32_t hi, lo;
                        split2(make_float2(v0, v1), hi, lo);
                        *(uint32_t*)(Ch + rowo + n) = hi;
                        *(uint32_t*)(Cl + rowo + n) = lo;
                    }
                }
            }
        }
    }
}

#define GH_SMEM8  (3 * (2 * 128 * 64 + 2 * 128 * 64))   // 98304 (NMT=2, NT=8)
#define GH_SMEM14 (3 * (2 * 64 * 64 + 2 * 64 * 64))     // 49152 (NMT=1, NT=4)

// ------------------- fused flash attention ---------------------------------
// grid (4 m-tiles, 1, 32 bh), 256 thr = 8 warps x 16 rows.
// V now staged as pre-split halves (row stride 144B, conflict-free for
// ldmatrix.trans); PV B-fragments via ldsm4t — bitwise-identical to split2.
#define FA_QH 0
#define FA_QL 16384
#define FA_K0 32768            // 2 stages x 32768 (Kh+Kl)
#define FA_V0 98304            // 2 stages x (Vh 18432 + Vl 18432)
#define FA_VST 36864
#define FA_SMEM (98304 + 2*36864)   // 172032

__global__ __launch_bounds__(256, 1) void fused_attn(
    const __half* __restrict__ qkvh, const __half* __restrict__ qkvl,
    __half* __restrict__ Ch, __half* __restrict__ Cl,
    int causal)
{
    extern __shared__ char smf[];
    const uint32_t sb = (uint32_t)__cvta_generic_to_shared(smf);
    const int z = blockIdx.z;
    const int b = z >> 3, h = z & 7;
    const int mt = blockIdx.x;
    const int m0 = mt * 128;
    const long long tokb = (long long)b * 512;
    const int tid = threadIdx.x, wid = tid >> 5, lane = tid & 31;
    const int g = lane >> 2, t = lane & 3;
    const int aRow = lane & 15, aChk = lane >> 4;
    const int bRow = (lane & 7) + ((lane >> 4) << 3);
    const int bChk = (lane >> 3) & 1;

    // per-lane ldsm.trans V offset: quad = lane>>3
    //   k-add = (quad&1)*8, n-byte-add = (quad>>1)*16, row = lane&7
    const uint32_t vLane = (uint32_t)((((lane >> 3) & 1) * 8 + (lane & 7)) * 144
                                      + ((lane >> 4) & 1) * 16);

    // ---- stage Q (group 0) ----
#pragma unroll
    for (int j = 0; j < 4; j++) {
        int idx = tid + (j << 8);
        int r = idx >> 3, c = idx & 7;
        long long src = (tokb + m0 + r) * 1536 + h * 64 + c * 8;
        uint32_t so = (uint32_t)(r * 128) + SWZ128(r, c);
        cpasync16(sb + FA_QH + so, qkvh + src);
        cpasync16(sb + FA_QL + so, qkvl + src);
    }
    cpcommit();

    auto stageKV = [&](int kt, int buf) {
        uint32_t kdst = sb + FA_K0 + (uint32_t)buf * 32768u;
#pragma unroll
        for (int j = 0; j < 4; j++) {
            int idx = tid + (j << 8);
            int r = idx >> 3, c = idx & 7;
            long long src = (tokb + kt * 128 + r) * 1536 + 512 + h * 64 + c * 8;
            uint32_t so = (uint32_t)(r * 128) + SWZ128(r, c);
            cpasync16(kdst + so, qkvh + src);
            cpasync16(kdst + 16384 + so, qkvl + src);
        }
        uint32_t vdst = sb + FA_V0 + (uint32_t)buf * (uint32_t)FA_VST;
#pragma unroll
        for (int j = 0; j < 4; j++) {               // 1024 idx: V rows x 8 chunks
            int idx = tid + (j << 8);
            int r = idx >> 3, c = idx & 7;
            long long src = (tokb + kt * 128 + r) * 1536 + 1024 + h * 64 + c * 8;
            uint32_t so = (uint32_t)(r * 144 + c * 16);
            cpasync16(vdst + so, qkvh + src);
            cpasync16(vdst + 18432 + so, qkvl + src);
        }
    };

    stageKV(0, 0); cpcommit();

    cpwait<1>();
    __syncthreads();
    uint32_t qh[4][4], ql[4][4];
    {
        int r = wid * 16 + aRow;
        uint32_t qb = (uint32_t)(r * 128);
#pragma unroll
        for (int kc = 0; kc < 4; kc++) {
            uint32_t cb = SWZ128(r, kc * 2 + aChk);
            ldsm4(qh[kc], sb + FA_QH + qb + cb);
            ldsm4(ql[kc], sb + FA_QL + qb + cb);
        }
    }

    float accO[8][4];
#pragma unroll
    for (int nt = 0; nt < 8; nt++)
#pragma unroll
        for (int r = 0; r < 4; r++) accO[nt][r] = 0.f;
    float Mg = -1e30f, Mg8 = -1e30f, Lg = 0.f, Lg8 = 0.f;

    const int jmax = causal ? (mt + 1) : 4;

    for (int j = 0; j < jmax; j++) {
        if (j + 1 < jmax) { stageKV(j + 1, (j + 1) & 1); cpcommit(); cpwait<1>(); }
        else              { cpwait<0>(); }
        __syncthreads();

        const uint32_t kb  = sb + FA_K0 + (uint32_t)(j & 1) * 32768u;
        const uint32_t vhB = sb + FA_V0 + (uint32_t)(j & 1) * (uint32_t)FA_VST;
        const uint32_t vlB = vhB + 18432u;

        // ---- S = (Q K^T) * isq  (3-pass; per-acc order hh,lh,hl kept) ----
        float s[16][4];
#pragma unroll
        for (int nt = 0; nt < 16; nt++)
#pragma unroll
            for (int r = 0; r < 4; r++) s[nt][r] = 0.f;

#pragma unroll
        for (int kc = 0; kc < 4; kc++) {
#pragma unroll
            for (int p = 0; p < 8; p++) {
                int r = p * 16 + bRow;
                uint32_t off = (uint32_t)(r * 128) + SWZ128(r, kc * 2 + bChk);
                uint32_t bh4[4], bl4[4];
                ldsm4(bh4, kb + off);
                ldsm4(bl4, kb + 16384 + off);
                mma16(s[2*p],   qh[kc], &bh4[0]);
                mma16(s[2*p+1], qh[kc], &bh4[2]);
                mma16(s[2*p],   ql[kc], &bh4[0]);
                mma16(s[2*p+1], ql[kc], &bh4[2]);
                mma16(s[2*p],   qh[kc], &bl4[0]);
                mma16(s[2*p+1], qh[kc], &bl4[2]);
            }
        }
#pragma unroll
        for (int nt = 0; nt < 16; nt++)
#pragma unroll
            for (int r = 0; r < 4; r++) s[nt][r] *= 0.125f;

        if (causal && j == mt) {
            int rg = m0 + wid * 16 + g;
#pragma unroll
            for (int nt = 0; nt < 16; nt++) {
                int cb0 = j * 128 + nt * 8 + 2 * t;
                if (cb0     > rg)     s[nt][0] = -1e30f;
                if (cb0 + 1 > rg)     s[nt][1] = -1e30f;
                if (cb0     > rg + 8) s[nt][2] = -1e30f;
                if (cb0 + 1 > rg + 8) s[nt][3] = -1e30f;
            }
        }

        // ---- online softmax update ----
        float mg = -1e30f, mg8 = -1e30f;
#pragma unroll
        for (int nt = 0; nt < 16; nt++) {
            mg  = fmaxf(mg,  fmaxf(s[nt][0], s[nt][1]));
            mg8 = fmaxf(mg8, fmaxf(s[nt][2], s[nt][3]));
        }
        mg  = fmaxf(mg,  __shfl_xor_sync(0xffffffff, mg, 1));
        mg  = fmaxf(mg,  __shfl_xor_sync(0xffffffff, mg, 2));
        mg8 = fmaxf(mg8, __shfl_xor_sync(0xffffffff, mg8, 1));
        mg8 = fmaxf(mg8, __shfl_xor_sync(0xffffffff, mg8, 2));
        float Mn  = fmaxf(Mg,  mg);
        float Mn8 = fmaxf(Mg8, mg8);
        float f  = __expf(Mg  - Mn);
        float f8 = __expf(Mg8 - Mn8);
        Mg = Mn; Mg8 = Mn8;
        Lg *= f; Lg8 *= f8;
#pragma unroll
        for (int nt = 0; nt < 8; nt++) {
            accO[nt][0] *= f;  accO[nt][1] *= f;
            accO[nt][2] *= f8; accO[nt][3] *= f8;
        }

        // ---- P (fp16 A-fragments, in-register repack) ----
        uint32_t pa[8][4];
#pragma unroll
        for (int kc2 = 0; kc2 < 8; kc2++) {
            float p00 = __expf(s[2*kc2][0]   - Mg);
            float p01 = __expf(s[2*kc2][1]   - Mg);
            float p02 = __expf(s[2*kc2][2]   - Mg8);
            float p03 = __expf(s[2*kc2][3]   - Mg8);
            float p10 = __expf(s[2*kc2+1][0] - Mg);
            float p11 = __expf(s[2*kc2+1][1] - Mg);
            float p12 = __expf(s[2*kc2+1][2] - Mg8);
            float p13 = __expf(s[2*kc2+1][3] - Mg8);
            Lg  += p00 + p01 + p10 + p11;
            Lg8 += p02 + p03 + p12 + p13;
            __half2 h0 = __floats2half2_rn(p00, p01);
            __half2 h1 = __floats2half2_rn(p02, p03);
            __half2 h2v = __floats2half2_rn(p10, p11);
            __half2 h3 = __floats2half2_rn(p12, p13);
            pa[kc2][0] = *(uint32_t*)&h0;
            pa[kc2][1] = *(uint32_t*)&h1;
            pa[kc2][2] = *(uint32_t*)&h2v;
            pa[kc2][3] = *(uint32_t*)&h3;
        }

        // ---- O += P @ V  (half V via ldsm.trans; hh sweep then hl sweep) ----
#pragma unroll
        for (int kc2 = 0; kc2 < 8; kc2++) {
            uint32_t bv[8][2], bw[8][2];
#pragma unroll
            for (int ntp = 0; ntp < 4; ntp++) {
                uint32_t off = (uint32_t)(kc2 * 16 * 144 + ntp * 32) + vLane;
                uint32_t r4[4], s4[4];
                ldsm4t(r4, vhB + off);
                ldsm4t(s4, vlB + off);
                bv[2*ntp][0]   = r4[0]; bv[2*ntp][1]   = r4[1];
                bv[2*ntp+1][0] = r4[2]; bv[2*ntp+1][1] = r4[3];
                bw[2*ntp][0]   = s4[0]; bw[2*ntp][1]   = s4[1];
                bw[2*ntp+1][0] = s4[2]; bw[2*ntp+1][1] = s4[3];
            }
#pragma unroll
            for (int nt = 0; nt < 8; nt++) mma16(accO[nt], pa[kc2], bv[nt]);
#pragma unroll
            for (int nt = 0; nt < 8; nt++) mma16(accO[nt], pa[kc2], bw[nt]);
        }
        __syncthreads();
    }

    // ---- epilogue: normalize + write halves ----
    Lg  += __shfl_xor_sync(0xffffffff, Lg, 1);
    Lg  += __shfl_xor_sync(0xffffffff, Lg, 2);
    Lg8 += __shfl_xor_sync(0xffffffff, Lg8, 1);
    Lg8 += __shfl_xor_sync(0xffffffff, Lg8, 2);
    float invg  = 1.f / Lg;
    float invg8 = 1.f / Lg8;

    long long row0 = (tokb + m0 + wid * 16 + g) * 512 + h * 64;
    long long row8 = row0 + 8LL * 512;
#pragma unroll
    for (int nt = 0; nt < 8; nt++) {
        int n = nt * 8 + 2 * t;
        uint32_t hi, lo;
        split2(make_float2(accO[nt][0] * invg, accO[nt][1] * invg), hi, lo);
        *(uint32_t*)(Ch + row0 + n) = hi;
        *(uint32_t*)(Cl + row0 + n) = lo;
        split2(make_float2(accO[nt][2] * invg8, accO[nt][3] * invg8), hi, lo);
        *(uint32_t*)(Ch + row8 + n) = hi;
        *(uint32_t*)(Cl + row8 + n) = lo;
    }
}

// --------------------------- conversion kernels -----------------------------
__global__ void convw_kernel(const float* __restrict__ W,
                             __half* __restrict__ hi, __half* __restrict__ lo,
                             int K, int N, int Npad, long long inS, long long outS)
{
    __shared__ float tile[32][65];
    int z = blockIdx.z;
    const float* Wz = W + (long long)z * inS;
    int k0 = blockIdx.y * 32, n0 = blockIdx.x * 64;
    int tid = threadIdx.x;

#pragma unroll
    for (int j = 0; j < 2; j++) {
        int idx = tid + (j << 8);
        int k = idx >> 4, nq = (idx & 15) << 2;
        int n = n0 + nq;
        float4 v = make_float4(0.f, 0.f, 0.f, 0.f);
        const float* p = Wz + (long long)(k0 + k) * N;
        if (n + 3 < N) v = *(const float4*)(p + n);
        else {
            if (n + 0 < N) v.x = p[n + 0];
            if (n + 1 < N) v.y = p[n + 1];
            if (n + 2 < N) v.z = p[n + 2];
            if (n + 3 < N) v.w = p[n + 3];
        }
        tile[k][nq + 0] = v.x; tile[k][nq + 1] = v.y;
        tile[k][nq + 2] = v.z; tile[k][nq + 3] = v.w;
    }
    __syncthreads();

#pragma unroll
    for (int j = 0; j < 4; j++) {
        int idx = tid + (j << 8);
        int n = idx >> 4, tq = (idx & 15) << 1;
        int gn = n0 + n;
        if (gn < Npad) {
            float v0 = tile[tq][n], v1 = tile[tq + 1][n];
            __half2 h = __floats2half2_rn(v0, v1);
            long long o = (long long)z * outS + (long long)gn * K + k0 + tq;
            *(__half2*)(hi + o) = h;
            if (lo) {
                float2 hf = __half22float2(h);
                __half2 l = __floats2half2_rn(v0 - hf.x, v1 - hf.y);
                *(__half2*)(lo + o) = l;
            }
        }
    }
}

__global__ void convqkv_kernel(const float* __restrict__ Wq, const float* __restrict__ Wk,
                               const float* __restrict__ Wv,
                               __half* __restrict__ hi, __half* __restrict__ lo)
{
    __shared__ float tile[32][65];
    int kt = blockIdx.x, sh = blockIdx.y;
    int sel = sh >> 3, h = sh & 7;
    const float* W = (sel == 0) ? Wq : (sel == 1) ? Wk : Wv;
    const float* src = W + ((long long)h * 512 + kt * 32) * 64;
    int tid = threadIdx.x;

#pragma unroll
    for (int j = 0; j < 2; j++) {
        int idx = tid + (j << 8);
        int k = idx >> 4, eq = (idx & 15) << 2;
        float4 v = *(const float4*)(src + k * 64 + eq);
        tile[k][eq + 0] = v.x; tile[k][eq + 1] = v.y;
        tile[k][eq + 2] = v.z; tile[k][eq + 3] = v.w;
    }
    __syncthreads();

#pragma unroll
    for (int j = 0; j < 4; j++) {
        int idx = tid + (j << 8);
        int e = idx >> 4, tq = (idx & 15) << 1;
        int n = sel * 512 + h * 64 + e;
        float v0 = tile[tq][e], v1 = tile[tq + 1][e];
        __half2 hh = __floats2half2_rn(v0, v1);
        float2 hf = __half22float2(hh);
        __half2 ll = __floats2half2_rn(v0 - hf.x, v1 - hf.y);
        long long o = (long long)n * 512 + kt * 32 + tq;
        *(__half2*)(hi + o) = hh;
        *(__half2*)(lo + o) = ll;
    }
}

__global__ void conva_kernel(const float* __restrict__ src,
                             __half* __restrict__ hi, __half* __restrict__ lo, int n) {
    int i = blockIdx.x * 256 + threadIdx.x;
    if (i < n) {
        float v = src[i];
        __half h = __float2half_rn(v);
        hi[i] = h;
        lo[i] = __float2half_rn(v - __half2float(h));
    }
}

// --------------------------- elementwise kernels ---------------------------
__global__ void embed_kernel(const int* __restrict__ tok, const float* __restrict__ emb,
                             float* __restrict__ x,
                             __half* __restrict__ xh, __half* __restrict__ xl) {
    int idx = blockIdx.x * 256 + threadIdx.x;
    int t = tok[idx >> 9];
    float v = emb[(long long)t * Dm_ + (idx & 511)] * 8.0f;
    x[idx] = v;
    __half h = __float2half_rn(v);
    xh[idx] = h;
    xl[idx] = __float2half_rn(v - __half2float(h));
}

__global__ void bn_stats_kernel(const float* __restrict__ x,
                                float* __restrict__ mu, float* __restrict__ rstd) {
    int d = blockIdx.x * 32 + threadIdx.x;
    float s = 0.f, s2 = 0.f;
    for (int i = threadIdx.y; i < BS_; i += 8) {
        float v = x[(long long)i * Dm_ + d];
        s += v; s2 += v * v;
    }
    __shared__ float sh[8][33], sh2[8][33];
    sh[threadIdx.y][threadIdx.x] = s;
    sh2[threadIdx.y][threadIdx.x] = s2;
    __syncthreads();
    if (threadIdx.y == 0) {
#pragma unroll
        for (int r = 1; r < 8; r++) { s += sh[r][threadIdx.x]; s2 += sh2[r][threadIdx.x]; }
        float m = s * (1.f / BS_);
        float var = s2 * (1.f / BS_) - m * m;
        mu[d] = m;
        rstd[d] = rsqrtf(var + 1e-5f);
    }
}

__global__ void bn_apply_kernel(const float* __restrict__ xin, float* __restrict__ xout,
                                __half* __restrict__ xh, __half* __restrict__ xl,
                                const float* __restrict__ mu, const float* __restrict__ rstd,
                                const float* __restrict__ gamma, const float* __restrict__ beta) {
    int idx = blockIdx.x * 256 + threadIdx.x;
    int d = idx & 511;
    float v = (xin[idx] - mu[d]) * rstd[d] * gamma[d] + beta[d];
    xout[idx] = v;
    __half h = __float2half_rn(v);
    xh[idx] = h;
    xl[idx] = __float2half_rn(v - __half2float(h));
}

// Vocab softmax (register-resident, launch-bounded)
#define VITER 37
__global__ __launch_bounds__(1024, 1) void softmax_vocab_kernel(float* __restrict__ p, int T) {
    __shared__ float red[1024];
    long long row = blockIdx.x;
    float* x = p + row * (long long)T;
    int tid = threadIdx.x;

    float vals[VITER];
    float m = -1e30f;
#pragma unroll
    for (int j = 0; j < VITER; j++) {
        int t = tid + j * 1024;
        float v = (t < T) ? x[t] : -1e30f;
        vals[j] = v;
        m = fmaxf(m, v);
    }
    red[tid] = m; __syncthreads();
    for (int o = 512; o > 0; o >>= 1) {
        if (tid < o) red[tid] = fmaxf(red[tid], red[tid + o]);
        __syncthreads();
    }
    float M = red[0]; __syncthreads();

    float sum = 0.f;
#pragma unroll
    for (int j = 0; j < VITER; j++) {
        int t = tid + j * 1024;
        if (t < T) { vals[j] = __expf(vals[j] - M); sum += vals[j]; }
    }
    red[tid] = sum; __syncthreads();
    for (int o = 512; o > 0; o >>= 1) {
        if (tid < o) red[tid] += red[tid + o];
        __syncthreads();
    }
    float inv = 1.f / red[0];
#pragma unroll
    for (int j = 0; j < VITER; j++) {
        int t = tid + j * 1024;
        if (t < T) x[t] = vals[j] * inv;
    }
}

// ------------------------------- host side ---------------------------------
static inline int cdiv(int a, int b) { return (a + b - 1) / b; }

static void gh8(const __half* Ah, const __half* Al, const __half* Bh, const __half* Bl,
                float* C, __half* Ch, __half* Cl,
                const float* bias, const float* res,
                int M, int N, int K, int lda, int ldb, int ldc, int flags)
{
    dim3 g(cdiv(N, 128), M / 128, 1);
    gemm_h<2,8,0><<<g, 256, GH_SMEM8>>>(Ah, Al, Bh, Bl, C, Ch, Cl, bias, res,
                                        M, N, K, lda, ldb, ldc,
                                        0, 0, 1, 0, 0, 1, 0, 0, 1, 1.f, flags);
}
static void gh14(const __half* Ah, const __half* Al, const __half* Bh, const __half* Bl,
                 float* C, __half* Ch, __half* Cl,
                 const float* bias, const float* res,
                 int M, int N, int K, int lda, int ldb, int ldc, int flags)
{
    dim3 g(cdiv(N, 64), M / 64, 1);
    gemm_h<1,4,0><<<g, 256, GH_SMEM14>>>(Ah, Al, Bh, Bl, C, Ch, Cl, bias, res,
                                         M, N, K, lda, ldb, ldc,
                                         0, 0, 1, 0, 0, 1, 0, 0, 1, 1.f, flags);
}

extern "C" void kernel_launch(void* const* d_in, const int* in_sizes, int n_in,
                              void* d_out, int out_size)
{
    const int*   tok   = (const int*)  d_in[0];
    const float* enc   = (const float*)d_in[1];
    const float* emb   = (const float*)d_in[2];
    const float* Wq1   = (const float*)d_in[3];
    const float* Wk1   = (const float*)d_in[4];
    const float* Wv1   = (const float*)d_in[5];
    const float* Wo1   = (const float*)d_in[6];
    const float* Wq2   = (const float*)d_in[7];
    const float* Wk2   = (const float*)d_in[8];
    const float* Wv2   = (const float*)d_in[9];
    const float* Wo2   = (const float*)d_in[10];
    const float* gamma = (const float*)d_in[11];
    const float* beta  = (const float*)d_in[12];
    const float* W1    = (const float*)d_in[13];
    const float* b1    = (const float*)d_in[14];
    const float* W2    = (const float*)d_in[15];
    const float* b2    = (const float*)d_in[16];
    const float* Wout  = (const float*)d_in[17];
    const float* bout  = (const float*)d_in[18];
    float* out = (float*)d_out;

    cudaFuncSetAttribute((const void*)gemm_h<2,8,0>, cudaFuncAttributeMaxDynamicSharedMemorySize, GH_SMEM8);
    cudaFuncSetAttribute((const void*)gemm_h<2,8,1>, cudaFuncAttributeMaxDynamicSharedMemorySize, GH_SMEM8);
    cudaFuncSetAttribute((const void*)gemm_h<1,4,0>, cudaFuncAttributeMaxDynamicSharedMemorySize, GH_SMEM14);
    cudaFuncSetAttribute((const void*)fused_attn,    cudaFuncAttributeMaxDynamicSharedMemorySize, FA_SMEM);

    float *x, *tmp, *mu, *rstd;
    cudaGetSymbolAddress((void**)&x,    g_x);
    cudaGetSymbolAddress((void**)&tmp,  g_tmp);
    cudaGetSymbolAddress((void**)&mu,   g_mu);
    cudaGetSymbolAddress((void**)&rstd, g_rstd);

    __half *xh, *xl, *qkvh, *qkvl, *attnh, *attnl, *ffh, *ffl, *ench, *encl;
    cudaGetSymbolAddress((void**)&xh,    g_xh);
    cudaGetSymbolAddress((void**)&xl,    g_xl);
    cudaGetSymbolAddress((void**)&qkvh,  g_qkvh);
    cudaGetSymbolAddress((void**)&qkvl,  g_qkvl);
    cudaGetSymbolAddress((void**)&attnh, g_attnh);
    cudaGetSymbolAddress((void**)&attnl, g_attnl);
    cudaGetSymbolAddress((void**)&ffh,   g_ffh);
    cudaGetSymbolAddress((void**)&ffl,   g_ffl);
    cudaGetSymbolAddress((void**)&ench,  g_ench);
    cudaGetSymbolAddress((void**)&encl,  g_encl);

    __half *wtT_h, *wtT_l, *w1T_h, *w1T_l, *w2T_h, *w2T_l;
    __half *wo1T_h, *wo1T_l, *wo2T_h, *wo2T_l, *woutT_h;
    cudaGetSymbolAddress((void**)&wtT_h,  g_wtT_h);
    cudaGetSymbolAddress((void**)&wtT_l,  g_wtT_l);
    cudaGetSymbolAddress((void**)&w1T_h,  g_w1T_h);
    cudaGetSymbolAddress((void**)&w1T_l,  g_w1T_l);
    cudaGetSymbolAddress((void**)&w2T_h,  g_w2T_h);
    cudaGetSymbolAddress((void**)&w2T_l,  g_w2T_l);
    cudaGetSymbolAddress((void**)&wo1T_h, g_wo1T_h);
    cudaGetSymbolAddress((void**)&wo1T_l, g_wo1T_l);
    cudaGetSymbolAddress((void**)&wo2T_h, g_wo2T_h);
    cudaGetSymbolAddress((void**)&wo2T_l, g_wo2T_l);
    cudaGetSymbolAddress((void**)&woutT_h, g_woutT_h);

    const long long HW = (long long)Dm_ * Dk_;

    // ---- conversions ----
    convqkv_kernel<<<dim3(16, 24), 256>>>(Wq1, Wk1, Wv1, wtT_h, wtT_l);
    conva_kernel<<<cdiv(BS_*Dm_, 256), 256>>>(enc, ench, encl, BS_*Dm_);
    embed_kernel<<<BS_ * Dm_ / 256, 256>>>(tok, emb, x, xh, xl);
    convw_kernel<<<dim3(Ff_/64, Dm_/32, Nx_), 256>>>(W1, w1T_h, w1T_l, Dm_, Ff_, Ff_,
                                                     (long long)Dm_*Ff_, (long long)Ff_*Dm_);
    convw_kernel<<<dim3(Dm_/64, Ff_/32, Nx_), 256>>>(W2, w2T_h, w2T_l, Ff_, Dm_, Dm_,
                                                     (long long)Ff_*Dm_, (long long)Dm_*Ff_);
    gh8(xh, xl, wtT_h, wtT_l, nullptr, qkvh, qkvl, nullptr, nullptr,
        BS_, 1536, Dm_, Dm_, Dm_, 1536, 0);
    for (int s = 1; s < 12; s++) {
        int i = s >> 1, pass = s & 1;
        const float* wq = pass ? Wq2 : Wq1;
        const float* wk = pass ? Wk2 : Wk1;
        const float* wv = pass ? Wv2 : Wv1;
        convqkv_kernel<<<dim3(16, 24), 256>>>(wq + (long long)i*Hh_*HW,
                                              wk + (long long)i*Hh_*HW,
                                              wv + (long long)i*Hh_*HW,
                                              wtT_h + (long long)s*1536*512,
                                              wtT_l + (long long)s*1536*512);
    }
    convw_kernel<<<dim3(Dm_/64, Dm_/32, Nx_), 256>>>(Wo1, wo1T_h, wo1T_l, Dm_, Dm_, Dm_,
                                                     (long long)Dm_*Dm_, (long long)Dm_*Dm_);
    convw_kernel<<<dim3(Dm_/64, Dm_/32, Nx_), 256>>>(Wo2, wo2T_h, wo2T_l, Dm_, Dm_, Dm_,
                                                     (long long)Dm_*Dm_, (long long)Dm_*Dm_);
    convw_kernel<<<dim3(VvP_/64, Dm_/32, 1), 256>>>(Wout, woutT_h, nullptr, Dm_, Vv_, VvP_, 0, 0);

    for (int i = 0; i < Nx_; i++) {
        const float* bb1 = b1 + (long long)i * Ff_;
        const float* bb2 = b2 + (long long)i * Dm_;

        for (int attn_pass = 0; attn_pass < 2; attn_pass++) {
            const int self = (attn_pass == 0);
            const int s = i * 2 + attn_pass;
            const __half* wth = wtT_h + (long long)s * 1536 * 512;
            const __half* wtl = wtT_l + (long long)s * 1536 * 512;

            if (self) {
                if (i != 0)
                    gh8(xh, xl, wth, wtl, nullptr, qkvh, qkvl, nullptr, nullptr,
                        BS_, 1536, Dm_, Dm_, Dm_, 1536, 0);
            } else {
                gh14(xh, xl, wth, wtl, nullptr, qkvh, qkvl, nullptr, nullptr,
                     BS_, 512, Dm_, Dm_, Dm_, 1536, 0);
                dim3 g(8, 16, 1);
                gemm_h<2,8,0><<<g, 256, GH_SMEM8>>>(ench, encl,
                                                    wth + 512LL*512, wtl + 512LL*512,
                                                    nullptr, qkvh + 512, qkvl + 512,
                                                    nullptr, nullptr,
                                                    BS_, 1024, Dm_, Dm_, Dm_, 1536,
                                                    0, 0, 1, 0, 0, 1, 0, 0, 1, 1.f, 0);
            }
            // ---- fused attention (half V) ----
            {
                dim3 g(4, 1, Bb_ * Hh_);
                fused_attn<<<g, 256, FA_SMEM>>>(qkvh, qkvl, attnh, attnl,
                                                self ? 1 : 0);
            }
            // tmp = attn @ Wo + x
            const __half* woh = (self ? wo1T_h : wo2T_h) + (long long)i*512*512;
            const __half* wol = (self ? wo1T_l : wo2T_l) + (long long)i*512*512;
            gh14(attnh, attnl, woh, wol, tmp, nullptr, nullptr, nullptr, x,
                 BS_, Dm_, Dm_, Dm_, Dm_, Dm_, 0);
            bn_stats_kernel<<<Dm_/32, dim3(32, 8)>>>(tmp, mu, rstd);
            bn_apply_kernel<<<BS_*Dm_/256, 256>>>(tmp, x, xh, xl, mu, rstd,
                                                  gamma + (long long)(i*3 + attn_pass)*Dm_,
                                                  beta  + (long long)(i*3 + attn_pass)*Dm_);
        }

        // ---- feed-forward
        gh8(xh, xl, w1T_h + (long long)i*Ff_*512, w1T_l + (long long)i*Ff_*512,
            nullptr, ffh, ffl, bb1, nullptr, BS_, Ff_, Dm_, Dm_, Dm_, Ff_, 1);
        gh14(ffh, ffl, w2T_h + (long long)i*512LL*Ff_, w2T_l + (long long)i*512LL*Ff_,
             tmp, nullptr, nullptr, bb2, x, BS_, Dm_, Ff_, Ff_, Ff_, Dm_, 0);
        bn_stats_kernel<<<Dm_/32, dim3(32, 8)>>>(tmp, mu, rstd);
        bn_apply_kernel<<<BS_*Dm_/256, 256>>>(tmp, x, xh, xl, mu, rstd,
                                              gamma + (long long)(i*3 + 2)*Dm_,
                                              beta  + (long long)(i*3 + 2)*Dm_);
    }

    // ---- output projection (2-pass) + vocab softmax
    {
        dim3 g(cdiv(Vv_, 128), BS_ / 128, 1);
        gemm_h<2,8,1><<<g, 256, GH_SMEM8>>>(xh, xl, woutT_h, woutT_h,
                                            out, nullptr, nullptr, bout, nullptr,
                                            BS_, Vv_, Dm_, Dm_, Dm_, Vv_,
                                            0, 0, 1, 0, 0, 1, 0, 0, 1, 1.f, 0);
    }
    softmax_vocab_kernel<<<BS_, 1024>>>(out, Vv_);

    (void)in_sizes; (void)n_in; (void)out_size;
}